// round 6
// baseline (speedup 1.0000x reference)
#include <cuda_runtime.h>
#include <math.h>
#include <stdint.h>

#define LTOT (2*64*32*1024)
#define ROWS 65536

__device__ float g_h5[LTOT];
__device__ float g_x1[LTOT];
__device__ float g_x2[LTOT];
__device__ float g_s [LTOT];

__device__ float g_Wp[384 * 128];
__device__ float g_bp[384];

__device__ float g_gre[32], g_gim[32], g_qre[32], g_qim[32];
__device__ float g_sum1[64], g_sq1[64], g_sum2[64], g_sq2[64];
__device__ float g_a1[64], g_b1[64], g_a2[64], g_b2[64];

__device__ __forceinline__ float gelu_f(float v) {
    return 0.5f * v * (1.0f + erff(v * 0.70710678118654752f));
}

__device__ __forceinline__ uint32_t f2tf32(float f) {
    uint32_t r;
    asm("cvt.rna.tf32.f32 %0, %1;" : "=r"(r) : "f"(f));
    return r;
}

__device__ __forceinline__ void mma_tf32(float c[4], uint32_t a0, uint32_t a1,
                                         uint32_t a2, uint32_t a3,
                                         uint32_t b0, uint32_t b1) {
    asm volatile(
        "mma.sync.aligned.m16n8k8.row.col.f32.tf32.tf32.f32 "
        "{%0,%1,%2,%3}, {%4,%5,%6,%7}, {%8,%9}, {%0,%1,%2,%3};"
        : "+f"(c[0]), "+f"(c[1]), "+f"(c[2]), "+f"(c[3])
        : "r"(a0), "r"(a1), "r"(a2), "r"(a3), "r"(b0), "r"(b1));
}

// K0: g = ifft_T(fw), q = ifft_T(fb); zero BN stats
__global__ void k_prep(const float* __restrict__ fw, const float* __restrict__ fb) {
    int n = threadIdx.x;
    if (n < 32) {
        double gr = 0, gi = 0, qr = 0, qi = 0;
        for (int k = 0; k < 32; k++) {
            double ang = 6.283185307179586476925 * (double)((k * n) & 31) / 32.0;
            double cs = cos(ang), sn = sin(ang);
            gr += (double)fw[k] * cs; gi += (double)fw[k] * sn;
            qr += (double)fb[k] * cs; qi += (double)fb[k] * sn;
        }
        g_gre[n] = (float)(gr / 32.0); g_gim[n] = (float)(gi / 32.0);
        g_qre[n] = (float)(qr / 32.0); g_qim[n] = (float)(qi / 32.0);
    }
    if (n < 64) { g_sum1[n] = 0.f; g_sq1[n] = 0.f; g_sum2[n] = 0.f; g_sq2[n] = 0.f; }
}

// K0b: fold channel-mix into up-proj: W' = [U | U*W2], b' = ub + U*cb
__global__ void k_fold(const float* __restrict__ up, const float* __restrict__ upb,
                       const float* __restrict__ w2, const float* __restrict__ cb) {
    int of = blockIdx.x;
    int j = threadIdx.x;   // 0..63
    float m = 0.f;
    #pragma unroll 8
    for (int o2 = 0; o2 < 64; o2++)
        m = fmaf(up[of * 64 + o2], w2[o2 * 64 + j], m);
    g_Wp[of * 128 + j] = up[of * 64 + j];
    g_Wp[of * 128 + 64 + j] = m;
    if (j == 0) {
        float bb = upb[of];
        for (int o2 = 0; o2 < 64; o2++)
            bb = fmaf(up[of * 64 + o2], cb[o2], bb);
        g_bp[of] = bb;
    }
}

// K1: down GEMM (tf32) [65536,384]x[64,384]^T + bias + GELU -> h5 NCDHW
__global__ void __launch_bounds__(256) k_down(const float* __restrict__ x,
                                              const float* __restrict__ w,
                                              const float* __restrict__ bias) {
    __shared__ uint32_t As[128][36];
    __shared__ uint32_t Bs[64][36];
    int tid = threadIdx.x;
    int r0 = blockIdx.x * 128;
    int wid = tid >> 5, lane = tid & 31;
    int g = lane >> 2, tig = lane & 3;
    int warp_m = (wid & 3) * 32;
    int warp_n = (wid >> 2) * 32;

    float acc[2][4][4];
    #pragma unroll
    for (int i = 0; i < 2; i++)
        #pragma unroll
        for (int j = 0; j < 4; j++)
            #pragma unroll
            for (int l = 0; l < 4; l++) acc[i][j][l] = 0.f;

    for (int k0 = 0; k0 < 384; k0 += 32) {
        #pragma unroll
        for (int i = 0; i < 4; i++) {
            int idx4 = tid + i * 256;
            int m = idx4 >> 3, k4 = (idx4 & 7) * 4;
            float4 v = *reinterpret_cast<const float4*>(&x[(size_t)(r0 + m) * 384 + k0 + k4]);
            As[m][k4 + 0] = f2tf32(v.x); As[m][k4 + 1] = f2tf32(v.y);
            As[m][k4 + 2] = f2tf32(v.z); As[m][k4 + 3] = f2tf32(v.w);
        }
        #pragma unroll
        for (int i = 0; i < 2; i++) {
            int idx4 = tid + i * 256;
            int n = idx4 >> 3, k4 = (idx4 & 7) * 4;
            float4 v = *reinterpret_cast<const float4*>(&w[n * 384 + k0 + k4]);
            Bs[n][k4 + 0] = f2tf32(v.x); Bs[n][k4 + 1] = f2tf32(v.y);
            Bs[n][k4 + 2] = f2tf32(v.z); Bs[n][k4 + 3] = f2tf32(v.w);
        }
        __syncthreads();
        #pragma unroll
        for (int ks = 0; ks < 4; ks++) {
            int kk = ks * 8;
            uint32_t a[2][4];
            #pragma unroll
            for (int mf = 0; mf < 2; mf++) {
                int row = warp_m + mf * 16;
                a[mf][0] = As[row + g    ][kk + tig];
                a[mf][1] = As[row + g + 8][kk + tig];
                a[mf][2] = As[row + g    ][kk + tig + 4];
                a[mf][3] = As[row + g + 8][kk + tig + 4];
            }
            uint32_t b[4][2];
            #pragma unroll
            for (int nf = 0; nf < 4; nf++) {
                int col = warp_n + nf * 8;
                b[nf][0] = Bs[col + g][kk + tig];
                b[nf][1] = Bs[col + g][kk + tig + 4];
            }
            #pragma unroll
            for (int mf = 0; mf < 2; mf++)
                #pragma unroll
                for (int nf = 0; nf < 4; nf++)
                    mma_tf32(acc[mf][nf], a[mf][0], a[mf][1], a[mf][2], a[mf][3],
                             b[nf][0], b[nf][1]);
        }
        __syncthreads();
    }
    int bt = r0 >> 10, hwbase = r0 & 1023;
    int b5i = bt >> 5, t = bt & 31;
    size_t planebase = (size_t)(b5i * 64) * 32768 + (size_t)t * 1024;
    #pragma unroll
    for (int nf = 0; nf < 4; nf++) {
        int c0 = warp_n + nf * 8 + 2 * tig;
        float bs0 = bias[c0], bs1 = bias[c0 + 1];
        #pragma unroll
        for (int mf = 0; mf < 2; mf++) {
            int m = warp_m + mf * 16 + g;
            size_t p0 = planebase + (size_t)c0 * 32768;
            g_h5[p0 + hwbase + m]             = gelu_f(acc[mf][nf][0] + bs0);
            g_h5[p0 + 32768 + hwbase + m]     = gelu_f(acc[mf][nf][1] + bs1);
            g_h5[p0 + hwbase + m + 8]         = gelu_f(acc[mf][nf][2] + bs0);
            g_h5[p0 + 32768 + hwbase + m + 8] = gelu_f(acc[mf][nf][3] + bs1);
        }
    }
}

// K2: fused spatial(3x3,5x5) + temporal(3,5) depthwise + BN stats
// block = (bc, 8-row h-band); dynamic smem: in[32][12][32], s3[32][8][32], s5[32][8][32]
__global__ void __launch_bounds__(256) k_conv(const float* __restrict__ w3g,
                                              const float* __restrict__ b3g,
                                              const float* __restrict__ w5g,
                                              const float* __restrict__ b5g,
                                              const float* __restrict__ wt3g,
                                              const float* __restrict__ bt3g,
                                              const float* __restrict__ wt5g,
                                              const float* __restrict__ bt5g) {
    extern __shared__ float sm[];
    float* in = sm;            // 32*384 = 12288
    float* s3 = sm + 12288;    // 32*256 = 8192
    float* s5 = sm + 20480;    // 8192
    int bc = blockIdx.x >> 2;
    int band = blockIdx.x & 3;
    int h0 = band * 8;
    int c = bc & 63;
    size_t base = (size_t)bc * 32768;
    int tid = threadIdx.x;

    __shared__ float w3s[9], w5s[25], wt3[3], wt5[5];
    if (tid < 9)  w3s[tid] = w3g[c * 9 + tid];
    if (tid >= 32 && tid < 57) w5s[tid - 32] = w5g[c * 25 + (tid - 32)];
    if (tid >= 64 && tid < 67) wt3[tid - 64] = wt3g[c * 3 + (tid - 64)];
    if (tid >= 96 && tid < 101) wt5[tid - 96] = wt5g[c * 5 + (tid - 96)];

    for (int i = tid; i < 12288; i += 256) {
        int t = i / 384; int rem = i - t * 384;
        int hh = rem >> 5, w = rem & 31;
        int gh = h0 - 2 + hh;
        float v = 0.f;
        if ((unsigned)gh < 32u) v = g_h5[base + (size_t)t * 1024 + gh * 32 + w];
        in[i] = v;
    }
    __syncthreads();

    float b3 = b3g[c], b5 = b5g[c];
    for (int i = tid; i < 8192; i += 256) {
        int t = i >> 8, p = i & 255, hl = p >> 5, w = p & 31;
        const float* tin = in + t * 384 + (hl + 2) * 32 + w;
        float a3 = b3;
        #pragma unroll
        for (int dh = -1; dh <= 1; dh++)
            #pragma unroll
            for (int dw = -1; dw <= 1; dw++) {
                int ww = w + dw;
                if ((unsigned)ww < 32u)
                    a3 = fmaf(tin[dh * 32 + dw], w3s[(dh + 1) * 3 + dw + 1], a3);
            }
        float a5 = b5;
        #pragma unroll
        for (int dh = -2; dh <= 2; dh++)
            #pragma unroll
            for (int dw = -2; dw <= 2; dw++) {
                int ww = w + dw;
                if ((unsigned)ww < 32u)
                    a5 = fmaf(tin[dh * 32 + dw], w5s[(dh + 2) * 5 + dw + 2], a5);
            }
        s3[i] = a3;
        s5[i] = a5;
    }
    __syncthreads();

    float bt3 = bt3g[c], bt5 = bt5g[c];
    float s1 = 0, q1 = 0, s2 = 0, q2 = 0;
    for (int i = tid; i < 8192; i += 256) {
        int t = i >> 8, p = i & 255;
        float a = bt3;
        #pragma unroll
        for (int dt = -1; dt <= 1; dt++) {
            int tt = t + dt;
            if ((unsigned)tt < 32u) a = fmaf(s3[tt * 256 + p], wt3[dt + 1], a);
        }
        float e = bt5;
        #pragma unroll
        for (int dt = -2; dt <= 2; dt++) {
            int tt = t + dt;
            if ((unsigned)tt < 32u) e = fmaf(s5[tt * 256 + p], wt5[dt + 2], e);
        }
        size_t gi = base + (size_t)t * 1024 + h0 * 32 + p;
        g_x1[gi] = a;
        g_x2[gi] = e;
        s1 += a; q1 = fmaf(a, a, q1);
        s2 += e; q2 = fmaf(e, e, q2);
    }
    #pragma unroll
    for (int off = 16; off; off >>= 1) {
        s1 += __shfl_down_sync(0xffffffffu, s1, off);
        q1 += __shfl_down_sync(0xffffffffu, q1, off);
        s2 += __shfl_down_sync(0xffffffffu, s2, off);
        q2 += __shfl_down_sync(0xffffffffu, q2, off);
    }
    __shared__ float red[4][8];
    int wid = tid >> 5, lane = tid & 31;
    if (lane == 0) { red[0][wid] = s1; red[1][wid] = q1; red[2][wid] = s2; red[3][wid] = q2; }
    __syncthreads();
    if (tid == 0) {
        float a = 0, b = 0, c2 = 0, d = 0;
        for (int i = 0; i < 8; i++) { a += red[0][i]; b += red[1][i]; c2 += red[2][i]; d += red[3][i]; }
        atomicAdd(&g_sum1[c], a);  atomicAdd(&g_sq1[c], b);
        atomicAdd(&g_sum2[c], c2); atomicAdd(&g_sq2[c], d);
    }
}

// K4: BN scale/shift
__global__ void k_bn(const float* __restrict__ g3, const float* __restrict__ b3,
                     const float* __restrict__ g5, const float* __restrict__ b5) {
    int c = threadIdx.x;
    const float inv = 1.0f / 65536.0f;
    float m1 = g_sum1[c] * inv;
    float v1 = g_sq1[c] * inv - m1 * m1;
    float a1 = g3[c] * rsqrtf(v1 + 1e-5f);
    g_a1[c] = a1; g_b1[c] = b3[c] - m1 * a1;
    float m2 = g_sum2[c] * inv;
    float v2 = g_sq2[c] * inv - m2 * m2;
    float a2 = g5[c] * rsqrtf(v2 + 1e-5f);
    g_a2[c] = a2; g_b2[c] = b5[c] - m2 * a2;
}

// K5: circulant T-conv (FFT branch) + BN-ReLU combine -> s
__global__ void __launch_bounds__(256) k_branch3() {
    int bc  = blockIdx.x >> 2;
    int hw0 = (blockIdx.x & 3) << 8;
    int c = bc & 63;
    size_t base = (size_t)bc * 32768;
    __shared__ float2 gg[64];
    __shared__ float2 qq[32];
    __shared__ __align__(16) float4 Vs[32][64];
    int tid = threadIdx.x;
    if (tid < 64) gg[tid] = make_float2(g_gre[tid & 31], g_gim[tid & 31]);
    if (tid < 32) qq[tid] = make_float2(g_qre[tid], g_qim[tid]);
    for (int i = tid; i < 2048; i += 256) {
        int t = i >> 6, q4 = i & 63;
        Vs[t][q4] = *reinterpret_cast<const float4*>(&g_h5[base + (size_t)t * 1024 + hw0 + q4 * 4]);
    }
    __syncthreads();
    int ty = tid >> 6;
    int tx = tid & 63;
    float re[8][4], im[8][4];
    #pragma unroll
    for (int i = 0; i < 8; i++)
        #pragma unroll
        for (int j = 0; j < 4; j++) { re[i][j] = 0.f; im[i][j] = 0.f; }
    for (int tau = 0; tau < 32; tau++) {
        float4 v = Vs[tau][tx];
        float vv[4] = {v.x, v.y, v.z, v.w};
        #pragma unroll
        for (int i = 0; i < 8; i++) {
            float2 g2 = gg[(ty * 8 + i - tau + 32) & 31];
            #pragma unroll
            for (int j = 0; j < 4; j++) {
                re[i][j] = fmaf(vv[j], g2.x, re[i][j]);
                im[i][j] = fmaf(vv[j], g2.y, im[i][j]);
            }
        }
    }
    float a1 = g_a1[c], b1 = g_b1[c], a2 = g_a2[c], b2v = g_b2[c];
    #pragma unroll
    for (int i = 0; i < 8; i++) {
        int t = ty * 8 + i;
        #pragma unroll
        for (int j = 0; j < 4; j++) {
            int hw = hw0 + tx * 4 + j;
            float rr = re[i][j], ii = im[i][j];
            if (hw == 0) { rr += qq[t].x; ii += qq[t].y; }
            float x3 = sqrtf(rr * rr + ii * ii);
            size_t idx = base + (size_t)t * 1024 + hw;
            float x1v = fmaxf(fmaf(g_x1[idx], a1, b1), 0.f);
            float x2v = fmaxf(fmaf(g_x2[idx], a2, b2v), 0.f);
            g_s[idx] = x1v + x2v + x3;
        }
    }
}

// K7: fused up GEMM (tf32, K=128 over [h5|s] plane layout) + bias + GELU + residual
__global__ void __launch_bounds__(256) k_up2(const float* __restrict__ x,
                                             float* __restrict__ out) {
    __shared__ uint32_t As[128][36];
    __shared__ uint32_t Bs[128][36];
    int tid = threadIdx.x;
    int r0 = blockIdx.x * 128;
    int n0 = blockIdx.y * 128;
    int bt = r0 >> 10, hw0 = r0 & 1023;
    int b = bt >> 5, t = bt & 31;
    int wid = tid >> 5, lane = tid & 31;
    int g = lane >> 2, tig = lane & 3;
    int warp_m = (wid & 1) * 64;
    int warp_n = (wid >> 1) * 32;

    float acc[4][4][4];
    #pragma unroll
    for (int i = 0; i < 4; i++)
        #pragma unroll
        for (int j = 0; j < 4; j++)
            #pragma unroll
            for (int l = 0; l < 4; l++) acc[i][j][l] = 0.f;

    #pragma unroll
    for (int kc = 0; kc < 4; kc++) {
        int k0 = kc * 32;
        const float* src = (k0 < 64) ? g_h5 : g_s;
        int cb0 = (k0 < 64) ? k0 : (k0 - 64);
        #pragma unroll
        for (int i = 0; i < 4; i++) {
            int idx4 = tid + i * 256;
            int cl = idx4 >> 5, hw4 = (idx4 & 31) * 4;
            size_t adr = ((size_t)((b * 64 + cb0 + cl) * 32 + t)) * 1024 + hw0 + hw4;
            float4 v = *reinterpret_cast<const float4*>(&src[adr]);
            As[hw4 + 0][cl] = f2tf32(v.x); As[hw4 + 1][cl] = f2tf32(v.y);
            As[hw4 + 2][cl] = f2tf32(v.z); As[hw4 + 3][cl] = f2tf32(v.w);
        }
        #pragma unroll
        for (int i = 0; i < 4; i++) {
            int idx4 = tid + i * 256;
            int n = idx4 >> 3, k4 = (idx4 & 7) * 4;
            float4 v = *reinterpret_cast<const float4*>(&g_Wp[(size_t)(n0 + n) * 128 + k0 + k4]);
            Bs[n][k4 + 0] = f2tf32(v.x); Bs[n][k4 + 1] = f2tf32(v.y);
            Bs[n][k4 + 2] = f2tf32(v.z); Bs[n][k4 + 3] = f2tf32(v.w);
        }
        __syncthreads();
        #pragma unroll
        for (int ks = 0; ks < 4; ks++) {
            int kk = ks * 8;
            uint32_t a[4][4];
            #pragma unroll
            for (int mf = 0; mf < 4; mf++) {
                int row = warp_m + mf * 16;
                a[mf][0] = As[row + g    ][kk + tig];
                a[mf][1] = As[row + g + 8][kk + tig];
                a[mf][2] = As[row + g    ][kk + tig + 4];
                a[mf][3] = As[row + g + 8][kk + tig + 4];
            }
            uint32_t bfr[4][2];
            #pragma unroll
            for (int nf = 0; nf < 4; nf++) {
                int col = warp_n + nf * 8;
                bfr[nf][0] = Bs[col + g][kk + tig];
                bfr[nf][1] = Bs[col + g][kk + tig + 4];
            }
            #pragma unroll
            for (int mf = 0; mf < 4; mf++)
                #pragma unroll
                for (int nf = 0; nf < 4; nf++)
                    mma_tf32(acc[mf][nf], a[mf][0], a[mf][1], a[mf][2], a[mf][3],
                             bfr[nf][0], bfr[nf][1]);
        }
        __syncthreads();
    }
    #pragma unroll
    for (int nf = 0; nf < 4; nf++) {
        int col = n0 + warp_n + nf * 8 + 2 * tig;
        float bs0 = g_bp[col], bs1 = g_bp[col + 1];
        #pragma unroll
        for (int mf = 0; mf < 4; mf++) {
            #pragma unroll
            for (int half = 0; half < 2; half++) {
                int row = r0 + warp_m + mf * 16 + g + half * 8;
                float c0 = acc[mf][nf][half * 2 + 0];
                float c1 = acc[mf][nf][half * 2 + 1];
                const float2 xin = *reinterpret_cast<const float2*>(&x[(size_t)row * 384 + col]);
                float2 o;
                o.x = xin.x + gelu_f(c0 + bs0);
                o.y = xin.y + gelu_f(c1 + bs1);
                *reinterpret_cast<float2*>(&out[(size_t)row * 384 + col]) = o;
            }
        }
    }
}

extern "C" void kernel_launch(void* const* d_in, const int* in_sizes, int n_in,
                              void* d_out, int out_size) {
    const float* x      = (const float*)d_in[0];
    const float* down_w = (const float*)d_in[1];
    const float* down_b = (const float*)d_in[2];
    const float* k31w   = (const float*)d_in[3];
    const float* k31b   = (const float*)d_in[4];
    const float* k32w   = (const float*)d_in[5];
    const float* k32b   = (const float*)d_in[6];
    const float* bn3g   = (const float*)d_in[7];
    const float* bn3b   = (const float*)d_in[8];
    const float* k51w   = (const float*)d_in[9];
    const float* k51b   = (const float*)d_in[10];
    const float* k52w   = (const float*)d_in[11];
    const float* k52b   = (const float*)d_in[12];
    const float* bn5g   = (const float*)d_in[13];
    const float* bn5b   = (const float*)d_in[14];
    const float* convw  = (const float*)d_in[15];
    const float* convb  = (const float*)d_in[16];
    const float* fw     = (const float*)d_in[17];
    const float* fb     = (const float*)d_in[18];
    const float* upw    = (const float*)d_in[19];
    const float* upb    = (const float*)d_in[20];
    float* out = (float*)d_out;

    static int smem_set = 0;
    if (!smem_set) {
        cudaFuncSetAttribute(k_conv, cudaFuncAttributeMaxDynamicSharedMemorySize, 114688);
        smem_set = 1;
    }

    k_prep    <<<1, 64>>>(fw, fb);
    k_fold    <<<384, 64>>>(upw, upb, convw, convb);
    k_down    <<<512, 256>>>(x, down_w, down_b);
    k_conv    <<<512, 256, 114688>>>(k31w, k31b, k51w, k51b, k32w, k32b, k52w, k52b);
    k_bn      <<<1, 64>>>(bn3g, bn3b, bn5g, bn5b);
    k_branch3 <<<512, 256>>>();
    {
        dim3 grid(ROWS / 128, 384 / 128);
        k_up2 <<<grid, 256>>>(x, out);
    }
}

// round 7
// speedup vs baseline: 1.0923x; 1.0923x over previous
#include <cuda_runtime.h>
#include <math.h>
#include <stdint.h>

#define LTOT (2*64*32*1024)
#define ROWS 65536

__device__ float g_h5[LTOT];
__device__ float g_x1[LTOT];
__device__ float g_x2[LTOT];
__device__ float g_s [LTOT];

__device__ float g_Wp[384 * 128];
__device__ float g_bp[384];

__device__ float g_gre[32], g_gim[32], g_qre[32], g_qim[32];
__device__ float g_sum1[64], g_sq1[64], g_sum2[64], g_sq2[64];
__device__ float g_a1[64], g_b1[64], g_a2[64], g_b2[64];

__device__ __forceinline__ float gelu_f(float v) {
    return 0.5f * v * (1.0f + erff(v * 0.70710678118654752f));
}

__device__ __forceinline__ uint32_t f2tf32(float f) {
    uint32_t r;
    asm("cvt.rna.tf32.f32 %0, %1;" : "=r"(r) : "f"(f));
    return r;
}

__device__ __forceinline__ uint4 f4tf32(float4 v) {
    uint4 r;
    r.x = f2tf32(v.x); r.y = f2tf32(v.y); r.z = f2tf32(v.z); r.w = f2tf32(v.w);
    return r;
}

__device__ __forceinline__ void mma_tf32(float c[4], uint32_t a0, uint32_t a1,
                                         uint32_t a2, uint32_t a3,
                                         uint32_t b0, uint32_t b1) {
    asm volatile(
        "mma.sync.aligned.m16n8k8.row.col.f32.tf32.tf32.f32 "
        "{%0,%1,%2,%3}, {%4,%5,%6,%7}, {%8,%9}, {%0,%1,%2,%3};"
        : "+f"(c[0]), "+f"(c[1]), "+f"(c[2]), "+f"(c[3])
        : "r"(a0), "r"(a1), "r"(a2), "r"(a3), "r"(b0), "r"(b1));
}

// K0: g = ifft_T(fw), q = ifft_T(fb); zero BN stats
__global__ void k_prep(const float* __restrict__ fw, const float* __restrict__ fb) {
    int n = threadIdx.x;
    if (n < 32) {
        double gr = 0, gi = 0, qr = 0, qi = 0;
        for (int k = 0; k < 32; k++) {
            double ang = 6.283185307179586476925 * (double)((k * n) & 31) / 32.0;
            double cs = cos(ang), sn = sin(ang);
            gr += (double)fw[k] * cs; gi += (double)fw[k] * sn;
            qr += (double)fb[k] * cs; qi += (double)fb[k] * sn;
        }
        g_gre[n] = (float)(gr / 32.0); g_gim[n] = (float)(gi / 32.0);
        g_qre[n] = (float)(qr / 32.0); g_qim[n] = (float)(qi / 32.0);
    }
    if (n < 64) { g_sum1[n] = 0.f; g_sq1[n] = 0.f; g_sum2[n] = 0.f; g_sq2[n] = 0.f; }
}

// K0b: fold channel-mix into up-proj: W' = [U | U*W2], b' = ub + U*cb
__global__ void k_fold(const float* __restrict__ up, const float* __restrict__ upb,
                       const float* __restrict__ w2, const float* __restrict__ cb) {
    int of = blockIdx.x;
    int j = threadIdx.x;   // 0..63
    float m = 0.f;
    #pragma unroll 8
    for (int o2 = 0; o2 < 64; o2++)
        m = fmaf(up[of * 64 + o2], w2[o2 * 64 + j], m);
    g_Wp[of * 128 + j] = up[of * 64 + j];
    g_Wp[of * 128 + 64 + j] = m;
    if (j == 0) {
        float bb = upb[of];
        for (int o2 = 0; o2 < 64; o2++)
            bb = fmaf(up[of * 64 + o2], cb[o2], bb);
        g_bp[of] = bb;
    }
}

// K1: down GEMM (tf32) [65536,384]x[64,384]^T + bias + GELU -> h5 NCDHW
__global__ void __launch_bounds__(256) k_down(const float* __restrict__ x,
                                              const float* __restrict__ w,
                                              const float* __restrict__ bias) {
    __shared__ __align__(16) uint32_t As[128][36];
    __shared__ __align__(16) uint32_t Bs[64][36];
    int tid = threadIdx.x;
    int r0 = blockIdx.x * 128;
    int wid = tid >> 5, lane = tid & 31;
    int g = lane >> 2, tig = lane & 3;
    int warp_m = (wid & 3) * 32;
    int warp_n = (wid >> 2) * 32;

    float acc[2][4][4];
    #pragma unroll
    for (int i = 0; i < 2; i++)
        #pragma unroll
        for (int j = 0; j < 4; j++)
            #pragma unroll
            for (int l = 0; l < 4; l++) acc[i][j][l] = 0.f;

    for (int k0 = 0; k0 < 384; k0 += 32) {
        #pragma unroll
        for (int i = 0; i < 4; i++) {
            int idx4 = tid + i * 256;
            int m = idx4 >> 3, k4 = (idx4 & 7) * 4;
            float4 v = *reinterpret_cast<const float4*>(&x[(size_t)(r0 + m) * 384 + k0 + k4]);
            *reinterpret_cast<uint4*>(&As[m][k4]) = f4tf32(v);
        }
        #pragma unroll
        for (int i = 0; i < 2; i++) {
            int idx4 = tid + i * 256;
            int n = idx4 >> 3, k4 = (idx4 & 7) * 4;
            float4 v = *reinterpret_cast<const float4*>(&w[n * 384 + k0 + k4]);
            *reinterpret_cast<uint4*>(&Bs[n][k4]) = f4tf32(v);
        }
        __syncthreads();
        #pragma unroll
        for (int ks = 0; ks < 4; ks++) {
            int kk = ks * 8;
            uint32_t a[2][4];
            #pragma unroll
            for (int mf = 0; mf < 2; mf++) {
                int row = warp_m + mf * 16;
                a[mf][0] = As[row + g    ][kk + tig];
                a[mf][1] = As[row + g + 8][kk + tig];
                a[mf][2] = As[row + g    ][kk + tig + 4];
                a[mf][3] = As[row + g + 8][kk + tig + 4];
            }
            uint32_t b[4][2];
            #pragma unroll
            for (int nf = 0; nf < 4; nf++) {
                int col = warp_n + nf * 8;
                b[nf][0] = Bs[col + g][kk + tig];
                b[nf][1] = Bs[col + g][kk + tig + 4];
            }
            #pragma unroll
            for (int mf = 0; mf < 2; mf++)
                #pragma unroll
                for (int nf = 0; nf < 4; nf++)
                    mma_tf32(acc[mf][nf], a[mf][0], a[mf][1], a[mf][2], a[mf][3],
                             b[nf][0], b[nf][1]);
        }
        __syncthreads();
    }
    int bt = r0 >> 10, hwbase = r0 & 1023;
    int b5i = bt >> 5, t = bt & 31;
    size_t planebase = (size_t)(b5i * 64) * 32768 + (size_t)t * 1024;
    #pragma unroll
    for (int nf = 0; nf < 4; nf++) {
        int c0 = warp_n + nf * 8 + 2 * tig;
        float bs0 = bias[c0], bs1 = bias[c0 + 1];
        #pragma unroll
        for (int mf = 0; mf < 2; mf++) {
            int m = warp_m + mf * 16 + g;
            size_t p0 = planebase + (size_t)c0 * 32768;
            g_h5[p0 + hwbase + m]             = gelu_f(acc[mf][nf][0] + bs0);
            g_h5[p0 + 32768 + hwbase + m]     = gelu_f(acc[mf][nf][1] + bs1);
            g_h5[p0 + hwbase + m + 8]         = gelu_f(acc[mf][nf][2] + bs0);
            g_h5[p0 + 32768 + hwbase + m + 8] = gelu_f(acc[mf][nf][3] + bs1);
        }
    }
}

// K2: fused spatial(3x3,5x5) + temporal(3,5) depthwise + BN stats
__global__ void __launch_bounds__(256) k_conv(const float* __restrict__ w3g,
                                              const float* __restrict__ b3g,
                                              const float* __restrict__ w5g,
                                              const float* __restrict__ b5g,
                                              const float* __restrict__ wt3g,
                                              const float* __restrict__ bt3g,
                                              const float* __restrict__ wt5g,
                                              const float* __restrict__ bt5g) {
    extern __shared__ float sm[];
    float* in = sm;            // 32*384 = 12288
    float* s3 = sm + 12288;    // 8192
    float* s5 = sm + 20480;    // 8192
    int bc = blockIdx.x >> 2;
    int band = blockIdx.x & 3;
    int h0 = band * 8;
    int c = bc & 63;
    size_t base = (size_t)bc * 32768;
    int tid = threadIdx.x;

    __shared__ float w3s[9], w5s[25], wt3[3], wt5[5];
    if (tid < 9)  w3s[tid] = w3g[c * 9 + tid];
    if (tid >= 32 && tid < 57) w5s[tid - 32] = w5g[c * 25 + (tid - 32)];
    if (tid >= 64 && tid < 67) wt3[tid - 64] = wt3g[c * 3 + (tid - 64)];
    if (tid >= 96 && tid < 101) wt5[tid - 96] = wt5g[c * 5 + (tid - 96)];

    for (int i = tid; i < 12288; i += 256) {
        int t = i / 384; int rem = i - t * 384;
        int hh = rem >> 5, w = rem & 31;
        int gh = h0 - 2 + hh;
        float v = 0.f;
        if ((unsigned)gh < 32u) v = g_h5[base + (size_t)t * 1024 + gh * 32 + w];
        in[i] = v;
    }
    __syncthreads();

    float b3 = b3g[c], b5 = b5g[c];
    for (int i = tid; i < 8192; i += 256) {
        int t = i >> 8, p = i & 255, hl = p >> 5, w = p & 31;
        const float* tin = in + t * 384 + (hl + 2) * 32 + w;
        float a3 = b3;
        #pragma unroll
        for (int dh = -1; dh <= 1; dh++)
            #pragma unroll
            for (int dw = -1; dw <= 1; dw++) {
                int ww = w + dw;
                if ((unsigned)ww < 32u)
                    a3 = fmaf(tin[dh * 32 + dw], w3s[(dh + 1) * 3 + dw + 1], a3);
            }
        float a5 = b5;
        #pragma unroll
        for (int dh = -2; dh <= 2; dh++)
            #pragma unroll
            for (int dw = -2; dw <= 2; dw++) {
                int ww = w + dw;
                if ((unsigned)ww < 32u)
                    a5 = fmaf(tin[dh * 32 + dw], w5s[(dh + 2) * 5 + dw + 2], a5);
            }
        s3[i] = a3;
        s5[i] = a5;
    }
    __syncthreads();

    float bt3 = bt3g[c], bt5 = bt5g[c];
    float s1 = 0, q1 = 0, s2 = 0, q2 = 0;
    for (int i = tid; i < 8192; i += 256) {
        int t = i >> 8, p = i & 255;
        float a = bt3;
        #pragma unroll
        for (int dt = -1; dt <= 1; dt++) {
            int tt = t + dt;
            if ((unsigned)tt < 32u) a = fmaf(s3[tt * 256 + p], wt3[dt + 1], a);
        }
        float e = bt5;
        #pragma unroll
        for (int dt = -2; dt <= 2; dt++) {
            int tt = t + dt;
            if ((unsigned)tt < 32u) e = fmaf(s5[tt * 256 + p], wt5[dt + 2], e);
        }
        size_t gi = base + (size_t)t * 1024 + h0 * 32 + p;
        g_x1[gi] = a;
        g_x2[gi] = e;
        s1 += a; q1 = fmaf(a, a, q1);
        s2 += e; q2 = fmaf(e, e, q2);
    }
    #pragma unroll
    for (int off = 16; off; off >>= 1) {
        s1 += __shfl_down_sync(0xffffffffu, s1, off);
        q1 += __shfl_down_sync(0xffffffffu, q1, off);
        s2 += __shfl_down_sync(0xffffffffu, s2, off);
        q2 += __shfl_down_sync(0xffffffffu, q2, off);
    }
    __shared__ float red[4][8];
    int wid = tid >> 5, lane = tid & 31;
    if (lane == 0) { red[0][wid] = s1; red[1][wid] = q1; red[2][wid] = s2; red[3][wid] = q2; }
    __syncthreads();
    if (tid == 0) {
        float a = 0, b = 0, c2 = 0, d = 0;
        for (int i = 0; i < 8; i++) { a += red[0][i]; b += red[1][i]; c2 += red[2][i]; d += red[3][i]; }
        atomicAdd(&g_sum1[c], a);  atomicAdd(&g_sq1[c], b);
        atomicAdd(&g_sum2[c], c2); atomicAdd(&g_sq2[c], d);
    }
}

// K4: BN scale/shift
__global__ void k_bn(const float* __restrict__ g3, const float* __restrict__ b3,
                     const float* __restrict__ g5, const float* __restrict__ b5) {
    int c = threadIdx.x;
    const float inv = 1.0f / 65536.0f;
    float m1 = g_sum1[c] * inv;
    float v1 = g_sq1[c] * inv - m1 * m1;
    float a1 = g3[c] * rsqrtf(v1 + 1e-5f);
    g_a1[c] = a1; g_b1[c] = b3[c] - m1 * a1;
    float m2 = g_sum2[c] * inv;
    float v2 = g_sq2[c] * inv - m2 * m2;
    float a2 = g5[c] * rsqrtf(v2 + 1e-5f);
    g_a2[c] = a2; g_b2[c] = b5[c] - m2 * a2;
}

// K5: circulant T-conv (FFT branch) + BN-ReLU combine -> s
__global__ void __launch_bounds__(256) k_branch3() {
    int bc  = blockIdx.x >> 2;
    int hw0 = (blockIdx.x & 3) << 8;
    int c = bc & 63;
    size_t base = (size_t)bc * 32768;
    __shared__ float2 gg[64];
    __shared__ float2 qq[32];
    __shared__ __align__(16) float4 Vs[32][64];
    int tid = threadIdx.x;
    if (tid < 64) gg[tid] = make_float2(g_gre[tid & 31], g_gim[tid & 31]);
    if (tid < 32) qq[tid] = make_float2(g_qre[tid], g_qim[tid]);
    for (int i = tid; i < 2048; i += 256) {
        int t = i >> 6, q4 = i & 63;
        Vs[t][q4] = *reinterpret_cast<const float4*>(&g_h5[base + (size_t)t * 1024 + hw0 + q4 * 4]);
    }
    __syncthreads();
    int ty = tid >> 6;
    int tx = tid & 63;
    float re[8][4], im[8][4];
    #pragma unroll
    for (int i = 0; i < 8; i++)
        #pragma unroll
        for (int j = 0; j < 4; j++) { re[i][j] = 0.f; im[i][j] = 0.f; }
    for (int tau = 0; tau < 32; tau++) {
        float4 v = Vs[tau][tx];
        float vv[4] = {v.x, v.y, v.z, v.w};
        #pragma unroll
        for (int i = 0; i < 8; i++) {
            float2 g2 = gg[(ty * 8 + i - tau + 32) & 31];
            #pragma unroll
            for (int j = 0; j < 4; j++) {
                re[i][j] = fmaf(vv[j], g2.x, re[i][j]);
                im[i][j] = fmaf(vv[j], g2.y, im[i][j]);
            }
        }
    }
    float a1 = g_a1[c], b1 = g_b1[c], a2 = g_a2[c], b2v = g_b2[c];
    #pragma unroll
    for (int i = 0; i < 8; i++) {
        int t = ty * 8 + i;
        #pragma unroll
        for (int j = 0; j < 4; j++) {
            int hw = hw0 + tx * 4 + j;
            float rr = re[i][j], ii = im[i][j];
            if (hw == 0) { rr += qq[t].x; ii += qq[t].y; }
            float x3 = sqrtf(rr * rr + ii * ii);
            size_t idx = base + (size_t)t * 1024 + hw;
            float x1v = fmaxf(fmaf(g_x1[idx], a1, b1), 0.f);
            float x2v = fmaxf(fmaf(g_x2[idx], a2, b2v), 0.f);
            g_s[idx] = x1v + x2v + x3;
        }
    }
}

// K7: fused up GEMM (tf32, K=128 over [h5|s]) + bias + GELU + residual
// A tile stored [k=channel][m=hw] pitch 136 (conflict-free fill AND fragment loads)
__global__ void __launch_bounds__(256) k_up2(const float* __restrict__ x,
                                             float* __restrict__ out) {
    __shared__ __align__(16) uint32_t As[32][136];
    __shared__ __align__(16) uint32_t Bs[128][36];
    int tid = threadIdx.x;
    int r0 = blockIdx.x * 128;
    int n0 = blockIdx.y * 128;
    int bt = r0 >> 10, hw0 = r0 & 1023;
    int b = bt >> 5, t = bt & 31;
    int wid = tid >> 5, lane = tid & 31;
    int g = lane >> 2, tig = lane & 3;
    int warp_m = (wid & 1) * 64;
    int warp_n = (wid >> 1) * 32;

    float acc[4][4][4];
    #pragma unroll
    for (int i = 0; i < 4; i++)
        #pragma unroll
        for (int j = 0; j < 4; j++)
            #pragma unroll
            for (int l = 0; l < 4; l++) acc[i][j][l] = 0.f;

    #pragma unroll
    for (int kc = 0; kc < 4; kc++) {
        int k0 = kc * 32;
        const float* src = (k0 < 64) ? g_h5 : g_s;
        int cb0 = (k0 < 64) ? k0 : (k0 - 64);
        #pragma unroll
        for (int i = 0; i < 4; i++) {
            int idx4 = tid + i * 256;
            int cl = idx4 >> 5, hw4 = (idx4 & 31) * 4;
            size_t adr = ((size_t)((b * 64 + cb0 + cl) * 32 + t)) * 1024 + hw0 + hw4;
            float4 v = *reinterpret_cast<const float4*>(&src[adr]);
            *reinterpret_cast<uint4*>(&As[cl][hw4]) = f4tf32(v);
        }
        #pragma unroll
        for (int i = 0; i < 4; i++) {
            int idx4 = tid + i * 256;
            int n = idx4 >> 3, k4 = (idx4 & 7) * 4;
            float4 v = *reinterpret_cast<const float4*>(&g_Wp[(size_t)(n0 + n) * 128 + k0 + k4]);
            *reinterpret_cast<uint4*>(&Bs[n][k4]) = f4tf32(v);
        }
        __syncthreads();
        #pragma unroll
        for (int ks = 0; ks < 4; ks++) {
            int kk = ks * 8;
            uint32_t a[4][4];
            #pragma unroll
            for (int mf = 0; mf < 4; mf++) {
                int row = warp_m + mf * 16;
                a[mf][0] = As[kk + tig    ][row + g];
                a[mf][1] = As[kk + tig    ][row + g + 8];
                a[mf][2] = As[kk + tig + 4][row + g];
                a[mf][3] = As[kk + tig + 4][row + g + 8];
            }
            uint32_t bfr[4][2];
            #pragma unroll
            for (int nf = 0; nf < 4; nf++) {
                int col = warp_n + nf * 8;
                bfr[nf][0] = Bs[col + g][kk + tig];
                bfr[nf][1] = Bs[col + g][kk + tig + 4];
            }
            #pragma unroll
            for (int mf = 0; mf < 4; mf++)
                #pragma unroll
                for (int nf = 0; nf < 4; nf++)
                    mma_tf32(acc[mf][nf], a[mf][0], a[mf][1], a[mf][2], a[mf][3],
                             bfr[nf][0], bfr[nf][1]);
        }
        __syncthreads();
    }
    #pragma unroll
    for (int nf = 0; nf < 4; nf++) {
        int col = n0 + warp_n + nf * 8 + 2 * tig;
        float bs0 = g_bp[col], bs1 = g_bp[col + 1];
        #pragma unroll
        for (int mf = 0; mf < 4; mf++) {
            #pragma unroll
            for (int half = 0; half < 2; half++) {
                int row = r0 + warp_m + mf * 16 + g + half * 8;
                float c0 = acc[mf][nf][half * 2 + 0];
                float c1 = acc[mf][nf][half * 2 + 1];
                const float2 xin = *reinterpret_cast<const float2*>(&x[(size_t)row * 384 + col]);
                float2 o;
                o.x = xin.x + gelu_f(c0 + bs0);
                o.y = xin.y + gelu_f(c1 + bs1);
                *reinterpret_cast<float2*>(&out[(size_t)row * 384 + col]) = o;
            }
        }
    }
}

extern "C" void kernel_launch(void* const* d_in, const int* in_sizes, int n_in,
                              void* d_out, int out_size) {
    const float* x      = (const float*)d_in[0];
    const float* down_w = (const float*)d_in[1];
    const float* down_b = (const float*)d_in[2];
    const float* k31w   = (const float*)d_in[3];
    const float* k31b   = (const float*)d_in[4];
    const float* k32w   = (const float*)d_in[5];
    const float* k32b   = (const float*)d_in[6];
    const float* bn3g   = (const float*)d_in[7];
    const float* bn3b   = (const float*)d_in[8];
    const float* k51w   = (const float*)d_in[9];
    const float* k51b   = (const float*)d_in[10];
    const float* k52w   = (const float*)d_in[11];
    const float* k52b   = (const float*)d_in[12];
    const float* bn5g   = (const float*)d_in[13];
    const float* bn5b   = (const float*)d_in[14];
    const float* convw  = (const float*)d_in[15];
    const float* convb  = (const float*)d_in[16];
    const float* fw     = (const float*)d_in[17];
    const float* fb     = (const float*)d_in[18];
    const float* upw    = (const float*)d_in[19];
    const float* upb    = (const float*)d_in[20];
    float* out = (float*)d_out;

    cudaFuncSetAttribute(k_conv, cudaFuncAttributeMaxDynamicSharedMemorySize, 114688);

    k_prep    <<<1, 64>>>(fw, fb);
    k_fold    <<<384, 64>>>(upw, upb, convw, convb);
    k_down    <<<512, 256>>>(x, down_w, down_b);
    k_conv    <<<512, 256, 114688>>>(k31w, k31b, k51w, k51b, k32w, k32b, k52w, k52b);
    k_bn      <<<1, 64>>>(bn3g, bn3b, bn5g, bn5b);
    k_branch3 <<<512, 256>>>();
    {
        dim3 grid(ROWS / 128, 384 / 128);
        k_up2 <<<grid, 256>>>(x, out);
    }
}

// round 8
// speedup vs baseline: 1.2108x; 1.1084x over previous
#include <cuda_runtime.h>
#include <cuda_fp16.h>
#include <math.h>
#include <stdint.h>

#define LTOT (2*64*32*1024)
#define ROWS 65536

__device__ float g_h5[LTOT];
__device__ float g_x1[LTOT];
__device__ float g_x2[LTOT];
__device__ float g_s [LTOT];

__device__ __align__(16) __half g_Wph[384 * 128];
__device__ float g_bp[384];

__device__ float g_gre[32], g_gim[32], g_qre[32], g_qim[32];
__device__ float g_sum1[64], g_sq1[64], g_sum2[64], g_sq2[64];
__device__ float g_a1[64], g_b1[64], g_a2[64], g_b2[64];

__device__ __forceinline__ float gelu_f(float v) {
    return 0.5f * v * (1.0f + erff(v * 0.70710678118654752f));
}

__device__ __forceinline__ uint32_t pack2(float a, float b) {
    __half2 h = __floats2half2_rn(a, b);
    return *reinterpret_cast<uint32_t*>(&h);
}

__device__ __forceinline__ uint32_t saddr(const void* p) {
    return static_cast<uint32_t>(__cvta_generic_to_shared(p));
}

__device__ __forceinline__ void ldsm4(uint32_t r[4], uint32_t a) {
    asm volatile("ldmatrix.sync.aligned.m8n8.x4.shared.b16 {%0,%1,%2,%3}, [%4];"
                 : "=r"(r[0]), "=r"(r[1]), "=r"(r[2]), "=r"(r[3]) : "r"(a));
}

__device__ __forceinline__ void ldsm4t(uint32_t r[4], uint32_t a) {
    asm volatile("ldmatrix.sync.aligned.m8n8.x4.trans.shared.b16 {%0,%1,%2,%3}, [%4];"
                 : "=r"(r[0]), "=r"(r[1]), "=r"(r[2]), "=r"(r[3]) : "r"(a));
}

__device__ __forceinline__ void mma16816(float c[4], const uint32_t a[4],
                                         uint32_t b0, uint32_t b1) {
    asm volatile(
        "mma.sync.aligned.m16n8k16.row.col.f32.f16.f16.f32 "
        "{%0,%1,%2,%3}, {%4,%5,%6,%7}, {%8,%9}, {%0,%1,%2,%3};"
        : "+f"(c[0]), "+f"(c[1]), "+f"(c[2]), "+f"(c[3])
        : "r"(a[0]), "r"(a[1]), "r"(a[2]), "r"(a[3]), "r"(b0), "r"(b1));
}

// K0: g = ifft_T(fw), q = ifft_T(fb); zero BN stats
__global__ void k_prep(const float* __restrict__ fw, const float* __restrict__ fb) {
    int n = threadIdx.x;
    if (n < 32) {
        double gr = 0, gi = 0, qr = 0, qi = 0;
        for (int k = 0; k < 32; k++) {
            double ang = 6.283185307179586476925 * (double)((k * n) & 31) / 32.0;
            double cs = cos(ang), sn = sin(ang);
            gr += (double)fw[k] * cs; gi += (double)fw[k] * sn;
            qr += (double)fb[k] * cs; qi += (double)fb[k] * sn;
        }
        g_gre[n] = (float)(gr / 32.0); g_gim[n] = (float)(gi / 32.0);
        g_qre[n] = (float)(qr / 32.0); g_qim[n] = (float)(qi / 32.0);
    }
    if (n < 64) { g_sum1[n] = 0.f; g_sq1[n] = 0.f; g_sum2[n] = 0.f; g_sq2[n] = 0.f; }
}

// K0b: fold channel-mix into up-proj (fp16 W'): W' = [U | U*W2], b' = ub + U*cb
__global__ void k_fold(const float* __restrict__ up, const float* __restrict__ upb,
                       const float* __restrict__ w2, const float* __restrict__ cb) {
    int of = blockIdx.x;
    int j = threadIdx.x;   // 0..63
    float m = 0.f;
    #pragma unroll 8
    for (int o2 = 0; o2 < 64; o2++)
        m = fmaf(up[of * 64 + o2], w2[o2 * 64 + j], m);
    g_Wph[of * 128 + j]      = __float2half_rn(up[of * 64 + j]);
    g_Wph[of * 128 + 64 + j] = __float2half_rn(m);
    if (j == 0) {
        float bb = upb[of];
        for (int o2 = 0; o2 < 64; o2++)
            bb = fmaf(up[of * 64 + o2], cb[o2], bb);
        g_bp[of] = bb;
    }
}

// K1: down GEMM (fp16 mma + ldmatrix) [65536,384]x[64,384]^T + bias + GELU -> h5 NCDHW
// block 128M x 64N, 8 warps (4M x 2N), warp tile 32x32, K-chunk 64
__global__ void __launch_bounds__(256) k_down(const float* __restrict__ x,
                                              const float* __restrict__ w,
                                              const float* __restrict__ bias) {
    __shared__ __align__(16) __half As[128][72];
    __shared__ __align__(16) __half Bs[64][72];
    int tid = threadIdx.x;
    int r0 = blockIdx.x * 128;
    int wid = tid >> 5, lane = tid & 31;
    int g = lane >> 2, tig = lane & 3;
    int warp_m = (wid & 3) * 32;
    int warp_n = (wid >> 2) * 32;

    float acc[2][4][4];
    #pragma unroll
    for (int i = 0; i < 2; i++)
        #pragma unroll
        for (int j = 0; j < 4; j++)
            #pragma unroll
            for (int l = 0; l < 4; l++) acc[i][j][l] = 0.f;

    for (int k0 = 0; k0 < 384; k0 += 64) {
        #pragma unroll
        for (int i = 0; i < 4; i++) {
            int idx = tid + i * 256;
            int m = idx >> 3, sg = idx & 7;
            const float4* p = reinterpret_cast<const float4*>(&x[(size_t)(r0 + m) * 384 + k0 + sg * 8]);
            float4 v0 = p[0], v1 = p[1];
            uint4 st;
            st.x = pack2(v0.x, v0.y); st.y = pack2(v0.z, v0.w);
            st.z = pack2(v1.x, v1.y); st.w = pack2(v1.z, v1.w);
            *reinterpret_cast<uint4*>(&As[m][sg * 8]) = st;
        }
        #pragma unroll
        for (int i = 0; i < 2; i++) {
            int idx = tid + i * 256;
            int n = idx >> 3, sg = idx & 7;
            const float4* p = reinterpret_cast<const float4*>(&w[n * 384 + k0 + sg * 8]);
            float4 v0 = p[0], v1 = p[1];
            uint4 st;
            st.x = pack2(v0.x, v0.y); st.y = pack2(v0.z, v0.w);
            st.z = pack2(v1.x, v1.y); st.w = pack2(v1.z, v1.w);
            *reinterpret_cast<uint4*>(&Bs[n][sg * 8]) = st;
        }
        __syncthreads();
        #pragma unroll
        for (int ks = 0; ks < 4; ks++) {
            int kk = ks * 16;
            uint32_t a[2][4];
            #pragma unroll
            for (int mf = 0; mf < 2; mf++)
                ldsm4(a[mf], saddr(&As[warp_m + mf * 16 + (lane & 15)][kk + (lane >> 4) * 8]));
            uint32_t b[2][4];
            #pragma unroll
            for (int h = 0; h < 2; h++)
                ldsm4(b[h], saddr(&Bs[warp_n + h * 16 + ((lane >> 4) & 1) * 8 + (lane & 7)]
                                     [kk + ((lane >> 3) & 1) * 8]));
            #pragma unroll
            for (int mf = 0; mf < 2; mf++)
                #pragma unroll
                for (int nf = 0; nf < 4; nf++)
                    mma16816(acc[mf][nf], a[mf], b[nf >> 1][(nf & 1) * 2], b[nf >> 1][(nf & 1) * 2 + 1]);
        }
        __syncthreads();
    }
    int bt = r0 >> 10, hwbase = r0 & 1023;
    int b5i = bt >> 5, t = bt & 31;
    size_t planebase = (size_t)(b5i * 64) * 32768 + (size_t)t * 1024;
    #pragma unroll
    for (int nf = 0; nf < 4; nf++) {
        int c0 = warp_n + nf * 8 + 2 * tig;
        float bs0 = bias[c0], bs1 = bias[c0 + 1];
        #pragma unroll
        for (int mf = 0; mf < 2; mf++) {
            int m = warp_m + mf * 16 + g;
            size_t p0 = planebase + (size_t)c0 * 32768;
            g_h5[p0 + hwbase + m]             = gelu_f(acc[mf][nf][0] + bs0);
            g_h5[p0 + 32768 + hwbase + m]     = gelu_f(acc[mf][nf][1] + bs1);
            g_h5[p0 + hwbase + m + 8]         = gelu_f(acc[mf][nf][2] + bs0);
            g_h5[p0 + 32768 + hwbase + m + 8] = gelu_f(acc[mf][nf][3] + bs1);
        }
    }
}

// K2: fused spatial(3x3,5x5) + temporal(3,5) depthwise + BN stats
__global__ void __launch_bounds__(256) k_conv(const float* __restrict__ w3g,
                                              const float* __restrict__ b3g,
                                              const float* __restrict__ w5g,
                                              const float* __restrict__ b5g,
                                              const float* __restrict__ wt3g,
                                              const float* __restrict__ bt3g,
                                              const float* __restrict__ wt5g,
                                              const float* __restrict__ bt5g) {
    extern __shared__ float sm[];
    float* in = sm;            // 32*384 = 12288
    float* s3 = sm + 12288;    // 8192
    float* s5 = sm + 20480;    // 8192
    int bc = blockIdx.x >> 2;
    int band = blockIdx.x & 3;
    int h0 = band * 8;
    int c = bc & 63;
    size_t base = (size_t)bc * 32768;
    int tid = threadIdx.x;

    __shared__ float w3s[9], w5s[25], wt3[3], wt5[5];
    if (tid < 9)  w3s[tid] = w3g[c * 9 + tid];
    if (tid >= 32 && tid < 57) w5s[tid - 32] = w5g[c * 25 + (tid - 32)];
    if (tid >= 64 && tid < 67) wt3[tid - 64] = wt3g[c * 3 + (tid - 64)];
    if (tid >= 96 && tid < 101) wt5[tid - 96] = wt5g[c * 5 + (tid - 96)];

    for (int i = tid; i < 12288; i += 256) {
        int t = i / 384; int rem = i - t * 384;
        int hh = rem >> 5, w = rem & 31;
        int gh = h0 - 2 + hh;
        float v = 0.f;
        if ((unsigned)gh < 32u) v = g_h5[base + (size_t)t * 1024 + gh * 32 + w];
        in[i] = v;
    }
    __syncthreads();

    float b3 = b3g[c], b5 = b5g[c];
    for (int i = tid; i < 8192; i += 256) {
        int t = i >> 8, p = i & 255, hl = p >> 5, w = p & 31;
        const float* tin = in + t * 384 + (hl + 2) * 32 + w;
        float a3 = b3;
        #pragma unroll
        for (int dh = -1; dh <= 1; dh++)
            #pragma unroll
            for (int dw = -1; dw <= 1; dw++) {
                int ww = w + dw;
                if ((unsigned)ww < 32u)
                    a3 = fmaf(tin[dh * 32 + dw], w3s[(dh + 1) * 3 + dw + 1], a3);
            }
        float a5 = b5;
        #pragma unroll
        for (int dh = -2; dh <= 2; dh++)
            #pragma unroll
            for (int dw = -2; dw <= 2; dw++) {
                int ww = w + dw;
                if ((unsigned)ww < 32u)
                    a5 = fmaf(tin[dh * 32 + dw], w5s[(dh + 2) * 5 + dw + 2], a5);
            }
        s3[i] = a3;
        s5[i] = a5;
    }
    __syncthreads();

    float bt3 = bt3g[c], bt5 = bt5g[c];
    float s1 = 0, q1 = 0, s2 = 0, q2 = 0;
    for (int i = tid; i < 8192; i += 256) {
        int t = i >> 8, p = i & 255;
        float a = bt3;
        #pragma unroll
        for (int dt = -1; dt <= 1; dt++) {
            int tt = t + dt;
            if ((unsigned)tt < 32u) a = fmaf(s3[tt * 256 + p], wt3[dt + 1], a);
        }
        float e = bt5;
        #pragma unroll
        for (int dt = -2; dt <= 2; dt++) {
            int tt = t + dt;
            if ((unsigned)tt < 32u) e = fmaf(s5[tt * 256 + p], wt5[dt + 2], e);
        }
        size_t gi = base + (size_t)t * 1024 + h0 * 32 + p;
        g_x1[gi] = a;
        g_x2[gi] = e;
        s1 += a; q1 = fmaf(a, a, q1);
        s2 += e; q2 = fmaf(e, e, q2);
    }
    #pragma unroll
    for (int off = 16; off; off >>= 1) {
        s1 += __shfl_down_sync(0xffffffffu, s1, off);
        q1 += __shfl_down_sync(0xffffffffu, q1, off);
        s2 += __shfl_down_sync(0xffffffffu, s2, off);
        q2 += __shfl_down_sync(0xffffffffu, q2, off);
    }
    __shared__ float red[4][8];
    int wid = tid >> 5, lane = tid & 31;
    if (lane == 0) { red[0][wid] = s1; red[1][wid] = q1; red[2][wid] = s2; red[3][wid] = q2; }
    __syncthreads();
    if (tid == 0) {
        float a = 0, b = 0, c2 = 0, d = 0;
        for (int i = 0; i < 8; i++) { a += red[0][i]; b += red[1][i]; c2 += red[2][i]; d += red[3][i]; }
        atomicAdd(&g_sum1[c], a);  atomicAdd(&g_sq1[c], b);
        atomicAdd(&g_sum2[c], c2); atomicAdd(&g_sq2[c], d);
    }
}

// K4: BN scale/shift
__global__ void k_bn(const float* __restrict__ g3, const float* __restrict__ b3,
                     const float* __restrict__ g5, const float* __restrict__ b5) {
    int c = threadIdx.x;
    const float inv = 1.0f / 65536.0f;
    float m1 = g_sum1[c] * inv;
    float v1 = g_sq1[c] * inv - m1 * m1;
    float a1 = g3[c] * rsqrtf(v1 + 1e-5f);
    g_a1[c] = a1; g_b1[c] = b3[c] - m1 * a1;
    float m2 = g_sum2[c] * inv;
    float v2 = g_sq2[c] * inv - m2 * m2;
    float a2 = g5[c] * rsqrtf(v2 + 1e-5f);
    g_a2[c] = a2; g_b2[c] = b5[c] - m2 * a2;
}

// K5: circulant T-conv (FFT branch) + BN-ReLU combine -> s
__global__ void __launch_bounds__(256) k_branch3() {
    int bc  = blockIdx.x >> 2;
    int hw0 = (blockIdx.x & 3) << 8;
    int c = bc & 63;
    size_t base = (size_t)bc * 32768;
    __shared__ float2 gg[64];
    __shared__ float2 qq[32];
    __shared__ __align__(16) float4 Vs[32][64];
    int tid = threadIdx.x;
    if (tid < 64) gg[tid] = make_float2(g_gre[tid & 31], g_gim[tid & 31]);
    if (tid < 32) qq[tid] = make_float2(g_qre[tid], g_qim[tid]);
    for (int i = tid; i < 2048; i += 256) {
        int t = i >> 6, q4 = i & 63;
        Vs[t][q4] = *reinterpret_cast<const float4*>(&g_h5[base + (size_t)t * 1024 + hw0 + q4 * 4]);
    }
    __syncthreads();
    int ty = tid >> 6;
    int tx = tid & 63;
    float re[8][4], im[8][4];
    #pragma unroll
    for (int i = 0; i < 8; i++)
        #pragma unroll
        for (int j = 0; j < 4; j++) { re[i][j] = 0.f; im[i][j] = 0.f; }
    for (int tau = 0; tau < 32; tau++) {
        float4 v = Vs[tau][tx];
        float vv[4] = {v.x, v.y, v.z, v.w};
        #pragma unroll
        for (int i = 0; i < 8; i++) {
            float2 g2 = gg[(ty * 8 + i - tau + 32) & 31];
            #pragma unroll
            for (int j = 0; j < 4; j++) {
                re[i][j] = fmaf(vv[j], g2.x, re[i][j]);
                im[i][j] = fmaf(vv[j], g2.y, im[i][j]);
            }
        }
    }
    float a1 = g_a1[c], b1 = g_b1[c], a2 = g_a2[c], b2v = g_b2[c];
    #pragma unroll
    for (int i = 0; i < 8; i++) {
        int t = ty * 8 + i;
        #pragma unroll
        for (int j = 0; j < 4; j++) {
            int hw = hw0 + tx * 4 + j;
            float rr = re[i][j], ii = im[i][j];
            if (hw == 0) { rr += qq[t].x; ii += qq[t].y; }
            float x3 = sqrtf(rr * rr + ii * ii);
            size_t idx = base + (size_t)t * 1024 + hw;
            float x1v = fmaxf(fmaf(g_x1[idx], a1, b1), 0.f);
            float x2v = fmaxf(fmaf(g_x2[idx], a2, b2v), 0.f);
            g_s[idx] = x1v + x2v + x3;
        }
    }
}

// K7: fused up GEMM (fp16 mma + ldmatrix, K=128 over [h5|s]) + bias + GELU + residual
// A stored [k=channel][m=hw] pitch 136 halves; a-frags via ldmatrix.trans
__global__ void __launch_bounds__(256) k_up2(const float* __restrict__ x,
                                             float* __restrict__ out) {
    __shared__ __align__(16) __half As[64][136];
    __shared__ __align__(16) __half Bs[128][72];
    int tid = threadIdx.x;
    int r0 = blockIdx.x * 128;
    int n0 = blockIdx.y * 128;
    int bt = r0 >> 10, hw0 = r0 & 1023;
    int b = bt >> 5, t = bt & 31;
    int wid = tid >> 5, lane = tid & 31;
    int g = lane >> 2, tig = lane & 3;
    int warp_m = (wid & 1) * 64;
    int warp_n = (wid >> 1) * 32;

    float acc[4][4][4];
    #pragma unroll
    for (int i = 0; i < 4; i++)
        #pragma unroll
        for (int j = 0; j < 4; j++)
            #pragma unroll
            for (int l = 0; l < 4; l++) acc[i][j][l] = 0.f;

    #pragma unroll
    for (int kc = 0; kc < 2; kc++) {
        int k0 = kc * 64;
        const float* src = (kc == 0) ? g_h5 : g_s;
        #pragma unroll
        for (int i = 0; i < 8; i++) {
            int idx = tid + i * 256;
            int cl = idx >> 5, hw4 = (idx & 31) * 4;
            size_t adr = ((size_t)((b * 64 + cl) * 32 + t)) * 1024 + hw0 + hw4;
            float4 v = *reinterpret_cast<const float4*>(&src[adr]);
            uint2 st;
            st.x = pack2(v.x, v.y); st.y = pack2(v.z, v.w);
            *reinterpret_cast<uint2*>(&As[cl][hw4]) = st;
        }
        #pragma unroll
        for (int i = 0; i < 4; i++) {
            int idx = tid + i * 256;
            int n = idx >> 3, sg = idx & 7;
            *reinterpret_cast<uint4*>(&Bs[n][sg * 8]) =
                *reinterpret_cast<const uint4*>(&g_Wph[(size_t)(n0 + n) * 128 + k0 + sg * 8]);
        }
        __syncthreads();
        #pragma unroll
        for (int ks = 0; ks < 4; ks++) {
            int kk = ks * 16;
            uint32_t a[4][4];
            #pragma unroll
            for (int mf = 0; mf < 4; mf++) {
                int krow = kk + (lane & 7) + ((lane >> 4) & 1) * 8;
                int mcol = warp_m + mf * 16 + ((lane >> 3) & 1) * 8;
                ldsm4t(a[mf], saddr(&As[krow][mcol]));
            }
            uint32_t bfr[2][4];
            #pragma unroll
            for (int h = 0; h < 2; h++)
                ldsm4(bfr[h], saddr(&Bs[warp_n + h * 16 + ((lane >> 4) & 1) * 8 + (lane & 7)]
                                       [kk + ((lane >> 3) & 1) * 8]));
            #pragma unroll
            for (int mf = 0; mf < 4; mf++)
                #pragma unroll
                for (int nf = 0; nf < 4; nf++)
                    mma16816(acc[mf][nf], a[mf],
                             bfr[nf >> 1][(nf & 1) * 2], bfr[nf >> 1][(nf & 1) * 2 + 1]);
        }
        __syncthreads();
    }
    #pragma unroll
    for (int nf = 0; nf < 4; nf++) {
        int col = n0 + warp_n + nf * 8 + 2 * tig;
        float bs0 = g_bp[col], bs1 = g_bp[col + 1];
        #pragma unroll
        for (int mf = 0; mf < 4; mf++) {
            #pragma unroll
            for (int half = 0; half < 2; half++) {
                int row = r0 + warp_m + mf * 16 + g + half * 8;
                float c0 = acc[mf][nf][half * 2 + 0];
                float c1 = acc[mf][nf][half * 2 + 1];
                const float2 xin = *reinterpret_cast<const float2*>(&x[(size_t)row * 384 + col]);
                float2 o;
                o.x = xin.x + gelu_f(c0 + bs0);
                o.y = xin.y + gelu_f(c1 + bs1);
                *reinterpret_cast<float2*>(&out[(size_t)row * 384 + col]) = o;
            }
        }
    }
}

extern "C" void kernel_launch(void* const* d_in, const int* in_sizes, int n_in,
                              void* d_out, int out_size) {
    const float* x      = (const float*)d_in[0];
    const float* down_w = (const float*)d_in[1];
    const float* down_b = (const float*)d_in[2];
    const float* k31w   = (const float*)d_in[3];
    const float* k31b   = (const float*)d_in[4];
    const float* k32w   = (const float*)d_in[5];
    const float* k32b   = (const float*)d_in[6];
    const float* bn3g   = (const float*)d_in[7];
    const float* bn3b   = (const float*)d_in[8];
    const float* k51w   = (const float*)d_in[9];
    const float* k51b   = (const float*)d_in[10];
    const float* k52w   = (const float*)d_in[11];
    const float* k52b   = (const float*)d_in[12];
    const float* bn5g   = (const float*)d_in[13];
    const float* bn5b   = (const float*)d_in[14];
    const float* convw  = (const float*)d_in[15];
    const float* convb  = (const float*)d_in[16];
    const float* fw     = (const float*)d_in[17];
    const float* fb     = (const float*)d_in[18];
    const float* upw    = (const float*)d_in[19];
    const float* upb    = (const float*)d_in[20];
    float* out = (float*)d_out;

    cudaFuncSetAttribute(k_conv, cudaFuncAttributeMaxDynamicSharedMemorySize, 114688);

    k_prep    <<<1, 64>>>(fw, fb);
    k_fold    <<<384, 64>>>(upw, upb, convw, convb);
    k_down    <<<512, 256>>>(x, down_w, down_b);
    k_conv    <<<512, 256, 114688>>>(k31w, k31b, k51w, k51b, k32w, k32b, k52w, k52b);
    k_bn      <<<1, 64>>>(bn3g, bn3b, bn5g, bn5b);
    k_branch3 <<<512, 256>>>();
    {
        dim3 grid(ROWS / 128, 384 / 128);
        k_up2 <<<grid, 256>>>(x, out);
    }
}

// round 9
// speedup vs baseline: 1.4613x; 1.2069x over previous
#include <cuda_runtime.h>
#include <cuda_fp16.h>
#include <math.h>
#include <stdint.h>

#define LTOT (2*64*32*1024)
#define ROWS 65536

__device__ float g_h5[LTOT];
__device__ float g_s3[LTOT];
__device__ float g_s5[LTOT];
__device__ float g_x1[LTOT];
__device__ float g_x2[LTOT];
__device__ float g_s [LTOT];
__device__ __align__(16) __half g_yTh[(size_t)ROWS * 64];
__device__ __align__(16) __half g_Wph[384 * 64];

__device__ float g_gre[32], g_gim[32], g_qre[32], g_qim[32];
__device__ float g_sum1[64], g_sq1[64], g_sum2[64], g_sq2[64];
__device__ float g_a1[64], g_b1[64], g_a2[64], g_b2[64];

__device__ __forceinline__ float gelu_f(float v) {
    return 0.5f * v * (1.0f + erff(v * 0.70710678118654752f));
}

__device__ __forceinline__ uint32_t pack2(float a, float b) {
    __half2 h = __floats2half2_rn(a, b);
    return *reinterpret_cast<uint32_t*>(&h);
}

__device__ __forceinline__ uint32_t saddr(const void* p) {
    return static_cast<uint32_t>(__cvta_generic_to_shared(p));
}

__device__ __forceinline__ void ldsm4(uint32_t r[4], uint32_t a) {
    asm volatile("ldmatrix.sync.aligned.m8n8.x4.shared.b16 {%0,%1,%2,%3}, [%4];"
                 : "=r"(r[0]), "=r"(r[1]), "=r"(r[2]), "=r"(r[3]) : "r"(a));
}

__device__ __forceinline__ void mma16816(float c[4], const uint32_t a[4],
                                         uint32_t b0, uint32_t b1) {
    asm volatile(
        "mma.sync.aligned.m16n8k16.row.col.f32.f16.f16.f32 "
        "{%0,%1,%2,%3}, {%4,%5,%6,%7}, {%8,%9}, {%0,%1,%2,%3};"
        : "+f"(c[0]), "+f"(c[1]), "+f"(c[2]), "+f"(c[3])
        : "r"(a[0]), "r"(a[1]), "r"(a[2]), "r"(a[3]), "r"(b0), "r"(b1));
}

// K0: g = ifft_T(fw), q = ifft_T(fb); zero BN stats
__global__ void k_prep(const float* __restrict__ fw, const float* __restrict__ fb) {
    int n = threadIdx.x;
    if (n < 32) {
        double gr = 0, gi = 0, qr = 0, qi = 0;
        for (int k = 0; k < 32; k++) {
            double ang = 6.283185307179586476925 * (double)((k * n) & 31) / 32.0;
            double cs = cos(ang), sn = sin(ang);
            gr += (double)fw[k] * cs; gi += (double)fw[k] * sn;
            qr += (double)fb[k] * cs; qi += (double)fb[k] * sn;
        }
        g_gre[n] = (float)(gr / 32.0); g_gim[n] = (float)(gi / 32.0);
        g_qre[n] = (float)(qr / 32.0); g_qim[n] = (float)(qi / 32.0);
    }
    if (n < 64) { g_sum1[n] = 0.f; g_sq1[n] = 0.f; g_sum2[n] = 0.f; g_sq2[n] = 0.f; }
}

// K0b: up_w -> fp16
__global__ void k_cvt(const float* __restrict__ up) {
    int of = blockIdx.x, j = threadIdx.x;
    g_Wph[of * 64 + j] = __float2half_rn(up[of * 64 + j]);
}

// K1: down GEMM (fp16 mma + ldmatrix) + bias + GELU -> h5 NCDHW
__global__ void __launch_bounds__(256) k_down(const float* __restrict__ x,
                                              const float* __restrict__ w,
                                              const float* __restrict__ bias) {
    __shared__ __align__(16) __half As[128][72];
    __shared__ __align__(16) __half Bs[64][72];
    int tid = threadIdx.x;
    int r0 = blockIdx.x * 128;
    int wid = tid >> 5, lane = tid & 31;
    int g = lane >> 2, tig = lane & 3;
    int warp_m = (wid & 3) * 32;
    int warp_n = (wid >> 2) * 32;

    float acc[2][4][4];
    #pragma unroll
    for (int i = 0; i < 2; i++)
        #pragma unroll
        for (int j = 0; j < 4; j++)
            #pragma unroll
            for (int l = 0; l < 4; l++) acc[i][j][l] = 0.f;

    for (int k0 = 0; k0 < 384; k0 += 64) {
        #pragma unroll
        for (int i = 0; i < 4; i++) {
            int idx = tid + i * 256;
            int m = idx >> 3, sg = idx & 7;
            const float4* p = reinterpret_cast<const float4*>(&x[(size_t)(r0 + m) * 384 + k0 + sg * 8]);
            float4 v0 = p[0], v1 = p[1];
            uint4 st;
            st.x = pack2(v0.x, v0.y); st.y = pack2(v0.z, v0.w);
            st.z = pack2(v1.x, v1.y); st.w = pack2(v1.z, v1.w);
            *reinterpret_cast<uint4*>(&As[m][sg * 8]) = st;
        }
        #pragma unroll
        for (int i = 0; i < 2; i++) {
            int idx = tid + i * 256;
            int n = idx >> 3, sg = idx & 7;
            const float4* p = reinterpret_cast<const float4*>(&w[n * 384 + k0 + sg * 8]);
            float4 v0 = p[0], v1 = p[1];
            uint4 st;
            st.x = pack2(v0.x, v0.y); st.y = pack2(v0.z, v0.w);
            st.z = pack2(v1.x, v1.y); st.w = pack2(v1.z, v1.w);
            *reinterpret_cast<uint4*>(&Bs[n][sg * 8]) = st;
        }
        __syncthreads();
        #pragma unroll
        for (int ks = 0; ks < 4; ks++) {
            int kk = ks * 16;
            uint32_t a[2][4];
            #pragma unroll
            for (int mf = 0; mf < 2; mf++)
                ldsm4(a[mf], saddr(&As[warp_m + mf * 16 + (lane & 15)][kk + (lane >> 4) * 8]));
            uint32_t b[2][4];
            #pragma unroll
            for (int h = 0; h < 2; h++)
                ldsm4(b[h], saddr(&Bs[warp_n + h * 16 + ((lane >> 4) & 1) * 8 + (lane & 7)]
                                     [kk + ((lane >> 3) & 1) * 8]));
            #pragma unroll
            for (int mf = 0; mf < 2; mf++)
                #pragma unroll
                for (int nf = 0; nf < 4; nf++)
                    mma16816(acc[mf][nf], a[mf], b[nf >> 1][(nf & 1) * 2], b[nf >> 1][(nf & 1) * 2 + 1]);
        }
        __syncthreads();
    }
    int bt = r0 >> 10, hwbase = r0 & 1023;
    int b5i = bt >> 5, t = bt & 31;
    size_t planebase = (size_t)(b5i * 64) * 32768 + (size_t)t * 1024;
    #pragma unroll
    for (int nf = 0; nf < 4; nf++) {
        int c0 = warp_n + nf * 8 + 2 * tig;
        float bs0 = bias[c0], bs1 = bias[c0 + 1];
        #pragma unroll
        for (int mf = 0; mf < 2; mf++) {
            int m = warp_m + mf * 16 + g;
            size_t p0 = planebase + (size_t)c0 * 32768;
            g_h5[p0 + hwbase + m]             = gelu_f(acc[mf][nf][0] + bs0);
            g_h5[p0 + 32768 + hwbase + m]     = gelu_f(acc[mf][nf][1] + bs1);
            g_h5[p0 + hwbase + m + 8]         = gelu_f(acc[mf][nf][2] + bs0);
            g_h5[p0 + 32768 + hwbase + m + 8] = gelu_f(acc[mf][nf][3] + bs1);
        }
    }
}

// K2: spatial depthwise 3x3 and 5x5 per (b,c,t) slice
__global__ void __launch_bounds__(256) k_spatial(const float* __restrict__ w3g,
                                                 const float* __restrict__ b3g,
                                                 const float* __restrict__ w5g,
                                                 const float* __restrict__ b5g) {
    int bct = blockIdx.x;
    int c = (bct >> 5) & 63;
    __shared__ float tile[1024];
    __shared__ float w3[9], w5[25];
    int tid = threadIdx.x;
    if (tid < 9)  w3[tid] = w3g[c * 9 + tid];
    if (tid >= 32 && tid < 57) w5[tid - 32] = w5g[c * 25 + (tid - 32)];
    const float* src = g_h5 + (size_t)bct * 1024;
    for (int i = tid; i < 1024; i += 256) tile[i] = src[i];
    __syncthreads();
    float b3 = b3g[c], b5 = b5g[c];
    for (int p = tid; p < 1024; p += 256) {
        int h = p >> 5, wq = p & 31;
        float a3 = b3;
        #pragma unroll
        for (int dh = -1; dh <= 1; dh++) {
            int hh = h + dh;
            if ((unsigned)hh >= 32u) continue;
            #pragma unroll
            for (int dw = -1; dw <= 1; dw++) {
                int ww = wq + dw;
                if ((unsigned)ww >= 32u) continue;
                a3 = fmaf(tile[hh * 32 + ww], w3[(dh + 1) * 3 + dw + 1], a3);
            }
        }
        float a5 = b5;
        #pragma unroll
        for (int dh = -2; dh <= 2; dh++) {
            int hh = h + dh;
            if ((unsigned)hh >= 32u) continue;
            #pragma unroll
            for (int dw = -2; dw <= 2; dw++) {
                int ww = wq + dw;
                if ((unsigned)ww >= 32u) continue;
                a5 = fmaf(tile[hh * 32 + ww], w5[(dh + 2) * 5 + dw + 2], a5);
            }
        }
        g_s3[(size_t)bct * 1024 + p] = a3;
        g_s5[(size_t)bct * 1024 + p] = a5;
    }
}

// K3: temporal depthwise 3/5-tap + BN stats (smem tiled)
__global__ void __launch_bounds__(256) k_temporal(const float* __restrict__ w3g,
                                                  const float* __restrict__ b3g,
                                                  const float* __restrict__ w5g,
                                                  const float* __restrict__ b5g) {
    int bc  = blockIdx.x >> 3;
    int hw0 = (blockIdx.x & 7) << 7;
    int c = bc & 63;
    size_t base = (size_t)bc * 32768;
    __shared__ float s3t[32][128];
    __shared__ float s5t[32][128];
    int tid = threadIdx.x;
    for (int i = tid; i < 4096; i += 256) {
        int t = i >> 7, p = i & 127;
        s3t[t][p] = g_s3[base + (size_t)t * 1024 + hw0 + p];
        s5t[t][p] = g_s5[base + (size_t)t * 1024 + hw0 + p];
    }
    __syncthreads();
    float w3[3], w5[5];
    #pragma unroll
    for (int i = 0; i < 3; i++) w3[i] = w3g[c * 3 + i];
    #pragma unroll
    for (int i = 0; i < 5; i++) w5[i] = w5g[c * 5 + i];
    float b3 = b3g[c], b5 = b5g[c];
    float s1 = 0, q1 = 0, s2 = 0, q2 = 0;
    for (int i = tid; i < 4096; i += 256) {
        int t = i >> 7, p = i & 127;
        float a = b3;
        #pragma unroll
        for (int dt = -1; dt <= 1; dt++) {
            int tt = t + dt;
            if ((unsigned)tt < 32u) a = fmaf(s3t[tt][p], w3[dt + 1], a);
        }
        float e = b5;
        #pragma unroll
        for (int dt = -2; dt <= 2; dt++) {
            int tt = t + dt;
            if ((unsigned)tt < 32u) e = fmaf(s5t[tt][p], w5[dt + 2], e);
        }
        g_x1[base + (size_t)t * 1024 + hw0 + p] = a;
        g_x2[base + (size_t)t * 1024 + hw0 + p] = e;
        s1 += a; q1 = fmaf(a, a, q1);
        s2 += e; q2 = fmaf(e, e, q2);
    }
    #pragma unroll
    for (int off = 16; off; off >>= 1) {
        s1 += __shfl_down_sync(0xffffffffu, s1, off);
        q1 += __shfl_down_sync(0xffffffffu, q1, off);
        s2 += __shfl_down_sync(0xffffffffu, s2, off);
        q2 += __shfl_down_sync(0xffffffffu, q2, off);
    }
    __shared__ float red[4][8];
    int wid = threadIdx.x >> 5, lane = threadIdx.x & 31;
    if (lane == 0) { red[0][wid] = s1; red[1][wid] = q1; red[2][wid] = s2; red[3][wid] = q2; }
    __syncthreads();
    if (threadIdx.x == 0) {
        float a = 0, b = 0, c2 = 0, d = 0;
        for (int i = 0; i < 8; i++) { a += red[0][i]; b += red[1][i]; c2 += red[2][i]; d += red[3][i]; }
        atomicAdd(&g_sum1[c], a);  atomicAdd(&g_sq1[c], b);
        atomicAdd(&g_sum2[c], c2); atomicAdd(&g_sq2[c], d);
    }
}

// K4: BN scale/shift
__global__ void k_bn(const float* __restrict__ g3, const float* __restrict__ b3,
                     const float* __restrict__ g5, const float* __restrict__ b5) {
    int c = threadIdx.x;
    const float inv = 1.0f / 65536.0f;
    float m1 = g_sum1[c] * inv;
    float v1 = g_sq1[c] * inv - m1 * m1;
    float a1 = g3[c] * rsqrtf(v1 + 1e-5f);
    g_a1[c] = a1; g_b1[c] = b3[c] - m1 * a1;
    float m2 = g_sum2[c] * inv;
    float v2 = g_sq2[c] * inv - m2 * m2;
    float a2 = g5[c] * rsqrtf(v2 + 1e-5f);
    g_a2[c] = a2; g_b2[c] = b5[c] - m2 * a2;
}

// K5: circulant T-conv (FFT branch) + BN-ReLU combine -> s
__global__ void __launch_bounds__(256) k_branch3() {
    int bc  = blockIdx.x >> 2;
    int hw0 = (blockIdx.x & 3) << 8;
    int c = bc & 63;
    size_t base = (size_t)bc * 32768;
    __shared__ float2 gg[64];
    __shared__ float2 qq[32];
    __shared__ __align__(16) float4 Vs[32][64];
    int tid = threadIdx.x;
    if (tid < 64) gg[tid] = make_float2(g_gre[tid & 31], g_gim[tid & 31]);
    if (tid < 32) qq[tid] = make_float2(g_qre[tid], g_qim[tid]);
    for (int i = tid; i < 2048; i += 256) {
        int t = i >> 6, q4 = i & 63;
        Vs[t][q4] = *reinterpret_cast<const float4*>(&g_h5[base + (size_t)t * 1024 + hw0 + q4 * 4]);
    }
    __syncthreads();
    int ty = tid >> 6;
    int tx = tid & 63;
    float re[8][4], im[8][4];
    #pragma unroll
    for (int i = 0; i < 8; i++)
        #pragma unroll
        for (int j = 0; j < 4; j++) { re[i][j] = 0.f; im[i][j] = 0.f; }
    for (int tau = 0; tau < 32; tau++) {
        float4 v = Vs[tau][tx];
        float vv[4] = {v.x, v.y, v.z, v.w};
        #pragma unroll
        for (int i = 0; i < 8; i++) {
            float2 g2 = gg[(ty * 8 + i - tau + 32) & 31];
            #pragma unroll
            for (int j = 0; j < 4; j++) {
                re[i][j] = fmaf(vv[j], g2.x, re[i][j]);
                im[i][j] = fmaf(vv[j], g2.y, im[i][j]);
            }
        }
    }
    float a1 = g_a1[c], b1 = g_b1[c], a2 = g_a2[c], b2v = g_b2[c];
    #pragma unroll
    for (int i = 0; i < 8; i++) {
        int t = ty * 8 + i;
        #pragma unroll
        for (int j = 0; j < 4; j++) {
            int hw = hw0 + tx * 4 + j;
            float rr = re[i][j], ii = im[i][j];
            if (hw == 0) { rr += qq[t].x; ii += qq[t].y; }
            float x3 = sqrtf(rr * rr + ii * ii);
            size_t idx = base + (size_t)t * 1024 + hw;
            float x1v = fmaxf(fmaf(g_x1[idx], a1, b1), 0.f);
            float x2v = fmaxf(fmaf(g_x2[idx], a2, b2v), 0.f);
            g_s[idx] = x1v + x2v + x3;
        }
    }
}

// K6: 64x64 channel mix + shortcut -> yT fp16 [row][c]
__global__ void __launch_bounds__(256) k_mix(const float* __restrict__ w2,
                                             const float* __restrict__ cb) {
    int bt  = blockIdx.x >> 3;
    int hw0 = (blockIdx.x & 7) << 7;
    int b = bt >> 5, t = bt & 31;
    __shared__ float W2t[64][64];
    __shared__ float st[64][128];
    int tid = threadIdx.x;
    for (int i = tid; i < 4096; i += 256) {
        int o = i & 63, cx = i >> 6;
        W2t[cx][o] = w2[o * 64 + cx];
    }
    for (int i = tid; i < 8192; i += 256) {
        int cx = i >> 7, p = i & 127;
        st[cx][p] = g_s[(size_t)((b * 64 + cx) * 32 + t) * 1024 + hw0 + p];
    }
    __syncthreads();
    int to  = tid & 15;
    int thw = tid >> 4;
    float acc[8][4];
    #pragma unroll
    for (int i = 0; i < 8; i++)
        #pragma unroll
        for (int j = 0; j < 4; j++) acc[i][j] = 0.f;
    for (int cx = 0; cx < 64; cx++) {
        float sv[8], wv[4];
        #pragma unroll
        for (int i = 0; i < 8; i++) sv[i] = st[cx][thw * 8 + i];
        #pragma unroll
        for (int j = 0; j < 4; j++) wv[j] = W2t[cx][to * 4 + j];
        #pragma unroll
        for (int i = 0; i < 8; i++)
            #pragma unroll
            for (int j = 0; j < 4; j++)
                acc[i][j] = fmaf(wv[j], sv[i], acc[i][j]);
    }
    float cbv[4];
    #pragma unroll
    for (int j = 0; j < 4; j++) cbv[j] = cb[to * 4 + j];
    #pragma unroll
    for (int i = 0; i < 8; i++) {
        int hw = hw0 + thw * 8 + i;
        float o0 = g_h5[(size_t)((b * 64 + to * 4 + 0) * 32 + t) * 1024 + hw] + acc[i][0] + cbv[0];
        float o1 = g_h5[(size_t)((b * 64 + to * 4 + 1) * 32 + t) * 1024 + hw] + acc[i][1] + cbv[1];
        float o2 = g_h5[(size_t)((b * 64 + to * 4 + 2) * 32 + t) * 1024 + hw] + acc[i][2] + cbv[2];
        float o3 = g_h5[(size_t)((b * 64 + to * 4 + 3) * 32 + t) * 1024 + hw] + acc[i][3] + cbv[3];
        uint2 st2;
        st2.x = pack2(o0, o1);
        st2.y = pack2(o2, o3);
        *reinterpret_cast<uint2*>(&g_yTh[((size_t)bt * 1024 + hw) * 64 + to * 4]) = st2;
    }
}

// K7: up GEMM (fp16 mma + ldmatrix, K=64 single chunk) + bias + GELU + residual
__global__ void __launch_bounds__(256) k_up(const float* __restrict__ x,
                                            const float* __restrict__ bias,
                                            float* __restrict__ out) {
    __shared__ __align__(16) __half As[128][72];
    __shared__ __align__(16) __half Bs[128][72];
    int tid = threadIdx.x;
    int r0 = blockIdx.x * 128;
    int n0 = blockIdx.y * 128;
    int wid = tid >> 5, lane = tid & 31;
    int g = lane >> 2, tig = lane & 3;
    int warp_m = (wid & 1) * 64;
    int warp_n = (wid >> 1) * 32;

    float acc[4][4][4];
    #pragma unroll
    for (int i = 0; i < 4; i++)
        #pragma unroll
        for (int j = 0; j < 4; j++)
            #pragma unroll
            for (int l = 0; l < 4; l++) acc[i][j][l] = 0.f;

    #pragma unroll
    for (int i = 0; i < 4; i++) {
        int idx = tid + i * 256;
        int m = idx >> 3, sg = idx & 7;
        *reinterpret_cast<uint4*>(&As[m][sg * 8]) =
            *reinterpret_cast<const uint4*>(&g_yTh[(size_t)(r0 + m) * 64 + sg * 8]);
    }
    #pragma unroll
    for (int i = 0; i < 4; i++) {
        int idx = tid + i * 256;
        int n = idx >> 3, sg = idx & 7;
        *reinterpret_cast<uint4*>(&Bs[n][sg * 8]) =
            *reinterpret_cast<const uint4*>(&g_Wph[(size_t)(n0 + n) * 64 + sg * 8]);
    }
    __syncthreads();
    #pragma unroll
    for (int ks = 0; ks < 4; ks++) {
        int kk = ks * 16;
        uint32_t a[4][4];
        #pragma unroll
        for (int mf = 0; mf < 4; mf++)
            ldsm4(a[mf], saddr(&As[warp_m + mf * 16 + (lane & 15)][kk + (lane >> 4) * 8]));
        uint32_t bfr[2][4];
        #pragma unroll
        for (int h = 0; h < 2; h++)
            ldsm4(bfr[h], saddr(&Bs[warp_n + h * 16 + ((lane >> 4) & 1) * 8 + (lane & 7)]
                                   [kk + ((lane >> 3) & 1) * 8]));
        #pragma unroll
        for (int mf = 0; mf < 4; mf++)
            #pragma unroll
            for (int nf = 0; nf < 4; nf++)
                mma16816(acc[mf][nf], a[mf],
                         bfr[nf >> 1][(nf & 1) * 2], bfr[nf >> 1][(nf & 1) * 2 + 1]);
    }
    #pragma unroll
    for (int nf = 0; nf < 4; nf++) {
        int col = n0 + warp_n + nf * 8 + 2 * tig;
        float bs0 = bias[col], bs1 = bias[col + 1];
        #pragma unroll
        for (int mf = 0; mf < 4; mf++) {
            #pragma unroll
            for (int half = 0; half < 2; half++) {
                int row = r0 + warp_m + mf * 16 + g + half * 8;
                float c0 = acc[mf][nf][half * 2 + 0];
                float c1 = acc[mf][nf][half * 2 + 1];
                const float2 xin = *reinterpret_cast<const float2*>(&x[(size_t)row * 384 + col]);
                float2 o;
                o.x = xin.x + gelu_f(c0 + bs0);
                o.y = xin.y + gelu_f(c1 + bs1);
                *reinterpret_cast<float2*>(&out[(size_t)row * 384 + col]) = o;
            }
        }
    }
}

extern "C" void kernel_launch(void* const* d_in, const int* in_sizes, int n_in,
                              void* d_out, int out_size) {
    const float* x      = (const float*)d_in[0];
    const float* down_w = (const float*)d_in[1];
    const float* down_b = (const float*)d_in[2];
    const float* k31w   = (const float*)d_in[3];
    const float* k31b   = (const float*)d_in[4];
    const float* k32w   = (const float*)d_in[5];
    const float* k32b   = (const float*)d_in[6];
    const float* bn3g   = (const float*)d_in[7];
    const float* bn3b   = (const float*)d_in[8];
    const float* k51w   = (const float*)d_in[9];
    const float* k51b   = (const float*)d_in[10];
    const float* k52w   = (const float*)d_in[11];
    const float* k52b   = (const float*)d_in[12];
    const float* bn5g   = (const float*)d_in[13];
    const float* bn5b   = (const float*)d_in[14];
    const float* convw  = (const float*)d_in[15];
    const float* convb  = (const float*)d_in[16];
    const float* fw     = (const float*)d_in[17];
    const float* fb     = (const float*)d_in[18];
    const float* upw    = (const float*)d_in[19];
    const float* upb    = (const float*)d_in[20];
    float* out = (float*)d_out;

    k_prep    <<<1, 64>>>(fw, fb);
    k_cvt     <<<384, 64>>>(upw);
    k_down    <<<512, 256>>>(x, down_w, down_b);
    k_spatial <<<4096, 256>>>(k31w, k31b, k51w, k51b);
    k_temporal<<<1024, 256>>>(k32w, k32b, k52w, k52b);
    k_bn      <<<1, 64>>>(bn3g, bn3b, bn5g, bn5b);
    k_branch3 <<<512, 256>>>();
    k_mix     <<<512, 256>>>(convw, convb);
    {
        dim3 grid(ROWS / 128, 384 / 128);
        k_up <<<grid, 256>>>(x, upb, out);
    }
}

// round 10
// speedup vs baseline: 1.6177x; 1.1070x over previous
#include <cuda_runtime.h>
#include <cuda_fp16.h>
#include <math.h>
#include <stdint.h>

#define LTOT (2*64*32*1024)
#define ROWS 65536

__device__ float g_h5[LTOT];
__device__ __align__(16) __half g_s3h[LTOT];
__device__ __align__(16) __half g_s5h[LTOT];
__device__ __align__(16) __half2 g_x12[LTOT];
__device__ float g_s [LTOT];
__device__ __align__(16) __half g_yTh[(size_t)ROWS * 64];
__device__ __align__(16) __half g_Wph[384 * 64];

__device__ float g_gre[32], g_gim[32], g_qre[32], g_qim[32];
__device__ float g_sum1[64], g_sq1[64], g_sum2[64], g_sq2[64];
__device__ float g_a1[64], g_b1[64], g_a2[64], g_b2[64];

__device__ __forceinline__ float gelu_f(float v) {
    return 0.5f * v * (1.0f + erff(v * 0.70710678118654752f));
}

__device__ __forceinline__ uint32_t pack2(float a, float b) {
    __half2 h = __floats2half2_rn(a, b);
    return *reinterpret_cast<uint32_t*>(&h);
}

__device__ __forceinline__ uint32_t saddr(const void* p) {
    return static_cast<uint32_t>(__cvta_generic_to_shared(p));
}

__device__ __forceinline__ void ldsm4(uint32_t r[4], uint32_t a) {
    asm volatile("ldmatrix.sync.aligned.m8n8.x4.shared.b16 {%0,%1,%2,%3}, [%4];"
                 : "=r"(r[0]), "=r"(r[1]), "=r"(r[2]), "=r"(r[3]) : "r"(a));
}

__device__ __forceinline__ void mma16816(float c[4], const uint32_t a[4],
                                         uint32_t b0, uint32_t b1) {
    asm volatile(
        "mma.sync.aligned.m16n8k16.row.col.f32.f16.f16.f32 "
        "{%0,%1,%2,%3}, {%4,%5,%6,%7}, {%8,%9}, {%0,%1,%2,%3};"
        : "+f"(c[0]), "+f"(c[1]), "+f"(c[2]), "+f"(c[3])
        : "r"(a[0]), "r"(a[1]), "r"(a[2]), "r"(a[3]), "r"(b0), "r"(b1));
}

// K0: g = ifft_T(fw), q = ifft_T(fb); zero BN stats
__global__ void k_prep(const float* __restrict__ fw, const float* __restrict__ fb) {
    int n = threadIdx.x;
    if (n < 32) {
        double gr = 0, gi = 0, qr = 0, qi = 0;
        for (int k = 0; k < 32; k++) {
            double ang = 6.283185307179586476925 * (double)((k * n) & 31) / 32.0;
            double cs = cos(ang), sn = sin(ang);
            gr += (double)fw[k] * cs; gi += (double)fw[k] * sn;
            qr += (double)fb[k] * cs; qi += (double)fb[k] * sn;
        }
        g_gre[n] = (float)(gr / 32.0); g_gim[n] = (float)(gi / 32.0);
        g_qre[n] = (float)(qr / 32.0); g_qim[n] = (float)(qi / 32.0);
    }
    if (n < 64) { g_sum1[n] = 0.f; g_sq1[n] = 0.f; g_sum2[n] = 0.f; g_sq2[n] = 0.f; }
}

// K0b: up_w -> fp16
__global__ void k_cvt(const float* __restrict__ up) {
    int of = blockIdx.x, j = threadIdx.x;
    g_Wph[of * 64 + j] = __float2half_rn(up[of * 64 + j]);
}

// K1: down GEMM (fp16 mma + ldmatrix) + bias + GELU -> h5 NCDHW
__global__ void __launch_bounds__(256) k_down(const float* __restrict__ x,
                                              const float* __restrict__ w,
                                              const float* __restrict__ bias) {
    __shared__ __align__(16) __half As[128][72];
    __shared__ __align__(16) __half Bs[64][72];
    int tid = threadIdx.x;
    int r0 = blockIdx.x * 128;
    int wid = tid >> 5, lane = tid & 31;
    int g = lane >> 2, tig = lane & 3;
    int warp_m = (wid & 3) * 32;
    int warp_n = (wid >> 2) * 32;

    float acc[2][4][4];
    #pragma unroll
    for (int i = 0; i < 2; i++)
        #pragma unroll
        for (int j = 0; j < 4; j++)
            #pragma unroll
            for (int l = 0; l < 4; l++) acc[i][j][l] = 0.f;

    for (int k0 = 0; k0 < 384; k0 += 64) {
        #pragma unroll
        for (int i = 0; i < 4; i++) {
            int idx = tid + i * 256;
            int m = idx >> 3, sg = idx & 7;
            const float4* p = reinterpret_cast<const float4*>(&x[(size_t)(r0 + m) * 384 + k0 + sg * 8]);
            float4 v0 = p[0], v1 = p[1];
            uint4 st;
            st.x = pack2(v0.x, v0.y); st.y = pack2(v0.z, v0.w);
            st.z = pack2(v1.x, v1.y); st.w = pack2(v1.z, v1.w);
            *reinterpret_cast<uint4*>(&As[m][sg * 8]) = st;
        }
        #pragma unroll
        for (int i = 0; i < 2; i++) {
            int idx = tid + i * 256;
            int n = idx >> 3, sg = idx & 7;
            const float4* p = reinterpret_cast<const float4*>(&w[n * 384 + k0 + sg * 8]);
            float4 v0 = p[0], v1 = p[1];
            uint4 st;
            st.x = pack2(v0.x, v0.y); st.y = pack2(v0.z, v0.w);
            st.z = pack2(v1.x, v1.y); st.w = pack2(v1.z, v1.w);
            *reinterpret_cast<uint4*>(&Bs[n][sg * 8]) = st;
        }
        __syncthreads();
        #pragma unroll
        for (int ks = 0; ks < 4; ks++) {
            int kk = ks * 16;
            uint32_t a[2][4];
            #pragma unroll
            for (int mf = 0; mf < 2; mf++)
                ldsm4(a[mf], saddr(&As[warp_m + mf * 16 + (lane & 15)][kk + (lane >> 4) * 8]));
            uint32_t b[2][4];
            #pragma unroll
            for (int h = 0; h < 2; h++)
                ldsm4(b[h], saddr(&Bs[warp_n + h * 16 + ((lane >> 4) & 1) * 8 + (lane & 7)]
                                     [kk + ((lane >> 3) & 1) * 8]));
            #pragma unroll
            for (int mf = 0; mf < 2; mf++)
                #pragma unroll
                for (int nf = 0; nf < 4; nf++)
                    mma16816(acc[mf][nf], a[mf], b[nf >> 1][(nf & 1) * 2], b[nf >> 1][(nf & 1) * 2 + 1]);
        }
        __syncthreads();
    }
    int bt = r0 >> 10, hwbase = r0 & 1023;
    int b5i = bt >> 5, t = bt & 31;
    size_t planebase = (size_t)(b5i * 64) * 32768 + (size_t)t * 1024;
    #pragma unroll
    for (int nf = 0; nf < 4; nf++) {
        int c0 = warp_n + nf * 8 + 2 * tig;
        float bs0 = bias[c0], bs1 = bias[c0 + 1];
        #pragma unroll
        for (int mf = 0; mf < 2; mf++) {
            int m = warp_m + mf * 16 + g;
            size_t p0 = planebase + (size_t)c0 * 32768;
            g_h5[p0 + hwbase + m]             = gelu_f(acc[mf][nf][0] + bs0);
            g_h5[p0 + 32768 + hwbase + m]     = gelu_f(acc[mf][nf][1] + bs1);
            g_h5[p0 + hwbase + m + 8]         = gelu_f(acc[mf][nf][2] + bs0);
            g_h5[p0 + 32768 + hwbase + m + 8] = gelu_f(acc[mf][nf][3] + bs1);
        }
    }
}

// K2: spatial depthwise 3x3+5x5, register-cached, 4 px/thread -> fp16 s3/s5
__global__ void __launch_bounds__(256) k_spatial(const float* __restrict__ w3g,
                                                 const float* __restrict__ b3g,
                                                 const float* __restrict__ w5g,
                                                 const float* __restrict__ b5g) {
    int bct = blockIdx.x;
    int c = (bct >> 5) & 63;
    __shared__ float tile[32 * 33];
    __shared__ float w3[9], w5[25];
    int tid = threadIdx.x;
    if (tid < 9)  w3[tid] = w3g[c * 9 + tid];
    if (tid >= 32 && tid < 57) w5[tid - 32] = w5g[c * 25 + (tid - 32)];
    const float* src = g_h5 + (size_t)bct * 1024;
    for (int i = tid; i < 1024; i += 256) tile[(i >> 5) * 33 + (i & 31)] = src[i];
    __syncthreads();
    float b3 = b3g[c], b5 = b5g[c];
    int h = tid >> 3;
    int w0 = (tid & 7) * 4;
    float a3[4] = {b3, b3, b3, b3};
    float a5[4] = {b5, b5, b5, b5};
    #pragma unroll
    for (int dh = -2; dh <= 2; dh++) {
        int hh = h + dh;
        if ((unsigned)hh >= 32u) continue;
        float r[8];
        #pragma unroll
        for (int j = 0; j < 8; j++) {
            int ww = w0 - 2 + j;
            r[j] = ((unsigned)ww < 32u) ? tile[hh * 33 + ww] : 0.f;
        }
        #pragma unroll
        for (int px = 0; px < 4; px++)
            #pragma unroll
            for (int dw = 0; dw < 5; dw++)
                a5[px] = fmaf(r[px + dw], w5[(dh + 2) * 5 + dw], a5[px]);
        if (dh >= -1 && dh <= 1) {
            #pragma unroll
            for (int px = 0; px < 4; px++)
                #pragma unroll
                for (int dw = 0; dw < 3; dw++)
                    a3[px] = fmaf(r[px + dw + 1], w3[(dh + 1) * 3 + dw], a3[px]);
        }
    }
    size_t op = (size_t)bct * 1024 + h * 32 + w0;
    uint2 st3, st5;
    st3.x = pack2(a3[0], a3[1]); st3.y = pack2(a3[2], a3[3]);
    st5.x = pack2(a5[0], a5[1]); st5.y = pack2(a5[2], a5[3]);
    *reinterpret_cast<uint2*>(&g_s3h[op]) = st3;
    *reinterpret_cast<uint2*>(&g_s5h[op]) = st5;
}

// K3: temporal depthwise 3/5-tap + BN stats -> packed half2 x12
__global__ void __launch_bounds__(256) k_temporal(const float* __restrict__ w3g,
                                                  const float* __restrict__ b3g,
                                                  const float* __restrict__ w5g,
                                                  const float* __restrict__ b5g) {
    int bc  = blockIdx.x >> 3;
    int hw0 = (blockIdx.x & 7) << 7;
    int c = bc & 63;
    size_t base = (size_t)bc * 32768;
    __shared__ float s3t[32][128];
    __shared__ float s5t[32][128];
    int tid = threadIdx.x;
    for (int i = tid; i < 4096; i += 256) {
        int t = i >> 7, p = i & 127;
        s3t[t][p] = __half2float(g_s3h[base + (size_t)t * 1024 + hw0 + p]);
        s5t[t][p] = __half2float(g_s5h[base + (size_t)t * 1024 + hw0 + p]);
    }
    __syncthreads();
    float w3[3], w5[5];
    #pragma unroll
    for (int i = 0; i < 3; i++) w3[i] = w3g[c * 3 + i];
    #pragma unroll
    for (int i = 0; i < 5; i++) w5[i] = w5g[c * 5 + i];
    float b3 = b3g[c], b5 = b5g[c];
    float s1 = 0, q1 = 0, s2 = 0, q2 = 0;
    for (int i = tid; i < 4096; i += 256) {
        int t = i >> 7, p = i & 127;
        float a = b3;
        #pragma unroll
        for (int dt = -1; dt <= 1; dt++) {
            int tt = t + dt;
            if ((unsigned)tt < 32u) a = fmaf(s3t[tt][p], w3[dt + 1], a);
        }
        float e = b5;
        #pragma unroll
        for (int dt = -2; dt <= 2; dt++) {
            int tt = t + dt;
            if ((unsigned)tt < 32u) e = fmaf(s5t[tt][p], w5[dt + 2], e);
        }
        g_x12[base + (size_t)t * 1024 + hw0 + p] = __floats2half2_rn(a, e);
        s1 += a; q1 = fmaf(a, a, q1);
        s2 += e; q2 = fmaf(e, e, q2);
    }
    #pragma unroll
    for (int off = 16; off; off >>= 1) {
        s1 += __shfl_down_sync(0xffffffffu, s1, off);
        q1 += __shfl_down_sync(0xffffffffu, q1, off);
        s2 += __shfl_down_sync(0xffffffffu, s2, off);
        q2 += __shfl_down_sync(0xffffffffu, q2, off);
    }
    __shared__ float red[4][8];
    int wid = threadIdx.x >> 5, lane = threadIdx.x & 31;
    if (lane == 0) { red[0][wid] = s1; red[1][wid] = q1; red[2][wid] = s2; red[3][wid] = q2; }
    __syncthreads();
    if (threadIdx.x == 0) {
        float a = 0, b = 0, c2 = 0, d = 0;
        for (int i = 0; i < 8; i++) { a += red[0][i]; b += red[1][i]; c2 += red[2][i]; d += red[3][i]; }
        atomicAdd(&g_sum1[c], a);  atomicAdd(&g_sq1[c], b);
        atomicAdd(&g_sum2[c], c2); atomicAdd(&g_sq2[c], d);
    }
}

// K4: BN scale/shift
__global__ void k_bn(const float* __restrict__ g3, const float* __restrict__ b3,
                     const float* __restrict__ g5, const float* __restrict__ b5) {
    int c = threadIdx.x;
    const float inv = 1.0f / 65536.0f;
    float m1 = g_sum1[c] * inv;
    float v1 = g_sq1[c] * inv - m1 * m1;
    float a1 = g3[c] * rsqrtf(v1 + 1e-5f);
    g_a1[c] = a1; g_b1[c] = b3[c] - m1 * a1;
    float m2 = g_sum2[c] * inv;
    float v2 = g_sq2[c] * inv - m2 * m2;
    float a2 = g5[c] * rsqrtf(v2 + 1e-5f);
    g_a2[c] = a2; g_b2[c] = b5[c] - m2 * a2;
}

// K5: circulant T-conv (FFT branch) + BN-ReLU combine -> s
__global__ void __launch_bounds__(256) k_branch3() {
    int bc  = blockIdx.x >> 2;
    int hw0 = (blockIdx.x & 3) << 8;
    int c = bc & 63;
    size_t base = (size_t)bc * 32768;
    __shared__ float2 gg[64];
    __shared__ float2 qq[32];
    __shared__ __align__(16) float4 Vs[32][64];
    int tid = threadIdx.x;
    if (tid < 64) gg[tid] = make_float2(g_gre[tid & 31], g_gim[tid & 31]);
    if (tid < 32) qq[tid] = make_float2(g_qre[tid], g_qim[tid]);
    for (int i = tid; i < 2048; i += 256) {
        int t = i >> 6, q4 = i & 63;
        Vs[t][q4] = *reinterpret_cast<const float4*>(&g_h5[base + (size_t)t * 1024 + hw0 + q4 * 4]);
    }
    __syncthreads();
    int ty = tid >> 6;
    int tx = tid & 63;
    float re[8][4], im[8][4];
    #pragma unroll
    for (int i = 0; i < 8; i++)
        #pragma unroll
        for (int j = 0; j < 4; j++) { re[i][j] = 0.f; im[i][j] = 0.f; }
    for (int tau = 0; tau < 32; tau++) {
        float4 v = Vs[tau][tx];
        float vv[4] = {v.x, v.y, v.z, v.w};
        #pragma unroll
        for (int i = 0; i < 8; i++) {
            float2 g2 = gg[(ty * 8 + i - tau + 32) & 31];
            #pragma unroll
            for (int j = 0; j < 4; j++) {
                re[i][j] = fmaf(vv[j], g2.x, re[i][j]);
                im[i][j] = fmaf(vv[j], g2.y, im[i][j]);
            }
        }
    }
    float a1 = g_a1[c], b1 = g_b1[c], a2 = g_a2[c], b2v = g_b2[c];
    #pragma unroll
    for (int i = 0; i < 8; i++) {
        int t = ty * 8 + i;
        #pragma unroll
        for (int j = 0; j < 4; j++) {
            int hw = hw0 + tx * 4 + j;
            float rr = re[i][j], ii = im[i][j];
            if (hw == 0) { rr += qq[t].x; ii += qq[t].y; }
            float x3 = sqrtf(rr * rr + ii * ii);
            size_t idx = base + (size_t)t * 1024 + hw;
            float2 v12 = __half22float2(g_x12[idx]);
            float x1v = fmaxf(fmaf(v12.x, a1, b1), 0.f);
            float x2v = fmaxf(fmaf(v12.y, a2, b2v), 0.f);
            g_s[idx] = x1v + x2v + x3;
        }
    }
}

// K6: 64x64 channel mix + shortcut -> yT fp16 [row][c]
__global__ void __launch_bounds__(256) k_mix(const float* __restrict__ w2,
                                             const float* __restrict__ cb) {
    int bt  = blockIdx.x >> 3;
    int hw0 = (blockIdx.x & 7) << 7;
    int b = bt >> 5, t = bt & 31;
    __shared__ float W2t[64][64];
    __shared__ float st[64][128];
    int tid = threadIdx.x;
    for (int i = tid; i < 4096; i += 256) {
        int o = i & 63, cx = i >> 6;
        W2t[cx][o] = w2[o * 64 + cx];
    }
    for (int i = tid; i < 8192; i += 256) {
        int cx = i >> 7, p = i & 127;
        st[cx][p] = g_s[(size_t)((b * 64 + cx) * 32 + t) * 1024 + hw0 + p];
    }
    __syncthreads();
    int to  = tid & 15;
    int thw = tid >> 4;
    float acc[8][4];
    #pragma unroll
    for (int i = 0; i < 8; i++)
        #pragma unroll
        for (int j = 0; j < 4; j++) acc[i][j] = 0.f;
    for (int cx = 0; cx < 64; cx++) {
        float sv[8], wv[4];
        #pragma unroll
        for (int i = 0; i < 8; i++) sv[i] = st[cx][thw * 8 + i];
        #pragma unroll
        for (int j = 0; j < 4; j++) wv[j] = W2t[cx][to * 4 + j];
        #pragma unroll
        for (int i = 0; i < 8; i++)
            #pragma unroll
            for (int j = 0; j < 4; j++)
                acc[i][j] = fmaf(wv[j], sv[i], acc[i][j]);
    }
    float cbv[4];
    #pragma unroll
    for (int j = 0; j < 4; j++) cbv[j] = cb[to * 4 + j];
    #pragma unroll
    for (int i = 0; i < 8; i++) {
        int hw = hw0 + thw * 8 + i;
        float o0 = g_h5[(size_t)((b * 64 + to * 4 + 0) * 32 + t) * 1024 + hw] + acc[i][0] + cbv[0];
        float o1 = g_h5[(size_t)((b * 64 + to * 4 + 1) * 32 + t) * 1024 + hw] + acc[i][1] + cbv[1];
        float o2 = g_h5[(size_t)((b * 64 + to * 4 + 2) * 32 + t) * 1024 + hw] + acc[i][2] + cbv[2];
        float o3 = g_h5[(size_t)((b * 64 + to * 4 + 3) * 32 + t) * 1024 + hw] + acc[i][3] + cbv[3];
        uint2 st2;
        st2.x = pack2(o0, o1);
        st2.y = pack2(o2, o3);
        *reinterpret_cast<uint2*>(&g_yTh[((size_t)bt * 1024 + hw) * 64 + to * 4]) = st2;
    }
}

// K7: up GEMM (fp16 mma + ldmatrix, K=64 single chunk) + bias + GELU + residual
__global__ void __launch_bounds__(256) k_up(const float* __restrict__ x,
                                            const float* __restrict__ bias,
                                            float* __restrict__ out) {
    __shared__ __align__(16) __half As[128][72];
    __shared__ __align__(16) __half Bs[128][72];
    int tid = threadIdx.x;
    int r0 = blockIdx.x * 128;
    int n0 = blockIdx.y * 128;
    int wid = tid >> 5, lane = tid & 31;
    int g = lane >> 2, tig = lane & 3;
    int warp_m = (wid & 1) * 64;
    int warp_n = (wid >> 1) * 32;

    float acc[4][4][4];
    #pragma unroll
    for (int i = 0; i < 4; i++)
        #pragma unroll
        for (int j = 0; j < 4; j++)
            #pragma unroll
            for (int l = 0; l < 4; l++) acc[i][j][l] = 0.f;

    #pragma unroll
    for (int i = 0; i < 4; i++) {
        int idx = tid + i * 256;
        int m = idx >> 3, sg = idx & 7;
        *reinterpret_cast<uint4*>(&As[m][sg * 8]) =
            *reinterpret_cast<const uint4*>(&g_yTh[(size_t)(r0 + m) * 64 + sg * 8]);
    }
    #pragma unroll
    for (int i = 0; i < 4; i++) {
        int idx = tid + i * 256;
        int n = idx >> 3, sg = idx & 7;
        *reinterpret_cast<uint4*>(&Bs[n][sg * 8]) =
            *reinterpret_cast<const uint4*>(&g_Wph[(size_t)(n0 + n) * 64 + sg * 8]);
    }
    __syncthreads();
    #pragma unroll
    for (int ks = 0; ks < 4; ks++) {
        int kk = ks * 16;
        uint32_t a[4][4];
        #pragma unroll
        for (int mf = 0; mf < 4; mf++)
            ldsm4(a[mf], saddr(&As[warp_m + mf * 16 + (lane & 15)][kk + (lane >> 4) * 8]));
        uint32_t bfr[2][4];
        #pragma unroll
        for (int h = 0; h < 2; h++)
            ldsm4(bfr[h], saddr(&Bs[warp_n + h * 16 + ((lane >> 4) & 1) * 8 + (lane & 7)]
                                   [kk + ((lane >> 3) & 1) * 8]));
        #pragma unroll
        for (int mf = 0; mf < 4; mf++)
            #pragma unroll
            for (int nf = 0; nf < 4; nf++)
                mma16816(acc[mf][nf], a[mf],
                         bfr[nf >> 1][(nf & 1) * 2], bfr[nf >> 1][(nf & 1) * 2 + 1]);
    }
    #pragma unroll
    for (int nf = 0; nf < 4; nf++) {
        int col = n0 + warp_n + nf * 8 + 2 * tig;
        float bs0 = bias[col], bs1 = bias[col + 1];
        #pragma unroll
        for (int mf = 0; mf < 4; mf++) {
            #pragma unroll
            for (int half = 0; half < 2; half++) {
                int row = r0 + warp_m + mf * 16 + g + half * 8;
                float c0 = acc[mf][nf][half * 2 + 0];
                float c1 = acc[mf][nf][half * 2 + 1];
                const float2 xin = *reinterpret_cast<const float2*>(&x[(size_t)row * 384 + col]);
                float2 o;
                o.x = xin.x + gelu_f(c0 + bs0);
                o.y = xin.y + gelu_f(c1 + bs1);
                *reinterpret_cast<float2*>(&out[(size_t)row * 384 + col]) = o;
            }
        }
    }
}

extern "C" void kernel_launch(void* const* d_in, const int* in_sizes, int n_in,
                              void* d_out, int out_size) {
    const float* x      = (const float*)d_in[0];
    const float* down_w = (const float*)d_in[1];
    const float* down_b = (const float*)d_in[2];
    const float* k31w   = (const float*)d_in[3];
    const float* k31b   = (const float*)d_in[4];
    const float* k32w   = (const float*)d_in[5];
    const float* k32b   = (const float*)d_in[6];
    const float* bn3g   = (const float*)d_in[7];
    const float* bn3b   = (const float*)d_in[8];
    const float* k51w   = (const float*)d_in[9];
    const float* k51b   = (const float*)d_in[10];
    const float* k52w   = (const float*)d_in[11];
    const float* k52b   = (const float*)d_in[12];
    const float* bn5g   = (const float*)d_in[13];
    const float* bn5b   = (const float*)d_in[14];
    const float* convw  = (const float*)d_in[15];
    const float* convb  = (const float*)d_in[16];
    const float* fw     = (const float*)d_in[17];
    const float* fb     = (const float*)d_in[18];
    const float* upw    = (const float*)d_in[19];
    const float* upb    = (const float*)d_in[20];
    float* out = (float*)d_out;

    k_prep    <<<1, 64>>>(fw, fb);
    k_cvt     <<<384, 64>>>(upw);
    k_down    <<<512, 256>>>(x, down_w, down_b);
    k_spatial <<<4096, 256>>>(k31w, k31b, k51w, k51b);
    k_temporal<<<1024, 256>>>(k32w, k32b, k52w, k52b);
    k_bn      <<<1, 64>>>(bn3g, bn3b, bn5g, bn5b);
    k_branch3 <<<512, 256>>>();
    k_mix     <<<512, 256>>>(convw, convb);
    {
        dim3 grid(ROWS / 128, 384 / 128);
        k_up <<<grid, 256>>>(x, upb, out);
    }
}

// round 12
// speedup vs baseline: 1.8256x; 1.1285x over previous
#include <cuda_runtime.h>
#include <cuda_fp16.h>
#include <math.h>
#include <stdint.h>

#define LTOT (2*64*32*1024)
#define ROWS 65536

__device__ float g_h5[LTOT];
__device__ __align__(16) __half g_s3h[LTOT];
__device__ __align__(16) __half g_s5h[LTOT];
__device__ __align__(16) __half2 g_x12[LTOT];
__device__ __align__(16) __half g_sh[LTOT];
__device__ __align__(16) __half g_yTh[(size_t)ROWS * 64];
__device__ __align__(16) __half g_Wph[384 * 64];
__device__ __align__(16) __half g_W2h[64 * 64];

__device__ float g_gre[32], g_gim[32], g_qre[32], g_qim[32];
__device__ float g_sum1[64], g_sq1[64], g_sum2[64], g_sq2[64];
__device__ float g_a1[64], g_b1[64], g_a2[64], g_b2[64];

__device__ __forceinline__ float gelu_f(float v) {
    return 0.5f * v * (1.0f + erff(v * 0.70710678118654752f));
}

__device__ __forceinline__ uint32_t pack2(float a, float b) {
    __half2 h = __floats2half2_rn(a, b);
    return *reinterpret_cast<uint32_t*>(&h);
}

__device__ __forceinline__ uint32_t saddr(const void* p) {
    return static_cast<uint32_t>(__cvta_generic_to_shared(p));
}

__device__ __forceinline__ void ldsm4(uint32_t r[4], uint32_t a) {
    asm volatile("ldmatrix.sync.aligned.m8n8.x4.shared.b16 {%0,%1,%2,%3}, [%4];"
                 : "=r"(r[0]), "=r"(r[1]), "=r"(r[2]), "=r"(r[3]) : "r"(a));
}

__device__ __forceinline__ void ldsm4t(uint32_t r[4], uint32_t a) {
    asm volatile("ldmatrix.sync.aligned.m8n8.x4.trans.shared.b16 {%0,%1,%2,%3}, [%4];"
                 : "=r"(r[0]), "=r"(r[1]), "=r"(r[2]), "=r"(r[3]) : "r"(a));
}

__device__ __forceinline__ void mma16816(float c[4], const uint32_t a[4],
                                         uint32_t b0, uint32_t b1) {
    asm volatile(
        "mma.sync.aligned.m16n8k16.row.col.f32.f16.f16.f32 "
        "{%0,%1,%2,%3}, {%4,%5,%6,%7}, {%8,%9}, {%0,%1,%2,%3};"
        : "+f"(c[0]), "+f"(c[1]), "+f"(c[2]), "+f"(c[3])
        : "r"(a[0]), "r"(a[1]), "r"(a[2]), "r"(a[3]), "r"(b0), "r"(b1));
}

// K0: g = ifft_T(fw), q = ifft_T(fb); zero BN stats
__global__ void k_prep(const float* __restrict__ fw, const float* __restrict__ fb) {
    int n = threadIdx.x;
    if (n < 32) {
        double gr = 0, gi = 0, qr = 0, qi = 0;
        for (int k = 0; k < 32; k++) {
            double ang = 6.283185307179586476925 * (double)((k * n) & 31) / 32.0;
            double cs = cos(ang), sn = sin(ang);
            gr += (double)fw[k] * cs; gi += (double)fw[k] * sn;
            qr += (double)fb[k] * cs; qi += (double)fb[k] * sn;
        }
        g_gre[n] = (float)(gr / 32.0); g_gim[n] = (float)(gi / 32.0);
        g_qre[n] = (float)(qr / 32.0); g_qim[n] = (float)(qi / 32.0);
    }
    if (n < 64) { g_sum1[n] = 0.f; g_sq1[n] = 0.f; g_sum2[n] = 0.f; g_sq2[n] = 0.f; }
}

// K0b: up_w and conv_w -> fp16
__global__ void k_cvt(const float* __restrict__ up, const float* __restrict__ w2) {
    int of = blockIdx.x, j = threadIdx.x;
    g_Wph[of * 64 + j] = __float2half_rn(up[of * 64 + j]);
    if (of < 64) g_W2h[of * 64 + j] = __float2half_rn(w2[of * 64 + j]);
}

// K1: down GEMM (fp16 mma + ldmatrix) + bias + GELU -> h5 NCDHW
__global__ void __launch_bounds__(256) k_down(const float* __restrict__ x,
                                              const float* __restrict__ w,
                                              const float* __restrict__ bias) {
    __shared__ __align__(16) __half As[128][72];
    __shared__ __align__(16) __half Bs[64][72];
    int tid = threadIdx.x;
    int r0 = blockIdx.x * 128;
    int wid = tid >> 5, lane = tid & 31;
    int g = lane >> 2, tig = lane & 3;
    int warp_m = (wid & 3) * 32;
    int warp_n = (wid >> 2) * 32;

    float acc[2][4][4];
    #pragma unroll
    for (int i = 0; i < 2; i++)
        #pragma unroll
        for (int j = 0; j < 4; j++)
            #pragma unroll
            for (int l = 0; l < 4; l++) acc[i][j][l] = 0.f;

    for (int k0 = 0; k0 < 384; k0 += 64) {
        #pragma unroll
        for (int i = 0; i < 4; i++) {
            int idx = tid + i * 256;
            int m = idx >> 3, sg = idx & 7;
            const float4* p = reinterpret_cast<const float4*>(&x[(size_t)(r0 + m) * 384 + k0 + sg * 8]);
            float4 v0 = p[0], v1 = p[1];
            uint4 st;
            st.x = pack2(v0.x, v0.y); st.y = pack2(v0.z, v0.w);
            st.z = pack2(v1.x, v1.y); st.w = pack2(v1.z, v1.w);
            *reinterpret_cast<uint4*>(&As[m][sg * 8]) = st;
        }
        #pragma unroll
        for (int i = 0; i < 2; i++) {
            int idx = tid + i * 256;
            int n = idx >> 3, sg = idx & 7;
            const float4* p = reinterpret_cast<const float4*>(&w[n * 384 + k0 + sg * 8]);
            float4 v0 = p[0], v1 = p[1];
            uint4 st;
            st.x = pack2(v0.x, v0.y); st.y = pack2(v0.z, v0.w);
            st.z = pack2(v1.x, v1.y); st.w = pack2(v1.z, v1.w);
            *reinterpret_cast<uint4*>(&Bs[n][sg * 8]) = st;
        }
        __syncthreads();
        #pragma unroll
        for (int ks = 0; ks < 4; ks++) {
            int kk = ks * 16;
            uint32_t a[2][4];
            #pragma unroll
            for (int mf = 0; mf < 2; mf++)
                ldsm4(a[mf], saddr(&As[warp_m + mf * 16 + (lane & 15)][kk + (lane >> 4) * 8]));
            uint32_t b[2][4];
            #pragma unroll
            for (int h = 0; h < 2; h++)
                ldsm4(b[h], saddr(&Bs[warp_n + h * 16 + ((lane >> 4) & 1) * 8 + (lane & 7)]
                                     [kk + ((lane >> 3) & 1) * 8]));
            #pragma unroll
            for (int mf = 0; mf < 2; mf++)
                #pragma unroll
                for (int nf = 0; nf < 4; nf++)
                    mma16816(acc[mf][nf], a[mf], b[nf >> 1][(nf & 1) * 2], b[nf >> 1][(nf & 1) * 2 + 1]);
        }
        __syncthreads();
    }
    int bt = r0 >> 10, hwbase = r0 & 1023;
    int b5i = bt >> 5, t = bt & 31;
    size_t planebase = (size_t)(b5i * 64) * 32768 + (size_t)t * 1024;
    #pragma unroll
    for (int nf = 0; nf < 4; nf++) {
        int c0 = warp_n + nf * 8 + 2 * tig;
        float bs0 = bias[c0], bs1 = bias[c0 + 1];
        #pragma unroll
        for (int mf = 0; mf < 2; mf++) {
            int m = warp_m + mf * 16 + g;
            size_t p0 = planebase + (size_t)c0 * 32768;
            g_h5[p0 + hwbase + m]             = gelu_f(acc[mf][nf][0] + bs0);
            g_h5[p0 + 32768 + hwbase + m]     = gelu_f(acc[mf][nf][1] + bs1);
            g_h5[p0 + hwbase + m + 8]         = gelu_f(acc[mf][nf][2] + bs0);
            g_h5[p0 + 32768 + hwbase + m + 8] = gelu_f(acc[mf][nf][3] + bs1);
        }
    }
}

// K2: spatial depthwise 3x3+5x5, register-cached, 4 px/thread -> fp16 s3/s5
__global__ void __launch_bounds__(256) k_spatial(const float* __restrict__ w3g,
                                                 const float* __restrict__ b3g,
                                                 const float* __restrict__ w5g,
                                                 const float* __restrict__ b5g) {
    int bct = blockIdx.x;
    int c = (bct >> 5) & 63;
    __shared__ float tile[32 * 33];
    __shared__ float w3[9], w5[25];
    int tid = threadIdx.x;
    if (tid < 9)  w3[tid] = w3g[c * 9 + tid];
    if (tid >= 32 && tid < 57) w5[tid - 32] = w5g[c * 25 + (tid - 32)];
    const float* src = g_h5 + (size_t)bct * 1024;
    for (int i = tid; i < 1024; i += 256) tile[(i >> 5) * 33 + (i & 31)] = src[i];
    __syncthreads();
    float b3 = b3g[c], b5 = b5g[c];
    int h = tid >> 3;
    int w0 = (tid & 7) * 4;
    float a3[4] = {b3, b3, b3, b3};
    float a5[4] = {b5, b5, b5, b5};
    #pragma unroll
    for (int dh = -2; dh <= 2; dh++) {
        int hh = h + dh;
        if ((unsigned)hh >= 32u) continue;
        float r[8];
        #pragma unroll
        for (int j = 0; j < 8; j++) {
            int ww = w0 - 2 + j;
            r[j] = ((unsigned)ww < 32u) ? tile[hh * 33 + ww] : 0.f;
        }
        #pragma unroll
        for (int px = 0; px < 4; px++)
            #pragma unroll
            for (int dw = 0; dw < 5; dw++)
                a5[px] = fmaf(r[px + dw], w5[(dh + 2) * 5 + dw], a5[px]);
        if (dh >= -1 && dh <= 1) {
            #pragma unroll
            for (int px = 0; px < 4; px++)
                #pragma unroll
                for (int dw = 0; dw < 3; dw++)
                    a3[px] = fmaf(r[px + dw + 1], w3[(dh + 1) * 3 + dw], a3[px]);
        }
    }
    size_t op = (size_t)bct * 1024 + h * 32 + w0;
    uint2 st3, st5;
    st3.x = pack2(a3[0], a3[1]); st3.y = pack2(a3[2], a3[3]);
    st5.x = pack2(a5[0], a5[1]); st5.y = pack2(a5[2], a5[3]);
    *reinterpret_cast<uint2*>(&g_s3h[op]) = st3;
    *reinterpret_cast<uint2*>(&g_s5h[op]) = st5;
}

// K3: temporal depthwise 3/5-tap + BN stats -> packed half2 x12
__global__ void __launch_bounds__(256) k_temporal(const float* __restrict__ w3g,
                                                  const float* __restrict__ b3g,
                                                  const float* __restrict__ w5g,
                                                  const float* __restrict__ b5g) {
    int bc  = blockIdx.x >> 3;
    int hw0 = (blockIdx.x & 7) << 7;
    int c = bc & 63;
    size_t base = (size_t)bc * 32768;
    __shared__ float s3t[32][128];
    __shared__ float s5t[32][128];
    int tid = threadIdx.x;
    for (int i = tid; i < 4096; i += 256) {
        int t = i >> 7, p = i & 127;
        s3t[t][p] = __half2float(g_s3h[base + (size_t)t * 1024 + hw0 + p]);
        s5t[t][p] = __half2float(g_s5h[base + (size_t)t * 1024 + hw0 + p]);
    }
    __syncthreads();
    float w3[3], w5[5];
    #pragma unroll
    for (int i = 0; i < 3; i++) w3[i] = w3g[c * 3 + i];
    #pragma unroll
    for (int i = 0; i < 5; i++) w5[i] = w5g[c * 5 + i];
    float b3 = b3g[c], b5 = b5g[c];
    float s1 = 0, q1 = 0, s2 = 0, q2 = 0;
    for (int i = tid; i < 4096; i += 256) {
        int t = i >> 7, p = i & 127;
        float a = b3;
        #pragma unroll
        for (int dt = -1; dt <= 1; dt++) {
            int tt = t + dt;
            if ((unsigned)tt < 32u) a = fmaf(s3t[tt][p], w3[dt + 1], a);
        }
        float e = b5;
        #pragma unroll
        for (int dt = -2; dt <= 2; dt++) {
            int tt = t + dt;
            if ((unsigned)tt < 32u) e = fmaf(s5t[tt][p], w5[dt + 2], e);
        }
        g_x12[base + (size_t)t * 1024 + hw0 + p] = __floats2half2_rn(a, e);
        s1 += a; q1 = fmaf(a, a, q1);
        s2 += e; q2 = fmaf(e, e, q2);
    }
    #pragma unroll
    for (int off = 16; off; off >>= 1) {
        s1 += __shfl_down_sync(0xffffffffu, s1, off);
        q1 += __shfl_down_sync(0xffffffffu, q1, off);
        s2 += __shfl_down_sync(0xffffffffu, s2, off);
        q2 += __shfl_down_sync(0xffffffffu, q2, off);
    }
    __shared__ float red[4][8];
    int wid = threadIdx.x >> 5, lane = threadIdx.x & 31;
    if (lane == 0) { red[0][wid] = s1; red[1][wid] = q1; red[2][wid] = s2; red[3][wid] = q2; }
    __syncthreads();
    if (threadIdx.x == 0) {
        float a = 0, b = 0, c2 = 0, d = 0;
        for (int i = 0; i < 8; i++) { a += red[0][i]; b += red[1][i]; c2 += red[2][i]; d += red[3][i]; }
        atomicAdd(&g_sum1[c], a);  atomicAdd(&g_sq1[c], b);
        atomicAdd(&g_sum2[c], c2); atomicAdd(&g_sq2[c], d);
    }
}

// K4: BN scale/shift
__global__ void k_bn(const float* __restrict__ g3, const float* __restrict__ b3,
                     const float* __restrict__ g5, const float* __restrict__ b5) {
    int c = threadIdx.x;
    const float inv = 1.0f / 65536.0f;
    float m1 = g_sum1[c] * inv;
    float v1 = g_sq1[c] * inv - m1 * m1;
    float a1 = g3[c] * rsqrtf(v1 + 1e-5f);
    g_a1[c] = a1; g_b1[c] = b3[c] - m1 * a1;
    float m2 = g_sum2[c] * inv;
    float v2 = g_sq2[c] * inv - m2 * m2;
    float a2 = g5[c] * rsqrtf(v2 + 1e-5f);
    g_a2[c] = a2; g_b2[c] = b5[c] - m2 * a2;
}

// K5: circulant T-conv via fp16 MMA + BN-ReLU combine -> s (fp16)
__global__ void __launch_bounds__(256) k_branch3() {
    __shared__ __align__(16) __half Gre[32][40];
    __shared__ __align__(16) __half Gim[32][40];
    __shared__ __align__(16) __half Vs[32][264];
    __shared__ float2 qq[32];
    int bc  = blockIdx.x >> 2;
    int hw0 = (blockIdx.x & 3) << 8;
    int c = bc & 63;
    size_t base = (size_t)bc * 32768;
    int tid = threadIdx.x;
    int wid = tid >> 5, lane = tid & 31;
    int g = lane >> 2, tig = lane & 3;
    int hwb = wid * 32;

    if (tid < 32) qq[tid] = make_float2(g_qre[tid], g_qim[tid]);
    for (int i = tid; i < 1024; i += 256) {
        int t = i >> 5, tau = i & 31;
        int d = (t - tau + 32) & 31;
        Gre[t][tau] = __float2half_rn(g_gre[d]);
        Gim[t][tau] = __float2half_rn(g_gim[d]);
    }
    for (int i = tid; i < 2048; i += 256) {
        int t = i >> 6, q4 = (i & 63) * 4;
        float4 v = *reinterpret_cast<const float4*>(&g_h5[base + (size_t)t * 1024 + hw0 + q4]);
        uint2 st;
        st.x = pack2(v.x, v.y); st.y = pack2(v.z, v.w);
        *reinterpret_cast<uint2*>(&Vs[t][q4]) = st;
    }
    __syncthreads();

    float ar[2][4][4], ai[2][4][4];
    #pragma unroll
    for (int i = 0; i < 2; i++)
        #pragma unroll
        for (int j = 0; j < 4; j++)
            #pragma unroll
            for (int l = 0; l < 4; l++) { ar[i][j][l] = 0.f; ai[i][j][l] = 0.f; }

    #pragma unroll
    for (int ks = 0; ks < 2; ks++) {
        int kk = ks * 16;
        uint32_t are[2][4], aim[2][4];
        #pragma unroll
        for (int mf = 0; mf < 2; mf++) {
            ldsm4(are[mf], saddr(&Gre[mf * 16 + (lane & 15)][kk + (lane >> 4) * 8]));
            ldsm4(aim[mf], saddr(&Gim[mf * 16 + (lane & 15)][kk + (lane >> 4) * 8]));
        }
        uint32_t b[2][4];
        #pragma unroll
        for (int h = 0; h < 2; h++)
            ldsm4t(b[h], saddr(&Vs[kk + (lane & 7) + ((lane >> 3) & 1) * 8]
                                  [hwb + h * 16 + ((lane >> 4) & 1) * 8]));
        #pragma unroll
        for (int mf = 0; mf < 2; mf++)
            #pragma unroll
            for (int nf = 0; nf < 4; nf++) {
                uint32_t b0 = b[nf >> 1][(nf & 1) * 2], b1 = b[nf >> 1][(nf & 1) * 2 + 1];
                mma16816(ar[mf][nf], are[mf], b0, b1);
                mma16816(ai[mf][nf], aim[mf], b0, b1);
            }
    }

    float a1 = g_a1[c], b1 = g_b1[c], a2 = g_a2[c], b2v = g_b2[c];
    #pragma unroll
    for (int mf = 0; mf < 2; mf++)
        #pragma unroll
        for (int nf = 0; nf < 4; nf++)
            #pragma unroll
            for (int l = 0; l < 4; l++) {
                int t = mf * 16 + g + (l >> 1) * 8;
                int hw = hw0 + hwb + nf * 8 + 2 * tig + (l & 1);
                float rr = ar[mf][nf][l], ii = ai[mf][nf][l];
                if (hw == 0) { rr += qq[t].x; ii += qq[t].y; }
                float x3 = sqrtf(rr * rr + ii * ii);
                size_t idx = base + (size_t)t * 1024 + hw;
                float2 v12 = __half22float2(g_x12[idx]);
                float x1v = fmaxf(fmaf(v12.x, a1, b1), 0.f);
                float x2v = fmaxf(fmaf(v12.y, a2, b2v), 0.f);
                g_sh[idx] = __float2half_rn(x1v + x2v + x3);
            }
}

// K6: channel mix via fp16 MMA + shortcut -> yT fp16 [row][o]
__global__ void __launch_bounds__(256) k_mix(const float* __restrict__ cb) {
    __shared__ __align__(16) __half W2s[64][72];
    __shared__ __align__(16) __half Ss[64][136];
    int bt  = blockIdx.x >> 3;
    int hw0 = (blockIdx.x & 7) << 7;
    int b = bt >> 5, t = bt & 31;
    int tid = threadIdx.x;
    int wid = tid >> 5, lane = tid & 31;
    int g = lane >> 2, tig = lane & 3;
    int warp_m = (wid & 1) * 32;
    int warp_n = (wid >> 1) * 32;

    // W2: 64 rows x 64 halves = 512 uint4 loads (8 halves each)
    for (int i = tid; i < 512; i += 256) {
        int o = i >> 3, sg = i & 7;
        *reinterpret_cast<uint4*>(&W2s[o][sg * 8]) =
            *reinterpret_cast<const uint4*>(&g_W2h[o * 64 + sg * 8]);
    }
    for (int i = tid; i < 1024; i += 256) {
        int cx = i >> 4, p8 = (i & 15) * 8;
        *reinterpret_cast<uint4*>(&Ss[cx][p8]) =
            *reinterpret_cast<const uint4*>(&g_sh[(size_t)((b * 64 + cx) * 32 + t) * 1024 + hw0 + p8]);
    }
    __syncthreads();

    float acc[2][4][4];
    #pragma unroll
    for (int i = 0; i < 2; i++)
        #pragma unroll
        for (int j = 0; j < 4; j++)
            #pragma unroll
            for (int l = 0; l < 4; l++) acc[i][j][l] = 0.f;

    #pragma unroll
    for (int ks = 0; ks < 4; ks++) {
        int kk = ks * 16;
        uint32_t a[2][4];
        #pragma unroll
        for (int mf = 0; mf < 2; mf++)
            ldsm4(a[mf], saddr(&W2s[warp_m + mf * 16 + (lane & 15)][kk + (lane >> 4) * 8]));
        uint32_t bfr[2][4];
        #pragma unroll
        for (int h = 0; h < 2; h++)
            ldsm4t(bfr[h], saddr(&Ss[kk + (lane & 7) + ((lane >> 3) & 1) * 8]
                                    [warp_n + h * 16 + ((lane >> 4) & 1) * 8]));
        #pragma unroll
        for (int mf = 0; mf < 2; mf++)
            #pragma unroll
            for (int nf = 0; nf < 4; nf++)
                mma16816(acc[mf][nf], a[mf],
                         bfr[nf >> 1][(nf & 1) * 2], bfr[nf >> 1][(nf & 1) * 2 + 1]);
    }

    #pragma unroll
    for (int mf = 0; mf < 2; mf++)
        #pragma unroll
        for (int nf = 0; nf < 4; nf++)
            #pragma unroll
            for (int l = 0; l < 4; l++) {
                int o = warp_m + mf * 16 + g + (l >> 1) * 8;
                int hw = hw0 + warp_n + nf * 8 + 2 * tig + (l & 1);
                float v = g_h5[(size_t)((b * 64 + o) * 32 + t) * 1024 + hw] + acc[mf][nf][l] + cb[o];
                g_yTh[((size_t)bt * 1024 + hw) * 64 + o] = __float2half_rn(v);
            }
}

// K7: up GEMM (fp16 mma + ldmatrix, K=64 single chunk) + bias + GELU + residual
__global__ void __launch_bounds__(256) k_up(const float* __restrict__ x,
                                            const float* __restrict__ bias,
                                            float* __restrict__ out) {
    __shared__ __align__(16) __half As[128][72];
    __shared__ __align__(16) __half Bs[128][72];
    int tid = threadIdx.x;
    int r0 = blockIdx.x * 128;
    int n0 = blockIdx.y * 128;
    int wid = tid >> 5, lane = tid & 31;
    int g = lane >> 2, tig = lane & 3;
    int warp_m = (wid & 1) * 64;
    int warp_n = (wid >> 1) * 32;

    float acc[4][4][4];
    #pragma unroll
    for (int i = 0; i < 4; i++)
        #pragma unroll
        for (int j = 0; j < 4; j++)
            #pragma unroll
            for (int l = 0; l < 4; l++) acc[i][j][l] = 0.f;

    #pragma unroll
    for (int i = 0; i < 4; i++) {
        int idx = tid + i * 256;
        int m = idx >> 3, sg = idx & 7;
        *reinterpret_cast<uint4*>(&As[m][sg * 8]) =
            *reinterpret_cast<const uint4*>(&g_yTh[(size_t)(r0 + m) * 64 + sg * 8]);
    }
    #pragma unroll
    for (int i = 0; i < 4; i++) {
        int idx = tid + i * 256;
        int n = idx >> 3, sg = idx & 7;
        *reinterpret_cast<uint4*>(&Bs[n][sg * 8]) =
            *reinterpret_cast<const uint4*>(&g_Wph[(size_t)(n0 + n) * 64 + sg * 8]);
    }
    __syncthreads();
    #pragma unroll
    for (int ks = 0; ks < 4; ks++) {
        int kk = ks * 16;
        uint32_t a[4][4];
        #pragma unroll
        for (int mf = 0; mf < 4; mf++)
            ldsm4(a[mf], saddr(&As[warp_m + mf * 16 + (lane & 15)][kk + (lane >> 4) * 8]));
        uint32_t bfr[2][4];
        #pragma unroll
        for (int h = 0; h < 2; h++)
            ldsm4(bfr[h], saddr(&Bs[warp_n + h * 16 + ((lane >> 4) & 1) * 8 + (lane & 7)]
                                   [kk + ((lane >> 3) & 1) * 8]));
        #pragma unroll
        for (int mf = 0; mf < 4; mf++)
            #pragma unroll
            for (int nf = 0; nf < 4; nf++)
                mma16816(acc[mf][nf], a[mf],
                         bfr[nf >> 1][(nf & 1) * 2], bfr[nf >> 1][(nf & 1) * 2 + 1]);
    }
    #pragma unroll
    for (int nf = 0; nf < 4; nf++) {
        int col = n0 + warp_n + nf * 8 + 2 * tig;
        float bs0 = bias[col], bs1 = bias[col + 1];
        #pragma unroll
        for (int mf = 0; mf < 4; mf++) {
            #pragma unroll
            for (int half = 0; half < 2; half++) {
                int row = r0 + warp_m + mf * 16 + g + half * 8;
                float c0 = acc[mf][nf][half * 2 + 0];
                float c1 = acc[mf][nf][half * 2 + 1];
                const float2 xin = *reinterpret_cast<const float2*>(&x[(size_t)row * 384 + col]);
                float2 o;
                o.x = xin.x + gelu_f(c0 + bs0);
                o.y = xin.y + gelu_f(c1 + bs1);
                *reinterpret_cast<float2*>(&out[(size_t)row * 384 + col]) = o;
            }
        }
    }
}

extern "C" void kernel_launch(void* const* d_in, const int* in_sizes, int n_in,
                              void* d_out, int out_size) {
    const float* x      = (const float*)d_in[0];
    const float* down_w = (const float*)d_in[1];
    const float* down_b = (const float*)d_in[2];
    const float* k31w   = (const float*)d_in[3];
    const float* k31b   = (const float*)d_in[4];
    const float* k32w   = (const float*)d_in[5];
    const float* k32b   = (const float*)d_in[6];
    const float* bn3g   = (const float*)d_in[7];
    const float* bn3b   = (const float*)d_in[8];
    const float* k51w   = (const float*)d_in[9];
    const float* k51b   = (const float*)d_in[10];
    const float* k52w   = (const float*)d_in[11];
    const float* k52b   = (const float*)d_in[12];
    const float* bn5g   = (const float*)d_in[13];
    const float* bn5b   = (const float*)d_in[14];
    const float* convw  = (const float*)d_in[15];
    const float* convb  = (const float*)d_in[16];
    const float* fw     = (const float*)d_in[17];
    const float* fb     = (const float*)d_in[18];
    const float* upw    = (const float*)d_in[19];
    const float* upb    = (const float*)d_in[20];
    float* out = (float*)d_out;

    k_prep    <<<1, 64>>>(fw, fb);
    k_cvt     <<<384, 64>>>(upw, convw);
    k_down    <<<512, 256>>>(x, down_w, down_b);
    k_spatial <<<4096, 256>>>(k31w, k31b, k51w, k51b);
    k_temporal<<<1024, 256>>>(k32w, k32b, k52w, k52b);
    k_bn      <<<1, 64>>>(bn3g, bn3b, bn5g, bn5b);
    k_branch3 <<<512, 256>>>();
    k_mix     <<<512, 256>>>(convb);
    {
        dim3 grid(ROWS / 128, 384 / 128);
        k_up <<<grid, 256>>>(x, upb, out);
    }
}

// round 13
// speedup vs baseline: 1.9446x; 1.0652x over previous
#include <cuda_runtime.h>
#include <cuda_fp16.h>
#include <math.h>
#include <stdint.h>

#define LTOT (2*64*32*1024)
#define ROWS 65536

__device__ __align__(16) __half g_h5h[LTOT];
__device__ __align__(16) __half2 g_x12[LTOT];
__device__ __align__(16) __half g_sh[LTOT];
__device__ __align__(16) __half g_yTh[(size_t)ROWS * 64];
__device__ __align__(16) __half g_Wph[384 * 64];
__device__ __align__(16) __half g_W2h[64 * 64];

__device__ float g_gre[32], g_gim[32], g_qre[32], g_qim[32];
__device__ float g_sum1[64], g_sq1[64], g_sum2[64], g_sq2[64];
__device__ float g_a1[64], g_b1[64], g_a2[64], g_b2[64];

__device__ __forceinline__ float gelu_f(float v) {
    return 0.5f * v * (1.0f + erff(v * 0.70710678118654752f));
}

__device__ __forceinline__ uint32_t pack2(float a, float b) {
    __half2 h = __floats2half2_rn(a, b);
    return *reinterpret_cast<uint32_t*>(&h);
}

__device__ __forceinline__ uint32_t saddr(const void* p) {
    return static_cast<uint32_t>(__cvta_generic_to_shared(p));
}

__device__ __forceinline__ void ldsm4(uint32_t r[4], uint32_t a) {
    asm volatile("ldmatrix.sync.aligned.m8n8.x4.shared.b16 {%0,%1,%2,%3}, [%4];"
                 : "=r"(r[0]), "=r"(r[1]), "=r"(r[2]), "=r"(r[3]) : "r"(a));
}

__device__ __forceinline__ void ldsm4t(uint32_t r[4], uint32_t a) {
    asm volatile("ldmatrix.sync.aligned.m8n8.x4.trans.shared.b16 {%0,%1,%2,%3}, [%4];"
                 : "=r"(r[0]), "=r"(r[1]), "=r"(r[2]), "=r"(r[3]) : "r"(a));
}

__device__ __forceinline__ void mma16816(float c[4], const uint32_t a[4],
                                         uint32_t b0, uint32_t b1) {
    asm volatile(
        "mma.sync.aligned.m16n8k16.row.col.f32.f16.f16.f32 "
        "{%0,%1,%2,%3}, {%4,%5,%6,%7}, {%8,%9}, {%0,%1,%2,%3};"
        : "+f"(c[0]), "+f"(c[1]), "+f"(c[2]), "+f"(c[3])
        : "r"(a[0]), "r"(a[1]), "r"(a[2]), "r"(a[3]), "r"(b0), "r"(b1));
}

// K0: g = ifft_T(fw), q = ifft_T(fb); zero BN stats
__global__ void k_prep(const float* __restrict__ fw, const float* __restrict__ fb) {
    int n = threadIdx.x;
    if (n < 32) {
        double gr = 0, gi = 0, qr = 0, qi = 0;
        for (int k = 0; k < 32; k++) {
            double ang = 6.283185307179586476925 * (double)((k * n) & 31) / 32.0;
            double cs = cos(ang), sn = sin(ang);
            gr += (double)fw[k] * cs; gi += (double)fw[k] * sn;
            qr += (double)fb[k] * cs; qi += (double)fb[k] * sn;
        }
        g_gre[n] = (float)(gr / 32.0); g_gim[n] = (float)(gi / 32.0);
        g_qre[n] = (float)(qr / 32.0); g_qim[n] = (float)(qi / 32.0);
    }
    if (n < 64) { g_sum1[n] = 0.f; g_sq1[n] = 0.f; g_sum2[n] = 0.f; g_sq2[n] = 0.f; }
}

// K0b: up_w and conv_w -> fp16
__global__ void k_cvt(const float* __restrict__ up, const float* __restrict__ w2) {
    int of = blockIdx.x, j = threadIdx.x;
    g_Wph[of * 64 + j] = __float2half_rn(up[of * 64 + j]);
    if (of < 64) g_W2h[of * 64 + j] = __float2half_rn(w2[of * 64 + j]);
}

// K1: down GEMM (fp16 mma + ldmatrix) + bias + GELU -> h5h NCDHW (fp16)
__global__ void __launch_bounds__(256) k_down(const float* __restrict__ x,
                                              const float* __restrict__ w,
                                              const float* __restrict__ bias) {
    __shared__ __align__(16) __half As[128][72];
    __shared__ __align__(16) __half Bs[64][72];
    int tid = threadIdx.x;
    int r0 = blockIdx.x * 128;
    int wid = tid >> 5, lane = tid & 31;
    int g = lane >> 2, tig = lane & 3;
    int warp_m = (wid & 3) * 32;
    int warp_n = (wid >> 2) * 32;

    float acc[2][4][4];
    #pragma unroll
    for (int i = 0; i < 2; i++)
        #pragma unroll
        for (int j = 0; j < 4; j++)
            #pragma unroll
            for (int l = 0; l < 4; l++) acc[i][j][l] = 0.f;

    for (int k0 = 0; k0 < 384; k0 += 64) {
        #pragma unroll
        for (int i = 0; i < 4; i++) {
            int idx = tid + i * 256;
            int m = idx >> 3, sg = idx & 7;
            const float4* p = reinterpret_cast<const float4*>(&x[(size_t)(r0 + m) * 384 + k0 + sg * 8]);
            float4 v0 = p[0], v1 = p[1];
            uint4 st;
            st.x = pack2(v0.x, v0.y); st.y = pack2(v0.z, v0.w);
            st.z = pack2(v1.x, v1.y); st.w = pack2(v1.z, v1.w);
            *reinterpret_cast<uint4*>(&As[m][sg * 8]) = st;
        }
        #pragma unroll
        for (int i = 0; i < 2; i++) {
            int idx = tid + i * 256;
            int n = idx >> 3, sg = idx & 7;
            const float4* p = reinterpret_cast<const float4*>(&w[n * 384 + k0 + sg * 8]);
            float4 v0 = p[0], v1 = p[1];
            uint4 st;
            st.x = pack2(v0.x, v0.y); st.y = pack2(v0.z, v0.w);
            st.z = pack2(v1.x, v1.y); st.w = pack2(v1.z, v1.w);
            *reinterpret_cast<uint4*>(&Bs[n][sg * 8]) = st;
        }
        __syncthreads();
        #pragma unroll
        for (int ks = 0; ks < 4; ks++) {
            int kk = ks * 16;
            uint32_t a[2][4];
            #pragma unroll
            for (int mf = 0; mf < 2; mf++)
                ldsm4(a[mf], saddr(&As[warp_m + mf * 16 + (lane & 15)][kk + (lane >> 4) * 8]));
            uint32_t b[2][4];
            #pragma unroll
            for (int h = 0; h < 2; h++)
                ldsm4(b[h], saddr(&Bs[warp_n + h * 16 + ((lane >> 4) & 1) * 8 + (lane & 7)]
                                     [kk + ((lane >> 3) & 1) * 8]));
            #pragma unroll
            for (int mf = 0; mf < 2; mf++)
                #pragma unroll
                for (int nf = 0; nf < 4; nf++)
                    mma16816(acc[mf][nf], a[mf], b[nf >> 1][(nf & 1) * 2], b[nf >> 1][(nf & 1) * 2 + 1]);
        }
        __syncthreads();
    }
    int bt = r0 >> 10, hwbase = r0 & 1023;
    int b5i = bt >> 5, t = bt & 31;
    size_t planebase = (size_t)(b5i * 64) * 32768 + (size_t)t * 1024;
    #pragma unroll
    for (int nf = 0; nf < 4; nf++) {
        int c0 = warp_n + nf * 8 + 2 * tig;
        float bs0 = bias[c0], bs1 = bias[c0 + 1];
        #pragma unroll
        for (int mf = 0; mf < 2; mf++) {
            int m = warp_m + mf * 16 + g;
            size_t p0 = planebase + (size_t)c0 * 32768;
            g_h5h[p0 + hwbase + m]             = __float2half_rn(gelu_f(acc[mf][nf][0] + bs0));
            g_h5h[p0 + 32768 + hwbase + m]     = __float2half_rn(gelu_f(acc[mf][nf][1] + bs1));
            g_h5h[p0 + hwbase + m + 8]         = __float2half_rn(gelu_f(acc[mf][nf][2] + bs0));
            g_h5h[p0 + 32768 + hwbase + m + 8] = __float2half_rn(gelu_f(acc[mf][nf][3] + bs1));
        }
    }
}

// K2: fused spatial(3x3,5x5) + temporal(3,5) depthwise + BN stats, all-smem
// block = (bc, 16-row h-band). smem: in[32][20][32] + s3[32][512] + s5[32][512] fp16
__global__ void __launch_bounds__(256) k_conv2(const float* __restrict__ w3g,
                                               const float* __restrict__ b3g,
                                               const float* __restrict__ w5g,
                                               const float* __restrict__ b5g,
                                               const float* __restrict__ wt3g,
                                               const float* __restrict__ bt3g,
                                               const float* __restrict__ wt5g,
                                               const float* __restrict__ bt5g) {
    extern __shared__ __half smh[];
    __half* in = smh;           // 20480 halves
    __half* s3 = smh + 20480;   // 16384
    __half* s5 = smh + 36864;   // 16384
    int bc = blockIdx.x >> 1;
    int band = blockIdx.x & 1;
    int h0 = band * 16;
    int c = bc & 63;
    size_t base = (size_t)bc * 32768;
    int tid = threadIdx.x;

    __shared__ float w3[9], w5[25], wt3[3], wt5[5];
    if (tid < 9)  w3[tid] = w3g[c * 9 + tid];
    if (tid >= 32 && tid < 57) w5[tid - 32] = w5g[c * 25 + (tid - 32)];
    if (tid >= 64 && tid < 67) wt3[tid - 64] = wt3g[c * 3 + (tid - 64)];
    if (tid >= 96 && tid < 101) wt5[tid - 96] = wt5g[c * 5 + (tid - 96)];

    // load input band with +-2 h halo (2560 uint4 of 8 halves)
    for (int i4 = tid; i4 < 2560; i4 += 256) {
        int t = i4 / 80, rem = i4 - t * 80;
        int r = rem >> 2, w8 = (rem & 3) * 8;
        int gh = h0 - 2 + r;
        uint4 v = make_uint4(0u, 0u, 0u, 0u);
        if ((unsigned)gh < 32u)
            v = *reinterpret_cast<const uint4*>(&g_h5h[base + (size_t)t * 1024 + gh * 32 + w8]);
        *reinterpret_cast<uint4*>(&in[t * 640 + r * 32 + w8]) = v;
    }
    __syncthreads();

    float b3 = b3g[c], b5 = b5g[c];
    // spatial: 4096 groups of 4 px (32 t x 16 h x 8 wgroups)
    for (int gid = tid; gid < 4096; gid += 256) {
        int t = gid >> 7;
        int rem = gid & 127;
        int h = rem >> 3;
        int w0 = (rem & 7) * 4;
        float a3[4] = {b3, b3, b3, b3};
        float a5[4] = {b5, b5, b5, b5};
        #pragma unroll
        for (int dh = 0; dh < 5; dh++) {
            const __half* rp = &in[t * 640 + (h + dh) * 32];
            float r[8];
            #pragma unroll
            for (int j = 0; j < 8; j++) {
                int ww = w0 - 2 + j;
                r[j] = ((unsigned)ww < 32u) ? __half2float(rp[ww]) : 0.f;
            }
            #pragma unroll
            for (int px = 0; px < 4; px++)
                #pragma unroll
                for (int dw = 0; dw < 5; dw++)
                    a5[px] = fmaf(r[px + dw], w5[dh * 5 + dw], a5[px]);
            if (dh >= 1 && dh <= 3) {
                #pragma unroll
                for (int px = 0; px < 4; px++)
                    #pragma unroll
                    for (int dw = 0; dw < 3; dw++)
                        a3[px] = fmaf(r[px + dw + 1], w3[(dh - 1) * 3 + dw], a3[px]);
            }
        }
        int p = h * 32 + w0;
        uint2 v3, v5;
        v3.x = pack2(a3[0], a3[1]); v3.y = pack2(a3[2], a3[3]);
        v5.x = pack2(a5[0], a5[1]); v5.y = pack2(a5[2], a5[3]);
        *reinterpret_cast<uint2*>(&s3[t * 512 + p]) = v3;
        *reinterpret_cast<uint2*>(&s5[t * 512 + p]) = v5;
    }
    __syncthreads();

    float bt3 = bt3g[c], bt5 = bt5g[c];
    float s1 = 0, q1 = 0, s2 = 0, q2 = 0;
    for (int i = tid; i < 16384; i += 256) {
        int t = i >> 9, p = i & 511;
        float a = bt3;
        #pragma unroll
        for (int dt = -1; dt <= 1; dt++) {
            int tt = t + dt;
            if ((unsigned)tt < 32u) a = fmaf(__half2float(s3[tt * 512 + p]), wt3[dt + 1], a);
        }
        float e = bt5;
        #pragma unroll
        for (int dt = -2; dt <= 2; dt++) {
            int tt = t + dt;
            if ((unsigned)tt < 32u) e = fmaf(__half2float(s5[tt * 512 + p]), wt5[dt + 2], e);
        }
        g_x12[base + (size_t)t * 1024 + h0 * 32 + p] = __floats2half2_rn(a, e);
        s1 += a; q1 = fmaf(a, a, q1);
        s2 += e; q2 = fmaf(e, e, q2);
    }
    #pragma unroll
    for (int off = 16; off; off >>= 1) {
        s1 += __shfl_down_sync(0xffffffffu, s1, off);
        q1 += __shfl_down_sync(0xffffffffu, q1, off);
        s2 += __shfl_down_sync(0xffffffffu, s2, off);
        q2 += __shfl_down_sync(0xffffffffu, q2, off);
    }
    __shared__ float red[4][8];
    int wid = tid >> 5, lane = tid & 31;
    if (lane == 0) { red[0][wid] = s1; red[1][wid] = q1; red[2][wid] = s2; red[3][wid] = q2; }
    __syncthreads();
    if (tid == 0) {
        float a = 0, b = 0, c2 = 0, d = 0;
        for (int i = 0; i < 8; i++) { a += red[0][i]; b += red[1][i]; c2 += red[2][i]; d += red[3][i]; }
        atomicAdd(&g_sum1[c], a);  atomicAdd(&g_sq1[c], b);
        atomicAdd(&g_sum2[c], c2); atomicAdd(&g_sq2[c], d);
    }
}

// K4: BN scale/shift
__global__ void k_bn(const float* __restrict__ g3, const float* __restrict__ b3,
                     const float* __restrict__ g5, const float* __restrict__ b5) {
    int c = threadIdx.x;
    const float inv = 1.0f / 65536.0f;
    float m1 = g_sum1[c] * inv;
    float v1 = g_sq1[c] * inv - m1 * m1;
    float a1 = g3[c] * rsqrtf(v1 + 1e-5f);
    g_a1[c] = a1; g_b1[c] = b3[c] - m1 * a1;
    float m2 = g_sum2[c] * inv;
    float v2 = g_sq2[c] * inv - m2 * m2;
    float a2 = g5[c] * rsqrtf(v2 + 1e-5f);
    g_a2[c] = a2; g_b2[c] = b5[c] - m2 * a2;
}

// K5: circulant T-conv via fp16 MMA + BN-ReLU combine -> s (fp16)
__global__ void __launch_bounds__(256) k_branch3() {
    __shared__ __align__(16) __half Gre[32][40];
    __shared__ __align__(16) __half Gim[32][40];
    __shared__ __align__(16) __half Vs[32][264];
    __shared__ float2 qq[32];
    int bc  = blockIdx.x >> 2;
    int hw0 = (blockIdx.x & 3) << 8;
    int c = bc & 63;
    size_t base = (size_t)bc * 32768;
    int tid = threadIdx.x;
    int wid = tid >> 5, lane = tid & 31;
    int g = lane >> 2, tig = lane & 3;
    int hwb = wid * 32;

    if (tid < 32) qq[tid] = make_float2(g_qre[tid], g_qim[tid]);
    for (int i = tid; i < 1024; i += 256) {
        int t = i >> 5, tau = i & 31;
        int d = (t - tau + 32) & 31;
        Gre[t][tau] = __float2half_rn(g_gre[d]);
        Gim[t][tau] = __float2half_rn(g_gim[d]);
    }
    // V copy: fp16 already, 1024 uint4 of 8 halves
    for (int i4 = tid; i4 < 1024; i4 += 256) {
        int t = i4 >> 5, q8 = (i4 & 31) * 8;
        *reinterpret_cast<uint4*>(&Vs[t][q8]) =
            *reinterpret_cast<const uint4*>(&g_h5h[base + (size_t)t * 1024 + hw0 + q8]);
    }
    __syncthreads();

    float ar[2][4][4], ai[2][4][4];
    #pragma unroll
    for (int i = 0; i < 2; i++)
        #pragma unroll
        for (int j = 0; j < 4; j++)
            #pragma unroll
            for (int l = 0; l < 4; l++) { ar[i][j][l] = 0.f; ai[i][j][l] = 0.f; }

    #pragma unroll
    for (int ks = 0; ks < 2; ks++) {
        int kk = ks * 16;
        uint32_t are[2][4], aim[2][4];
        #pragma unroll
        for (int mf = 0; mf < 2; mf++) {
            ldsm4(are[mf], saddr(&Gre[mf * 16 + (lane & 15)][kk + (lane >> 4) * 8]));
            ldsm4(aim[mf], saddr(&Gim[mf * 16 + (lane & 15)][kk + (lane >> 4) * 8]));
        }
        uint32_t b[2][4];
        #pragma unroll
        for (int h = 0; h < 2; h++)
            ldsm4t(b[h], saddr(&Vs[kk + (lane & 7) + ((lane >> 3) & 1) * 8]
                                  [hwb + h * 16 + ((lane >> 4) & 1) * 8]));
        #pragma unroll
        for (int mf = 0; mf < 2; mf++)
            #pragma unroll
            for (int nf = 0; nf < 4; nf++) {
                uint32_t b0 = b[nf >> 1][(nf & 1) * 2], b1 = b[nf >> 1][(nf & 1) * 2 + 1];
                mma16816(ar[mf][nf], are[mf], b0, b1);
                mma16816(ai[mf][nf], aim[mf], b0, b1);
            }
    }

    float a1 = g_a1[c], b1 = g_b1[c], a2 = g_a2[c], b2v = g_b2[c];
    #pragma unroll
    for (int mf = 0; mf < 2; mf++)
        #pragma unroll
        for (int nf = 0; nf < 4; nf++)
            #pragma unroll
            for (int l = 0; l < 4; l++) {
                int t = mf * 16 + g + (l >> 1) * 8;
                int hw = hw0 + hwb + nf * 8 + 2 * tig + (l & 1);
                float rr = ar[mf][nf][l], ii = ai[mf][nf][l];
                if (hw == 0) { rr += qq[t].x; ii += qq[t].y; }
                float x3 = sqrtf(rr * rr + ii * ii);
                size_t idx = base + (size_t)t * 1024 + hw;
                float2 v12 = __half22float2(g_x12[idx]);
                float x1v = fmaxf(fmaf(v12.x, a1, b1), 0.f);
                float x2v = fmaxf(fmaf(v12.y, a2, b2v), 0.f);
                g_sh[idx] = __float2half_rn(x1v + x2v + x3);
            }
}

// K6: channel mix via fp16 MMA + shortcut -> yT fp16 [row][o]
__global__ void __launch_bounds__(256) k_mix(const float* __restrict__ cb) {
    __shared__ __align__(16) __half W2s[64][72];
    __shared__ __align__(16) __half Ss[64][136];
    int bt  = blockIdx.x >> 3;
    int hw0 = (blockIdx.x & 7) << 7;
    int b = bt >> 5, t = bt & 31;
    int tid = threadIdx.x;
    int wid = tid >> 5, lane = tid & 31;
    int g = lane >> 2, tig = lane & 3;
    int warp_m = (wid & 1) * 32;
    int warp_n = (wid >> 1) * 32;

    for (int i = tid; i < 512; i += 256) {
        int o = i >> 3, sg = i & 7;
        *reinterpret_cast<uint4*>(&W2s[o][sg * 8]) =
            *reinterpret_cast<const uint4*>(&g_W2h[o * 64 + sg * 8]);
    }
    for (int i = tid; i < 1024; i += 256) {
        int cx = i >> 4, p8 = (i & 15) * 8;
        *reinterpret_cast<uint4*>(&Ss[cx][p8]) =
            *reinterpret_cast<const uint4*>(&g_sh[(size_t)((b * 64 + cx) * 32 + t) * 1024 + hw0 + p8]);
    }
    __syncthreads();

    float acc[2][4][4];
    #pragma unroll
    for (int i = 0; i < 2; i++)
        #pragma unroll
        for (int j = 0; j < 4; j++)
            #pragma unroll
            for (int l = 0; l < 4; l++) acc[i][j][l] = 0.f;

    #pragma unroll
    for (int ks = 0; ks < 4; ks++) {
        int kk = ks * 16;
        uint32_t a[2][4];
        #pragma unroll
        for (int mf = 0; mf < 2; mf++)
            ldsm4(a[mf], saddr(&W2s[warp_m + mf * 16 + (lane & 15)][kk + (lane >> 4) * 8]));
        uint32_t bfr[2][4];
        #pragma unroll
        for (int h = 0; h < 2; h++)
            ldsm4t(bfr[h], saddr(&Ss[kk + (lane & 7) + ((lane >> 3) & 1) * 8]
                                    [warp_n + h * 16 + ((lane >> 4) & 1) * 8]));
        #pragma unroll
        for (int mf = 0; mf < 2; mf++)
            #pragma unroll
            for (int nf = 0; nf < 4; nf++)
                mma16816(acc[mf][nf], a[mf],
                         bfr[nf >> 1][(nf & 1) * 2], bfr[nf >> 1][(nf & 1) * 2 + 1]);
    }

    #pragma unroll
    for (int mf = 0; mf < 2; mf++)
        #pragma unroll
        for (int nf = 0; nf < 4; nf++)
            #pragma unroll
            for (int l = 0; l < 4; l++) {
                int o = warp_m + mf * 16 + g + (l >> 1) * 8;
                int hw = hw0 + warp_n + nf * 8 + 2 * tig + (l & 1);
                float v = __half2float(g_h5h[(size_t)((b * 64 + o) * 32 + t) * 1024 + hw])
                          + acc[mf][nf][l] + cb[o];
                g_yTh[((size_t)bt * 1024 + hw) * 64 + o] = __float2half_rn(v);
            }
}

// K7: up GEMM (fp16 mma + ldmatrix, K=64 single chunk) + bias + GELU + residual
__global__ void __launch_bounds__(256) k_up(const float* __restrict__ x,
                                            const float* __restrict__ bias,
                                            float* __restrict__ out) {
    __shared__ __align__(16) __half As[128][72];
    __shared__ __align__(16) __half Bs[128][72];
    int tid = threadIdx.x;
    int r0 = blockIdx.x * 128;
    int n0 = blockIdx.y * 128;
    int wid = tid >> 5, lane = tid & 31;
    int g = lane >> 2, tig = lane & 3;
    int warp_m = (wid & 1) * 64;
    int warp_n = (wid >> 1) * 32;

    float acc[4][4][4];
    #pragma unroll
    for (int i = 0; i < 4; i++)
        #pragma unroll
        for (int j = 0; j < 4; j++)
            #pragma unroll
            for (int l = 0; l < 4; l++) acc[i][j][l] = 0.f;

    #pragma unroll
    for (int i = 0; i < 4; i++) {
        int idx = tid + i * 256;
        int m = idx >> 3, sg = idx & 7;
        *reinterpret_cast<uint4*>(&As[m][sg * 8]) =
            *reinterpret_cast<const uint4*>(&g_yTh[(size_t)(r0 + m) * 64 + sg * 8]);
    }
    #pragma unroll
    for (int i = 0; i < 4; i++) {
        int idx = tid + i * 256;
        int n = idx >> 3, sg = idx & 7;
        *reinterpret_cast<uint4*>(&Bs[n][sg * 8]) =
            *reinterpret_cast<const uint4*>(&g_Wph[(size_t)(n0 + n) * 64 + sg * 8]);
    }
    __syncthreads();
    #pragma unroll
    for (int ks = 0; ks < 4; ks++) {
        int kk = ks * 16;
        uint32_t a[4][4];
        #pragma unroll
        for (int mf = 0; mf < 4; mf++)
            ldsm4(a[mf], saddr(&As[warp_m + mf * 16 + (lane & 15)][kk + (lane >> 4) * 8]));
        uint32_t bfr[2][4];
        #pragma unroll
        for (int h = 0; h < 2; h++)
            ldsm4(bfr[h], saddr(&Bs[warp_n + h * 16 + ((lane >> 4) & 1) * 8 + (lane & 7)]
                                   [kk + ((lane >> 3) & 1) * 8]));
        #pragma unroll
        for (int mf = 0; mf < 4; mf++)
            #pragma unroll
            for (int nf = 0; nf < 4; nf++)
                mma16816(acc[mf][nf], a[mf],
                         bfr[nf >> 1][(nf & 1) * 2], bfr[nf >> 1][(nf & 1) * 2 + 1]);
    }
    #pragma unroll
    for (int nf = 0; nf < 4; nf++) {
        int col = n0 + warp_n + nf * 8 + 2 * tig;
        float bs0 = bias[col], bs1 = bias[col + 1];
        #pragma unroll
        for (int mf = 0; mf < 4; mf++) {
            #pragma unroll
            for (int half = 0; half < 2; half++) {
                int row = r0 + warp_m + mf * 16 + g + half * 8;
                float c0 = acc[mf][nf][half * 2 + 0];
                float c1 = acc[mf][nf][half * 2 + 1];
                const float2 xin = *reinterpret_cast<const float2*>(&x[(size_t)row * 384 + col]);
                float2 o;
                o.x = xin.x + gelu_f(c0 + bs0);
                o.y = xin.y + gelu_f(c1 + bs1);
                *reinterpret_cast<float2*>(&out[(size_t)row * 384 + col]) = o;
            }
        }
    }
}

extern "C" void kernel_launch(void* const* d_in, const int* in_sizes, int n_in,
                              void* d_out, int out_size) {
    const float* x      = (const float*)d_in[0];
    const float* down_w = (const float*)d_in[1];
    const float* down_b = (const float*)d_in[2];
    const float* k31w   = (const float*)d_in[3];
    const float* k31b   = (const float*)d_in[4];
    const float* k32w   = (const float*)d_in[5];
    const float* k32b   = (const float*)d_in[6];
    const float* bn3g   = (const float*)d_in[7];
    const float* bn3b   = (const float*)d_in[8];
    const float* k51w   = (const float*)d_in[9];
    const float* k51b   = (const float*)d_in[10];
    const float* k52w   = (const float*)d_in[11];
    const float* k52b   = (const float*)d_in[12];
    const float* bn5g   = (const float*)d_in[13];
    const float* bn5b   = (const float*)d_in[14];
    const float* convw  = (const float*)d_in[15];
    const float* convb  = (const float*)d_in[16];
    const float* fw     = (const float*)d_in[17];
    const float* fb     = (const float*)d_in[18];
    const float* upw    = (const float*)d_in[19];
    const float* upb    = (const float*)d_in[20];
    float* out = (float*)d_out;

    cudaFuncSetAttribute(k_conv2, cudaFuncAttributeMaxDynamicSharedMemorySize, 106496);

    k_prep    <<<1, 64>>>(fw, fb);
    k_cvt     <<<384, 64>>>(upw, convw);
    k_down    <<<512, 256>>>(x, down_w, down_b);
    k_conv2   <<<256, 256, 106496>>>(k31w, k31b, k51w, k51b, k32w, k32b, k52w, k52b);
    k_bn      <<<1, 64>>>(bn3g, bn3b, bn5g, bn5b);
    k_branch3 <<<512, 256>>>();
    k_mix     <<<512, 256>>>(convb);
    {
        dim3 grid(ROWS / 128, 384 / 128);
        k_up <<<grid, 256>>>(x, upb, out);
    }
}

// round 14
// speedup vs baseline: 1.9705x; 1.0133x over previous
#include <cuda_runtime.h>
#include <cuda_fp16.h>
#include <math.h>
#include <stdint.h>

#define LTOT (2*64*32*1024)
#define ROWS 65536

__device__ __align__(16) __half g_h5h[LTOT];
__device__ __align__(16) __half2 g_x12[LTOT];
__device__ __align__(16) __half g_sh[LTOT];
__device__ __align__(16) __half g_yTh[(size_t)ROWS * 64];
__device__ __align__(16) __half g_Wph[384 * 64];
__device__ __align__(16) __half g_W2h[64 * 64];

__device__ float g_gre[32], g_gim[32], g_qre[32], g_qim[32];
__device__ float g_sum1[64], g_sq1[64], g_sum2[64], g_sq2[64];

__device__ __forceinline__ float gelu_f(float v) {
    return 0.5f * v * (1.0f + erff(v * 0.70710678118654752f));
}

__device__ __forceinline__ uint32_t pack2(float a, float b) {
    __half2 h = __floats2half2_rn(a, b);
    return *reinterpret_cast<uint32_t*>(&h);
}

__device__ __forceinline__ uint32_t saddr(const void* p) {
    return static_cast<uint32_t>(__cvta_generic_to_shared(p));
}

__device__ __forceinline__ void ldsm4(uint32_t r[4], uint32_t a) {
    asm volatile("ldmatrix.sync.aligned.m8n8.x4.shared.b16 {%0,%1,%2,%3}, [%4];"
                 : "=r"(r[0]), "=r"(r[1]), "=r"(r[2]), "=r"(r[3]) : "r"(a));
}

__device__ __forceinline__ void ldsm4t(uint32_t r[4], uint32_t a) {
    asm volatile("ldmatrix.sync.aligned.m8n8.x4.trans.shared.b16 {%0,%1,%2,%3}, [%4];"
                 : "=r"(r[0]), "=r"(r[1]), "=r"(r[2]), "=r"(r[3]) : "r"(a));
}

__device__ __forceinline__ void mma16816(float c[4], const uint32_t a[4],
                                         uint32_t b0, uint32_t b1) {
    asm volatile(
        "mma.sync.aligned.m16n8k16.row.col.f32.f16.f16.f32 "
        "{%0,%1,%2,%3}, {%4,%5,%6,%7}, {%8,%9}, {%0,%1,%2,%3};"
        : "+f"(c[0]), "+f"(c[1]), "+f"(c[2]), "+f"(c[3])
        : "r"(a[0]), "r"(a[1]), "r"(a[2]), "r"(a[3]), "r"(b0), "r"(b1));
}

// K0: g = ifft_T(fw), q = ifft_T(fb); zero BN stats
__global__ void k_prep(const float* __restrict__ fw, const float* __restrict__ fb) {
    int n = threadIdx.x;
    if (n < 32) {
        double gr = 0, gi = 0, qr = 0, qi = 0;
        for (int k = 0; k < 32; k++) {
            double ang = 6.283185307179586476925 * (double)((k * n) & 31) / 32.0;
            double cs = cos(ang), sn = sin(ang);
            gr += (double)fw[k] * cs; gi += (double)fw[k] * sn;
            qr += (double)fb[k] * cs; qi += (double)fb[k] * sn;
        }
        g_gre[n] = (float)(gr / 32.0); g_gim[n] = (float)(gi / 32.0);
        g_qre[n] = (float)(qr / 32.0); g_qim[n] = (float)(qi / 32.0);
    }
    if (n < 64) { g_sum1[n] = 0.f; g_sq1[n] = 0.f; g_sum2[n] = 0.f; g_sq2[n] = 0.f; }
}

// K0b: up_w and conv_w -> fp16
__global__ void k_cvt(const float* __restrict__ up, const float* __restrict__ w2) {
    int of = blockIdx.x, j = threadIdx.x;
    g_Wph[of * 64 + j] = __float2half_rn(up[of * 64 + j]);
    if (of < 64) g_W2h[of * 64 + j] = __float2half_rn(w2[of * 64 + j]);
}

// K1: down GEMM (fp16 mma + ldmatrix) + bias + GELU -> h5h NCDHW (fp16)
__global__ void __launch_bounds__(256) k_down(const float* __restrict__ x,
                                              const float* __restrict__ w,
                                              const float* __restrict__ bias) {
    __shared__ __align__(16) __half As[128][72];
    __shared__ __align__(16) __half Bs[64][72];
    int tid = threadIdx.x;
    int r0 = blockIdx.x * 128;
    int wid = tid >> 5, lane = tid & 31;
    int g = lane >> 2, tig = lane & 3;
    int warp_m = (wid & 3) * 32;
    int warp_n = (wid >> 2) * 32;

    float acc[2][4][4];
    #pragma unroll
    for (int i = 0; i < 2; i++)
        #pragma unroll
        for (int j = 0; j < 4; j++)
            #pragma unroll
            for (int l = 0; l < 4; l++) acc[i][j][l] = 0.f;

    for (int k0 = 0; k0 < 384; k0 += 64) {
        #pragma unroll
        for (int i = 0; i < 4; i++) {
            int idx = tid + i * 256;
            int m = idx >> 3, sg = idx & 7;
            const float4* p = reinterpret_cast<const float4*>(&x[(size_t)(r0 + m) * 384 + k0 + sg * 8]);
            float4 v0 = p[0], v1 = p[1];
            uint4 st;
            st.x = pack2(v0.x, v0.y); st.y = pack2(v0.z, v0.w);
            st.z = pack2(v1.x, v1.y); st.w = pack2(v1.z, v1.w);
            *reinterpret_cast<uint4*>(&As[m][sg * 8]) = st;
        }
        #pragma unroll
        for (int i = 0; i < 2; i++) {
            int idx = tid + i * 256;
            int n = idx >> 3, sg = idx & 7;
            const float4* p = reinterpret_cast<const float4*>(&w[n * 384 + k0 + sg * 8]);
            float4 v0 = p[0], v1 = p[1];
            uint4 st;
            st.x = pack2(v0.x, v0.y); st.y = pack2(v0.z, v0.w);
            st.z = pack2(v1.x, v1.y); st.w = pack2(v1.z, v1.w);
            *reinterpret_cast<uint4*>(&Bs[n][sg * 8]) = st;
        }
        __syncthreads();
        #pragma unroll
        for (int ks = 0; ks < 4; ks++) {
            int kk = ks * 16;
            uint32_t a[2][4];
            #pragma unroll
            for (int mf = 0; mf < 2; mf++)
                ldsm4(a[mf], saddr(&As[warp_m + mf * 16 + (lane & 15)][kk + (lane >> 4) * 8]));
            uint32_t b[2][4];
            #pragma unroll
            for (int h = 0; h < 2; h++)
                ldsm4(b[h], saddr(&Bs[warp_n + h * 16 + ((lane >> 4) & 1) * 8 + (lane & 7)]
                                     [kk + ((lane >> 3) & 1) * 8]));
            #pragma unroll
            for (int mf = 0; mf < 2; mf++)
                #pragma unroll
                for (int nf = 0; nf < 4; nf++)
                    mma16816(acc[mf][nf], a[mf], b[nf >> 1][(nf & 1) * 2], b[nf >> 1][(nf & 1) * 2 + 1]);
        }
        __syncthreads();
    }
    int bt = r0 >> 10, hwbase = r0 & 1023;
    int b5i = bt >> 5, t = bt & 31;
    size_t planebase = (size_t)(b5i * 64) * 32768 + (size_t)t * 1024;
    #pragma unroll
    for (int nf = 0; nf < 4; nf++) {
        int c0 = warp_n + nf * 8 + 2 * tig;
        float bs0 = bias[c0], bs1 = bias[c0 + 1];
        #pragma unroll
        for (int mf = 0; mf < 2; mf++) {
            int m = warp_m + mf * 16 + g;
            size_t p0 = planebase + (size_t)c0 * 32768;
            g_h5h[p0 + hwbase + m]             = __float2half_rn(gelu_f(acc[mf][nf][0] + bs0));
            g_h5h[p0 + 32768 + hwbase + m]     = __float2half_rn(gelu_f(acc[mf][nf][1] + bs1));
            g_h5h[p0 + hwbase + m + 8]         = __float2half_rn(gelu_f(acc[mf][nf][2] + bs0));
            g_h5h[p0 + 32768 + hwbase + m + 8] = __float2half_rn(gelu_f(acc[mf][nf][3] + bs1));
        }
    }
}

// K2: fused spatial(3x3,5x5) + temporal(3,5) depthwise + BN stats, all-smem
// block = (bc, 8-row h-band). smem 56KB: in[32][12][32] + s3[32][256] + s5[32][256] fp16
__global__ void __launch_bounds__(256) k_conv2(const float* __restrict__ w3g,
                                               const float* __restrict__ b3g,
                                               const float* __restrict__ w5g,
                                               const float* __restrict__ b5g,
                                               const float* __restrict__ wt3g,
                                               const float* __restrict__ bt3g,
                                               const float* __restrict__ wt5g,
                                               const float* __restrict__ bt5g) {
    extern __shared__ __half smh[];
    __half* in = smh;           // 12288 halves
    __half* s3 = smh + 12288;   // 8192
    __half* s5 = smh + 20480;   // 8192
    int bc = blockIdx.x >> 2;
    int band = blockIdx.x & 3;
    int h0 = band * 8;
    int c = bc & 63;
    size_t base = (size_t)bc * 32768;
    int tid = threadIdx.x;

    __shared__ float w3[9], w5[25], wt3[3], wt5[5];
    if (tid < 9)  w3[tid] = w3g[c * 9 + tid];
    if (tid >= 32 && tid < 57) w5[tid - 32] = w5g[c * 25 + (tid - 32)];
    if (tid >= 64 && tid < 67) wt3[tid - 64] = wt3g[c * 3 + (tid - 64)];
    if (tid >= 96 && tid < 101) wt5[tid - 96] = wt5g[c * 5 + (tid - 96)];

    // load input band with +-2 h halo: 32 t x 12 rows x 32 = 1536 uint4
    for (int i4 = tid; i4 < 1536; i4 += 256) {
        int t = i4 / 48, rem = i4 - t * 48;
        int r = rem >> 2, w8 = (rem & 3) * 8;
        int gh = h0 - 2 + r;
        uint4 v = make_uint4(0u, 0u, 0u, 0u);
        if ((unsigned)gh < 32u)
            v = *reinterpret_cast<const uint4*>(&g_h5h[base + (size_t)t * 1024 + gh * 32 + w8]);
        *reinterpret_cast<uint4*>(&in[t * 384 + r * 32 + w8]) = v;
    }
    __syncthreads();

    float b3 = b3g[c], b5 = b5g[c];
    // spatial: 2048 groups of 4 px (32 t x 8 h x 8 wgroups)
    for (int gid = tid; gid < 2048; gid += 256) {
        int t = gid >> 6;
        int rem = gid & 63;
        int h = rem >> 3;
        int w0 = (rem & 7) * 4;
        float a3[4] = {b3, b3, b3, b3};
        float a5[4] = {b5, b5, b5, b5};
        #pragma unroll
        for (int dh = 0; dh < 5; dh++) {
            const __half* rp = &in[t * 384 + (h + dh) * 32];
            float r[8];
            #pragma unroll
            for (int j = 0; j < 8; j++) {
                int ww = w0 - 2 + j;
                r[j] = ((unsigned)ww < 32u) ? __half2float(rp[ww]) : 0.f;
            }
            #pragma unroll
            for (int px = 0; px < 4; px++)
                #pragma unroll
                for (int dw = 0; dw < 5; dw++)
                    a5[px] = fmaf(r[px + dw], w5[dh * 5 + dw], a5[px]);
            if (dh >= 1 && dh <= 3) {
                #pragma unroll
                for (int px = 0; px < 4; px++)
                    #pragma unroll
                    for (int dw = 0; dw < 3; dw++)
                        a3[px] = fmaf(r[px + dw + 1], w3[(dh - 1) * 3 + dw], a3[px]);
            }
        }
        int p = h * 32 + w0;
        uint2 v3, v5;
        v3.x = pack2(a3[0], a3[1]); v3.y = pack2(a3[2], a3[3]);
        v5.x = pack2(a5[0], a5[1]); v5.y = pack2(a5[2], a5[3]);
        *reinterpret_cast<uint2*>(&s3[t * 256 + p]) = v3;
        *reinterpret_cast<uint2*>(&s5[t * 256 + p]) = v5;
    }
    __syncthreads();

    float bt3 = bt3g[c], bt5 = bt5g[c];
    float s1 = 0, q1 = 0, s2 = 0, q2 = 0;
    for (int i = tid; i < 8192; i += 256) {
        int t = i >> 8, p = i & 255;
        float a = bt3;
        #pragma unroll
        for (int dt = -1; dt <= 1; dt++) {
            int tt = t + dt;
            if ((unsigned)tt < 32u) a = fmaf(__half2float(s3[tt * 256 + p]), wt3[dt + 1], a);
        }
        float e = bt5;
        #pragma unroll
        for (int dt = -2; dt <= 2; dt++) {
            int tt = t + dt;
            if ((unsigned)tt < 32u) e = fmaf(__half2float(s5[tt * 256 + p]), wt5[dt + 2], e);
        }
        g_x12[base + (size_t)t * 1024 + h0 * 32 + p] = __floats2half2_rn(a, e);
        s1 += a; q1 = fmaf(a, a, q1);
        s2 += e; q2 = fmaf(e, e, q2);
    }
    #pragma unroll
    for (int off = 16; off; off >>= 1) {
        s1 += __shfl_down_sync(0xffffffffu, s1, off);
        q1 += __shfl_down_sync(0xffffffffu, q1, off);
        s2 += __shfl_down_sync(0xffffffffu, s2, off);
        q2 += __shfl_down_sync(0xffffffffu, q2, off);
    }
    __shared__ float red[4][8];
    int wid = tid >> 5, lane = tid & 31;
    if (lane == 0) { red[0][wid] = s1; red[1][wid] = q1; red[2][wid] = s2; red[3][wid] = q2; }
    __syncthreads();
    if (tid == 0) {
        float a = 0, b = 0, c2 = 0, d = 0;
        for (int i = 0; i < 8; i++) { a += red[0][i]; b += red[1][i]; c2 += red[2][i]; d += red[3][i]; }
        atomicAdd(&g_sum1[c], a);  atomicAdd(&g_sq1[c], b);
        atomicAdd(&g_sum2[c], c2); atomicAdd(&g_sq2[c], d);
    }
}

// K5: circulant T-conv via fp16 MMA + BN-ReLU combine -> s (fp16). BN coeffs inlined.
__global__ void __launch_bounds__(256) k_branch3(const float* __restrict__ g3,
                                                 const float* __restrict__ b3,
                                                 const float* __restrict__ g5,
                                                 const float* __restrict__ b5) {
    __shared__ __align__(16) __half Gre[32][40];
    __shared__ __align__(16) __half Gim[32][40];
    __shared__ __align__(16) __half Vs[32][264];
    __shared__ float2 qq[32];
    int bc  = blockIdx.x >> 2;
    int hw0 = (blockIdx.x & 3) << 8;
    int c = bc & 63;
    size_t base = (size_t)bc * 32768;
    int tid = threadIdx.x;
    int wid = tid >> 5, lane = tid & 31;
    int g = lane >> 2, tig = lane & 3;
    int hwb = wid * 32;

    // BN coefficients (recomputed per block; cheap)
    const float inv = 1.0f / 65536.0f;
    float m1 = g_sum1[c] * inv;
    float v1 = g_sq1[c] * inv - m1 * m1;
    float a1 = g3[c] * rsqrtf(v1 + 1e-5f);
    float bb1 = b3[c] - m1 * a1;
    float m2 = g_sum2[c] * inv;
    float v2 = g_sq2[c] * inv - m2 * m2;
    float a2 = g5[c] * rsqrtf(v2 + 1e-5f);
    float bb2 = b5[c] - m2 * a2;

    if (tid < 32) qq[tid] = make_float2(g_qre[tid], g_qim[tid]);
    for (int i = tid; i < 1024; i += 256) {
        int t = i >> 5, tau = i & 31;
        int d = (t - tau + 32) & 31;
        Gre[t][tau] = __float2half_rn(g_gre[d]);
        Gim[t][tau] = __float2half_rn(g_gim[d]);
    }
    for (int i4 = tid; i4 < 1024; i4 += 256) {
        int t = i4 >> 5, q8 = (i4 & 31) * 8;
        *reinterpret_cast<uint4*>(&Vs[t][q8]) =
            *reinterpret_cast<const uint4*>(&g_h5h[base + (size_t)t * 1024 + hw0 + q8]);
    }
    __syncthreads();

    float ar[2][4][4], ai[2][4][4];
    #pragma unroll
    for (int i = 0; i < 2; i++)
        #pragma unroll
        for (int j = 0; j < 4; j++)
            #pragma unroll
            for (int l = 0; l < 4; l++) { ar[i][j][l] = 0.f; ai[i][j][l] = 0.f; }

    #pragma unroll
    for (int ks = 0; ks < 2; ks++) {
        int kk = ks * 16;
        uint32_t are[2][4], aim[2][4];
        #pragma unroll
        for (int mf = 0; mf < 2; mf++) {
            ldsm4(are[mf], saddr(&Gre[mf * 16 + (lane & 15)][kk + (lane >> 4) * 8]));
            ldsm4(aim[mf], saddr(&Gim[mf * 16 + (lane & 15)][kk + (lane >> 4) * 8]));
        }
        uint32_t b[2][4];
        #pragma unroll
        for (int h = 0; h < 2; h++)
            ldsm4t(b[h], saddr(&Vs[kk + (lane & 7) + ((lane >> 3) & 1) * 8]
                                  [hwb + h * 16 + ((lane >> 4) & 1) * 8]));
        #pragma unroll
        for (int mf = 0; mf < 2; mf++)
            #pragma unroll
            for (int nf = 0; nf < 4; nf++) {
                uint32_t b0 = b[nf >> 1][(nf & 1) * 2], b1v = b[nf >> 1][(nf & 1) * 2 + 1];
                mma16816(ar[mf][nf], are[mf], b0, b1v);
                mma16816(ai[mf][nf], aim[mf], b0, b1v);
            }
    }

    #pragma unroll
    for (int mf = 0; mf < 2; mf++)
        #pragma unroll
        for (int nf = 0; nf < 4; nf++)
            #pragma unroll
            for (int l = 0; l < 4; l++) {
                int t = mf * 16 + g + (l >> 1) * 8;
                int hw = hw0 + hwb + nf * 8 + 2 * tig + (l & 1);
                float rr = ar[mf][nf][l], ii = ai[mf][nf][l];
                if (hw == 0) { rr += qq[t].x; ii += qq[t].y; }
                float x3 = sqrtf(rr * rr + ii * ii);
                size_t idx = base + (size_t)t * 1024 + hw;
                float2 v12 = __half22float2(g_x12[idx]);
                float x1v = fmaxf(fmaf(v12.x, a1, bb1), 0.f);
                float x2v = fmaxf(fmaf(v12.y, a2, bb2), 0.f);
                g_sh[idx] = __float2half_rn(x1v + x2v + x3);
            }
}

// K6: channel mix via fp16 MMA + shortcut -> yT fp16 [row][o]
__global__ void __launch_bounds__(256) k_mix(const float* __restrict__ cb) {
    __shared__ __align__(16) __half W2s[64][72];
    __shared__ __align__(16) __half Ss[64][136];
    int bt  = blockIdx.x >> 3;
    int hw0 = (blockIdx.x & 7) << 7;
    int b = bt >> 5, t = bt & 31;
    int tid = threadIdx.x;
    int wid = tid >> 5, lane = tid & 31;
    int g = lane >> 2, tig = lane & 3;
    int warp_m = (wid & 1) * 32;
    int warp_n = (wid >> 1) * 32;

    for (int i = tid; i < 512; i += 256) {
        int o = i >> 3, sg = i & 7;
        *reinterpret_cast<uint4*>(&W2s[o][sg * 8]) =
            *reinterpret_cast<const uint4*>(&g_W2h[o * 64 + sg * 8]);
    }
    for (int i = tid; i < 1024; i += 256) {
        int cx = i >> 4, p8 = (i & 15) * 8;
        *reinterpret_cast<uint4*>(&Ss[cx][p8]) =
            *reinterpret_cast<const uint4*>(&g_sh[(size_t)((b * 64 + cx) * 32 + t) * 1024 + hw0 + p8]);
    }
    __syncthreads();

    float acc[2][4][4];
    #pragma unroll
    for (int i = 0; i < 2; i++)
        #pragma unroll
        for (int j = 0; j < 4; j++)
            #pragma unroll
            for (int l = 0; l < 4; l++) acc[i][j][l] = 0.f;

    #pragma unroll
    for (int ks = 0; ks < 4; ks++) {
        int kk = ks * 16;
        uint32_t a[2][4];
        #pragma unroll
        for (int mf = 0; mf < 2; mf++)
            ldsm4(a[mf], saddr(&W2s[warp_m + mf * 16 + (lane & 15)][kk + (lane >> 4) * 8]));
        uint32_t bfr[2][4];
        #pragma unroll
        for (int h = 0; h < 2; h++)
            ldsm4t(bfr[h], saddr(&Ss[kk + (lane & 7) + ((lane >> 3) & 1) * 8]
                                    [warp_n + h * 16 + ((lane >> 4) & 1) * 8]));
        #pragma unroll
        for (int mf = 0; mf < 2; mf++)
            #pragma unroll
            for (int nf = 0; nf < 4; nf++)
                mma16816(acc[mf][nf], a[mf],
                         bfr[nf >> 1][(nf & 1) * 2], bfr[nf >> 1][(nf & 1) * 2 + 1]);
    }

    #pragma unroll
    for (int mf = 0; mf < 2; mf++)
        #pragma unroll
        for (int nf = 0; nf < 4; nf++)
            #pragma unroll
            for (int l = 0; l < 4; l++) {
                int o = warp_m + mf * 16 + g + (l >> 1) * 8;
                int hw = hw0 + warp_n + nf * 8 + 2 * tig + (l & 1);
                float v = __half2float(g_h5h[(size_t)((b * 64 + o) * 32 + t) * 1024 + hw])
                          + acc[mf][nf][l] + cb[o];
                g_yTh[((size_t)bt * 1024 + hw) * 64 + o] = __float2half_rn(v);
            }
}

// K7: up GEMM (fp16 mma + ldmatrix, K=64 single chunk) + bias + GELU + residual
__global__ void __launch_bounds__(256) k_up(const float* __restrict__ x,
                                            const float* __restrict__ bias,
                                            float* __restrict__ out) {
    __shared__ __align__(16) __half As[128][72];
    __shared__ __align__(16) __half Bs[128][72];
    int tid = threadIdx.x;
    int r0 = blockIdx.x * 128;
    int n0 = blockIdx.y * 128;
    int wid = tid >> 5, lane = tid & 31;
    int g = lane >> 2, tig = lane & 3;
    int warp_m = (wid & 1) * 64;
    int warp_n = (wid >> 1) * 32;

    float acc[4][4][4];
    #pragma unroll
    for (int i = 0; i < 4; i++)
        #pragma unroll
        for (int j = 0; j < 4; j++)
            #pragma unroll
            for (int l = 0; l < 4; l++) acc[i][j][l] = 0.f;

    #pragma unroll
    for (int i = 0; i < 4; i++) {
        int idx = tid + i * 256;
        int m = idx >> 3, sg = idx & 7;
        *reinterpret_cast<uint4*>(&As[m][sg * 8]) =
            *reinterpret_cast<const uint4*>(&g_yTh[(size_t)(r0 + m) * 64 + sg * 8]);
    }
    #pragma unroll
    for (int i = 0; i < 4; i++) {
        int idx = tid + i * 256;
        int n = idx >> 3, sg = idx & 7;
        *reinterpret_cast<uint4*>(&Bs[n][sg * 8]) =
            *reinterpret_cast<const uint4*>(&g_Wph[(size_t)(n0 + n) * 64 + sg * 8]);
    }
    __syncthreads();
    #pragma unroll
    for (int ks = 0; ks < 4; ks++) {
        int kk = ks * 16;
        uint32_t a[4][4];
        #pragma unroll
        for (int mf = 0; mf < 4; mf++)
            ldsm4(a[mf], saddr(&As[warp_m + mf * 16 + (lane & 15)][kk + (lane >> 4) * 8]));
        uint32_t bfr[2][4];
        #pragma unroll
        for (int h = 0; h < 2; h++)
            ldsm4(bfr[h], saddr(&Bs[warp_n + h * 16 + ((lane >> 4) & 1) * 8 + (lane & 7)]
                                   [kk + ((lane >> 3) & 1) * 8]));
        #pragma unroll
        for (int mf = 0; mf < 4; mf++)
            #pragma unroll
            for (int nf = 0; nf < 4; nf++)
                mma16816(acc[mf][nf], a[mf],
                         bfr[nf >> 1][(nf & 1) * 2], bfr[nf >> 1][(nf & 1) * 2 + 1]);
    }
    #pragma unroll
    for (int nf = 0; nf < 4; nf++) {
        int col = n0 + warp_n + nf * 8 + 2 * tig;
        float bs0 = bias[col], bs1 = bias[col + 1];
        #pragma unroll
        for (int mf = 0; mf < 4; mf++) {
            #pragma unroll
            for (int half = 0; half < 2; half++) {
                int row = r0 + warp_m + mf * 16 + g + half * 8;
                float c0 = acc[mf][nf][half * 2 + 0];
                float c1 = acc[mf][nf][half * 2 + 1];
                const float2 xin = *reinterpret_cast<const float2*>(&x[(size_t)row * 384 + col]);
                float2 o;
                o.x = xin.x + gelu_f(c0 + bs0);
                o.y = xin.y + gelu_f(c1 + bs1);
                *reinterpret_cast<float2*>(&out[(size_t)row * 384 + col]) = o;
            }
        }
    }
}

extern "C" void kernel_launch(void* const* d_in, const int* in_sizes, int n_in,
                              void* d_out, int out_size) {
    const float* x      = (const float*)d_in[0];
    const float* down_w = (const float*)d_in[1];
    const float* down_b = (const float*)d_in[2];
    const float* k31w   = (const float*)d_in[3];
    const float* k31b   = (const float*)d_in[4];
    const float* k32w   = (const float*)d_in[5];
    const float* k32b   = (const float*)d_in[6];
    const float* bn3g   = (const float*)d_in[7];
    const float* bn3b   = (const float*)d_in[8];
    const float* k51w   = (const float*)d_in[9];
    const float* k51b   = (const float*)d_in[10];
    const float* k52w   = (const float*)d_in[11];
    const float* k52b   = (const float*)d_in[12];
    const float* bn5g   = (const float*)d_in[13];
    const float* bn5b   = (const float*)d_in[14];
    const float* convw  = (const float*)d_in[15];
    const float* convb  = (const float*)d_in[16];
    const float* fw     = (const float*)d_in[17];
    const float* fb     = (const float*)d_in[18];
    const float* upw    = (const float*)d_in[19];
    const float* upb    = (const float*)d_in[20];
    float* out = (float*)d_out;

    cudaFuncSetAttribute(k_conv2, cudaFuncAttributeMaxDynamicSharedMemorySize, 57344);

    k_prep    <<<1, 64>>>(fw, fb);
    k_cvt     <<<384, 64>>>(upw, convw);
    k_down    <<<512, 256>>>(x, down_w, down_b);
    k_conv2   <<<512, 256, 57344>>>(k31w, k31b, k51w, k51b, k32w, k32b, k52w, k52b);
    k_branch3 <<<512, 256>>>(bn3g, bn3b, bn5g, bn5b);
    k_mix     <<<512, 256>>>(convb);
    {
        dim3 grid(ROWS / 128, 384 / 128);
        k_up <<<grid, 256>>>(x, upb, out);
    }
}

// round 15
// speedup vs baseline: 2.0233x; 1.0268x over previous
#include <cuda_runtime.h>
#include <cuda_fp16.h>
#include <math.h>
#include <stdint.h>

#define LTOT (2*64*32*1024)
#define ROWS 65536

__device__ __align__(16) __half g_h5h[LTOT];
__device__ __align__(16) __half2 g_x12[LTOT];
__device__ __align__(16) __half g_sh[LTOT];
__device__ __align__(16) __half g_yTh[(size_t)ROWS * 64];
__device__ __align__(16) __half g_Wph[384 * 64];
__device__ __align__(16) __half g_W2h[64 * 64];

__device__ float g_gre[32], g_gim[32], g_qre[32], g_qim[32];
__device__ float g_sum1[64], g_sq1[64], g_sum2[64], g_sq2[64];

__device__ __forceinline__ float gelu_f(float v) {
    return 0.5f * v * (1.0f + erff(v * 0.70710678118654752f));
}

__device__ __forceinline__ uint32_t pack2(float a, float b) {
    __half2 h = __floats2half2_rn(a, b);
    return *reinterpret_cast<uint32_t*>(&h);
}

__device__ __forceinline__ uint32_t saddr(const void* p) {
    return static_cast<uint32_t>(__cvta_generic_to_shared(p));
}

__device__ __forceinline__ void ldsm4(uint32_t r[4], uint32_t a) {
    asm volatile("ldmatrix.sync.aligned.m8n8.x4.shared.b16 {%0,%1,%2,%3}, [%4];"
                 : "=r"(r[0]), "=r"(r[1]), "=r"(r[2]), "=r"(r[3]) : "r"(a));
}

__device__ __forceinline__ void ldsm4t(uint32_t r[4], uint32_t a) {
    asm volatile("ldmatrix.sync.aligned.m8n8.x4.trans.shared.b16 {%0,%1,%2,%3}, [%4];"
                 : "=r"(r[0]), "=r"(r[1]), "=r"(r[2]), "=r"(r[3]) : "r"(a));
}

__device__ __forceinline__ void mma16816(float c[4], const uint32_t a[4],
                                         uint32_t b0, uint32_t b1) {
    asm volatile(
        "mma.sync.aligned.m16n8k16.row.col.f32.f16.f16.f32 "
        "{%0,%1,%2,%3}, {%4,%5,%6,%7}, {%8,%9}, {%0,%1,%2,%3};"
        : "+f"(c[0]), "+f"(c[1]), "+f"(c[2]), "+f"(c[3])
        : "r"(a[0]), "r"(a[1]), "r"(a[2]), "r"(a[3]), "r"(b0), "r"(b1));
}

// K0: fused prep (ifft of fw/fb, zero stats) + weight conversion to fp16
__global__ void k_init(const float* __restrict__ fw, const float* __restrict__ fb,
                       const float* __restrict__ up, const float* __restrict__ w2) {
    int of = blockIdx.x, j = threadIdx.x;
    g_Wph[of * 64 + j] = __float2half_rn(up[of * 64 + j]);
    if (of < 64) g_W2h[of * 64 + j] = __float2half_rn(w2[of * 64 + j]);
    if (of == 0) {
        int n = j;
        if (n < 32) {
            double gr = 0, gi = 0, qr = 0, qi = 0;
            for (int k = 0; k < 32; k++) {
                double ang = 6.283185307179586476925 * (double)((k * n) & 31) / 32.0;
                double cs = cos(ang), sn = sin(ang);
                gr += (double)fw[k] * cs; gi += (double)fw[k] * sn;
                qr += (double)fb[k] * cs; qi += (double)fb[k] * sn;
            }
            g_gre[n] = (float)(gr / 32.0); g_gim[n] = (float)(gi / 32.0);
            g_qre[n] = (float)(qr / 32.0); g_qim[n] = (float)(qi / 32.0);
        }
        g_sum1[n] = 0.f; g_sq1[n] = 0.f; g_sum2[n] = 0.f; g_sq2[n] = 0.f;
    }
}

// K1: down GEMM (fp16 mma + ldmatrix) + bias + GELU -> h5h NCDHW (fp16)
__global__ void __launch_bounds__(256) k_down(const float* __restrict__ x,
                                              const float* __restrict__ w,
                                              const float* __restrict__ bias) {
    __shared__ __align__(16) __half As[128][72];
    __shared__ __align__(16) __half Bs[64][72];
    int tid = threadIdx.x;
    int r0 = blockIdx.x * 128;
    int wid = tid >> 5, lane = tid & 31;
    int g = lane >> 2, tig = lane & 3;
    int warp_m = (wid & 3) * 32;
    int warp_n = (wid >> 2) * 32;

    float acc[2][4][4];
    #pragma unroll
    for (int i = 0; i < 2; i++)
        #pragma unroll
        for (int j = 0; j < 4; j++)
            #pragma unroll
            for (int l = 0; l < 4; l++) acc[i][j][l] = 0.f;

    for (int k0 = 0; k0 < 384; k0 += 64) {
        #pragma unroll
        for (int i = 0; i < 4; i++) {
            int idx = tid + i * 256;
            int m = idx >> 3, sg = idx & 7;
            const float4* p = reinterpret_cast<const float4*>(&x[(size_t)(r0 + m) * 384 + k0 + sg * 8]);
            float4 v0 = p[0], v1 = p[1];
            uint4 st;
            st.x = pack2(v0.x, v0.y); st.y = pack2(v0.z, v0.w);
            st.z = pack2(v1.x, v1.y); st.w = pack2(v1.z, v1.w);
            *reinterpret_cast<uint4*>(&As[m][sg * 8]) = st;
        }
        #pragma unroll
        for (int i = 0; i < 2; i++) {
            int idx = tid + i * 256;
            int n = idx >> 3, sg = idx & 7;
            const float4* p = reinterpret_cast<const float4*>(&w[n * 384 + k0 + sg * 8]);
            float4 v0 = p[0], v1 = p[1];
            uint4 st;
            st.x = pack2(v0.x, v0.y); st.y = pack2(v0.z, v0.w);
            st.z = pack2(v1.x, v1.y); st.w = pack2(v1.z, v1.w);
            *reinterpret_cast<uint4*>(&Bs[n][sg * 8]) = st;
        }
        __syncthreads();
        #pragma unroll
        for (int ks = 0; ks < 4; ks++) {
            int kk = ks * 16;
            uint32_t a[2][4];
            #pragma unroll
            for (int mf = 0; mf < 2; mf++)
                ldsm4(a[mf], saddr(&As[warp_m + mf * 16 + (lane & 15)][kk + (lane >> 4) * 8]));
            uint32_t b[2][4];
            #pragma unroll
            for (int h = 0; h < 2; h++)
                ldsm4(b[h], saddr(&Bs[warp_n + h * 16 + ((lane >> 4) & 1) * 8 + (lane & 7)]
                                     [kk + ((lane >> 3) & 1) * 8]));
            #pragma unroll
            for (int mf = 0; mf < 2; mf++)
                #pragma unroll
                for (int nf = 0; nf < 4; nf++)
                    mma16816(acc[mf][nf], a[mf], b[nf >> 1][(nf & 1) * 2], b[nf >> 1][(nf & 1) * 2 + 1]);
        }
        __syncthreads();
    }
    int bt = r0 >> 10, hwbase = r0 & 1023;
    int b5i = bt >> 5, t = bt & 31;
    size_t planebase = (size_t)(b5i * 64) * 32768 + (size_t)t * 1024;
    #pragma unroll
    for (int nf = 0; nf < 4; nf++) {
        int c0 = warp_n + nf * 8 + 2 * tig;
        float bs0 = bias[c0], bs1 = bias[c0 + 1];
        #pragma unroll
        for (int mf = 0; mf < 2; mf++) {
            int m = warp_m + mf * 16 + g;
            size_t p0 = planebase + (size_t)c0 * 32768;
            g_h5h[p0 + hwbase + m]             = __float2half_rn(gelu_f(acc[mf][nf][0] + bs0));
            g_h5h[p0 + 32768 + hwbase + m]     = __float2half_rn(gelu_f(acc[mf][nf][1] + bs1));
            g_h5h[p0 + hwbase + m + 8]         = __float2half_rn(gelu_f(acc[mf][nf][2] + bs0));
            g_h5h[p0 + 32768 + hwbase + m + 8] = __float2half_rn(gelu_f(acc[mf][nf][3] + bs1));
        }
    }
}

// K2: fused spatial+temporal depthwise + BN stats; padded rows, aligned loads
// block = (bc, 8-row h-band). smem: in 32t x 12r x 36 + s3/s5 32 x 256 fp16
__global__ void __launch_bounds__(256) k_conv2(const float* __restrict__ w3g,
                                               const float* __restrict__ b3g,
                                               const float* __restrict__ w5g,
                                               const float* __restrict__ b5g,
                                               const float* __restrict__ wt3g,
                                               const float* __restrict__ bt3g,
                                               const float* __restrict__ wt5g,
                                               const float* __restrict__ bt5g) {
    extern __shared__ __half smh[];
    __half* in = smh;            // 32*12*36 = 13824 halves
    __half* s3 = smh + 13824;    // 8192
    __half* s5 = smh + 22016;    // 8192
    int bc = blockIdx.x >> 2;
    int band = blockIdx.x & 3;
    int h0 = band * 8;
    int c = bc & 63;
    size_t base = (size_t)bc * 32768;
    int tid = threadIdx.x;

    __shared__ float w3[9], w5[25], wt3[3], wt5[5];
    if (tid < 9)  w3[tid] = w3g[c * 9 + tid];
    if (tid >= 32 && tid < 57) w5[tid - 32] = w5g[c * 25 + (tid - 32)];
    if (tid >= 64 && tid < 67) wt3[tid - 64] = wt3g[c * 3 + (tid - 64)];
    if (tid >= 96 && tid < 101) wt5[tid - 96] = wt5g[c * 5 + (tid - 96)];

    // zero the 2-half borders of all 384 rows
    for (int r = tid; r < 384; r += 256) {
        __half* row = &in[r * 36];
        *reinterpret_cast<uint32_t*>(&row[0]) = 0u;
        *reinterpret_cast<uint32_t*>(&row[34]) = 0u;
    }
    // interior fill: 1536 global uint4 (8 halves), stored as 4 uint each at offset 2
    for (int i4 = tid; i4 < 1536; i4 += 256) {
        int t = i4 / 48, rem = i4 - t * 48;
        int r = rem >> 2, w8 = (rem & 3) * 8;
        int gh = h0 - 2 + r;
        uint4 v = make_uint4(0u, 0u, 0u, 0u);
        if ((unsigned)gh < 32u)
            v = *reinterpret_cast<const uint4*>(&g_h5h[base + (size_t)t * 1024 + gh * 32 + w8]);
        uint32_t* d = reinterpret_cast<uint32_t*>(&in[t * 432 + r * 36 + 2 + w8]);
        d[0] = v.x; d[1] = v.y; d[2] = v.z; d[3] = v.w;
    }
    __syncthreads();

    float b3 = b3g[c], b5 = b5g[c];
    // spatial: 2048 groups of 4 px (32 t x 8 h x 8 wgroups); aligned uint2 loads
    for (int gid = tid; gid < 2048; gid += 256) {
        int t = gid >> 6;
        int rem = gid & 63;
        int h = rem >> 3;
        int w0 = (rem & 7) * 4;
        float a3[4] = {b3, b3, b3, b3};
        float a5[4] = {b5, b5, b5, b5};
        const __half* tbase = &in[t * 432];
        #pragma unroll
        for (int dh = 0; dh < 5; dh++) {
            const __half* rp = &tbase[(h + dh) * 36 + w0];  // = logical w0-2 (border-padded)
            uint2 u0 = *reinterpret_cast<const uint2*>(rp);
            uint2 u1 = *reinterpret_cast<const uint2*>(rp + 4);
            float2 f0 = __half22float2(*reinterpret_cast<const __half2*>(&u0.x));
            float2 f1 = __half22float2(*reinterpret_cast<const __half2*>(&u0.y));
            float2 f2 = __half22float2(*reinterpret_cast<const __half2*>(&u1.x));
            float2 f3 = __half22float2(*reinterpret_cast<const __half2*>(&u1.y));
            float r[8] = {f0.x, f0.y, f1.x, f1.y, f2.x, f2.y, f3.x, f3.y};
            #pragma unroll
            for (int px = 0; px < 4; px++)
                #pragma unroll
                for (int dw = 0; dw < 5; dw++)
                    a5[px] = fmaf(r[px + dw], w5[dh * 5 + dw], a5[px]);
            if (dh >= 1 && dh <= 3) {
                #pragma unroll
                for (int px = 0; px < 4; px++)
                    #pragma unroll
                    for (int dw = 0; dw < 3; dw++)
                        a3[px] = fmaf(r[px + dw + 1], w3[(dh - 1) * 3 + dw], a3[px]);
            }
        }
        int p = h * 32 + w0;
        uint2 v3, v5;
        v3.x = pack2(a3[0], a3[1]); v3.y = pack2(a3[2], a3[3]);
        v5.x = pack2(a5[0], a5[1]); v5.y = pack2(a5[2], a5[3]);
        *reinterpret_cast<uint2*>(&s3[t * 256 + p]) = v3;
        *reinterpret_cast<uint2*>(&s5[t * 256 + p]) = v5;
    }
    __syncthreads();

    float bt3 = bt3g[c], bt5 = bt5g[c];
    float s1 = 0, q1 = 0, s2 = 0, q2 = 0;
    // temporal: half2 pairs (4096 iterations over 8192 px)
    for (int i = tid; i < 4096; i += 256) {
        int t = i >> 7, p2 = (i & 127) * 2;
        float2 a = make_float2(bt3, bt3);
        float2 e = make_float2(bt5, bt5);
        #pragma unroll
        for (int dt = -1; dt <= 1; dt++) {
            int tt = t + dt;
            if ((unsigned)tt < 32u) {
                float2 f = __half22float2(*reinterpret_cast<const __half2*>(&s3[tt * 256 + p2]));
                float wv = wt3[dt + 1];
                a.x = fmaf(f.x, wv, a.x); a.y = fmaf(f.y, wv, a.y);
            }
        }
        #pragma unroll
        for (int dt = -2; dt <= 2; dt++) {
            int tt = t + dt;
            if ((unsigned)tt < 32u) {
                float2 f = __half22float2(*reinterpret_cast<const __half2*>(&s5[tt * 256 + p2]));
                float wv = wt5[dt + 2];
                e.x = fmaf(f.x, wv, e.x); e.y = fmaf(f.y, wv, e.y);
            }
        }
        uint2 st;
        st.x = pack2(a.x, e.x);
        st.y = pack2(a.y, e.y);
        *reinterpret_cast<uint2*>(&g_x12[base + (size_t)t * 1024 + h0 * 32 + p2]) = st;
        s1 += a.x + a.y; q1 = fmaf(a.x, a.x, fmaf(a.y, a.y, q1));
        s2 += e.x + e.y; q2 = fmaf(e.x, e.x, fmaf(e.y, e.y, q2));
    }
    #pragma unroll
    for (int off = 16; off; off >>= 1) {
        s1 += __shfl_down_sync(0xffffffffu, s1, off);
        q1 += __shfl_down_sync(0xffffffffu, q1, off);
        s2 += __shfl_down_sync(0xffffffffu, s2, off);
        q2 += __shfl_down_sync(0xffffffffu, q2, off);
    }
    __shared__ float red[4][8];
    int wid = tid >> 5, lane = tid & 31;
    if (lane == 0) { red[0][wid] = s1; red[1][wid] = q1; red[2][wid] = s2; red[3][wid] = q2; }
    __syncthreads();
    if (tid == 0) {
        float a = 0, b = 0, c2 = 0, d = 0;
        for (int i = 0; i < 8; i++) { a += red[0][i]; b += red[1][i]; c2 += red[2][i]; d += red[3][i]; }
        atomicAdd(&g_sum1[c], a);  atomicAdd(&g_sq1[c], b);
        atomicAdd(&g_sum2[c], c2); atomicAdd(&g_sq2[c], d);
    }
}

// K5: circulant T-conv via fp16 MMA + BN-ReLU combine -> s (fp16). BN coeffs inlined.
__global__ void __launch_bounds__(256) k_branch3(const float* __restrict__ g3,
                                                 const float* __restrict__ b3,
                                                 const float* __restrict__ g5,
                                                 const float* __restrict__ b5) {
    __shared__ __align__(16) __half Gre[32][40];
    __shared__ __align__(16) __half Gim[32][40];
    __shared__ __align__(16) __half Vs[32][264];
    __shared__ float2 qq[32];
    int bc  = blockIdx.x >> 2;
    int hw0 = (blockIdx.x & 3) << 8;
    int c = bc & 63;
    size_t base = (size_t)bc * 32768;
    int tid = threadIdx.x;
    int wid = tid >> 5, lane = tid & 31;
    int g = lane >> 2, tig = lane & 3;
    int hwb = wid * 32;

    const float inv = 1.0f / 65536.0f;
    float m1 = g_sum1[c] * inv;
    float v1 = g_sq1[c] * inv - m1 * m1;
    float a1 = g3[c] * rsqrtf(v1 + 1e-5f);
    float bb1 = b3[c] - m1 * a1;
    float m2 = g_sum2[c] * inv;
    float v2 = g_sq2[c] * inv - m2 * m2;
    float a2 = g5[c] * rsqrtf(v2 + 1e-5f);
    float bb2 = b5[c] - m2 * a2;

    if (tid < 32) qq[tid] = make_float2(g_qre[tid], g_qim[tid]);
    for (int i = tid; i < 1024; i += 256) {
        int t = i >> 5, tau = i & 31;
        int d = (t - tau + 32) & 31;
        Gre[t][tau] = __float2half_rn(g_gre[d]);
        Gim[t][tau] = __float2half_rn(g_gim[d]);
    }
    for (int i4 = tid; i4 < 1024; i4 += 256) {
        int t = i4 >> 5, q8 = (i4 & 31) * 8;
        *reinterpret_cast<uint4*>(&Vs[t][q8]) =
            *reinterpret_cast<const uint4*>(&g_h5h[base + (size_t)t * 1024 + hw0 + q8]);
    }
    __syncthreads();

    float ar[2][4][4], ai[2][4][4];
    #pragma unroll
    for (int i = 0; i < 2; i++)
        #pragma unroll
        for (int j = 0; j < 4; j++)
            #pragma unroll
            for (int l = 0; l < 4; l++) { ar[i][j][l] = 0.f; ai[i][j][l] = 0.f; }

    #pragma unroll
    for (int ks = 0; ks < 2; ks++) {
        int kk = ks * 16;
        uint32_t are[2][4], aim[2][4];
        #pragma unroll
        for (int mf = 0; mf < 2; mf++) {
            ldsm4(are[mf], saddr(&Gre[mf * 16 + (lane & 15)][kk + (lane >> 4) * 8]));
            ldsm4(aim[mf], saddr(&Gim[mf * 16 + (lane & 15)][kk + (lane >> 4) * 8]));
        }
        uint32_t b[2][4];
        #pragma unroll
        for (int h = 0; h < 2; h++)
            ldsm4t(b[h], saddr(&Vs[kk + (lane & 7) + ((lane >> 3) & 1) * 8]
                                  [hwb + h * 16 + ((lane >> 4) & 1) * 8]));
        #pragma unroll
        for (int mf = 0; mf < 2; mf++)
            #pragma unroll
            for (int nf = 0; nf < 4; nf++) {
                uint32_t b0 = b[nf >> 1][(nf & 1) * 2], b1v = b[nf >> 1][(nf & 1) * 2 + 1];
                mma16816(ar[mf][nf], are[mf], b0, b1v);
                mma16816(ai[mf][nf], aim[mf], b0, b1v);
            }
    }

    #pragma unroll
    for (int mf = 0; mf < 2; mf++)
        #pragma unroll
        for (int nf = 0; nf < 4; nf++)
            #pragma unroll
            for (int l = 0; l < 4; l++) {
                int t = mf * 16 + g + (l >> 1) * 8;
                int hw = hw0 + hwb + nf * 8 + 2 * tig + (l & 1);
                float rr = ar[mf][nf][l], ii = ai[mf][nf][l];
                if (hw == 0) { rr += qq[t].x; ii += qq[t].y; }
                float x3 = sqrtf(rr * rr + ii * ii);
                size_t idx = base + (size_t)t * 1024 + hw;
                float2 v12 = __half22float2(g_x12[idx]);
                float x1v = fmaxf(fmaf(v12.x, a1, bb1), 0.f);
                float x2v = fmaxf(fmaf(v12.y, a2, bb2), 0.f);
                g_sh[idx] = __float2half_rn(x1v + x2v + x3);
            }
}

// K6: channel mix via fp16 MMA + shortcut -> yT fp16 [row][o]
__global__ void __launch_bounds__(256) k_mix(const float* __restrict__ cb) {
    __shared__ __align__(16) __half W2s[64][72];
    __shared__ __align__(16) __half Ss[64][136];
    int bt  = blockIdx.x >> 3;
    int hw0 = (blockIdx.x & 7) << 7;
    int b = bt >> 5, t = bt & 31;
    int tid = threadIdx.x;
    int wid = tid >> 5, lane = tid & 31;
    int g = lane >> 2, tig = lane & 3;
    int warp_m = (wid & 1) * 32;
    int warp_n = (wid >> 1) * 32;

    for (int i = tid; i < 512; i += 256) {
        int o = i >> 3, sg = i & 7;
        *reinterpret_cast<uint4*>(&W2s[o][sg * 8]) =
            *reinterpret_cast<const uint4*>(&g_W2h[o * 64 + sg * 8]);
    }
    for (int i = tid; i < 1024; i += 256) {
        int cx = i >> 4, p8 = (i & 15) * 8;
        *reinterpret_cast<uint4*>(&Ss[cx][p8]) =
            *reinterpret_cast<const uint4*>(&g_sh[(size_t)((b * 64 + cx) * 32 + t) * 1024 + hw0 + p8]);
    }
    __syncthreads();

    float acc[2][4][4];
    #pragma unroll
    for (int i = 0; i < 2; i++)
        #pragma unroll
        for (int j = 0; j < 4; j++)
            #pragma unroll
            for (int l = 0; l < 4; l++) acc[i][j][l] = 0.f;

    #pragma unroll
    for (int ks = 0; ks < 4; ks++) {
        int kk = ks * 16;
        uint32_t a[2][4];
        #pragma unroll
        for (int mf = 0; mf < 2; mf++)
            ldsm4(a[mf], saddr(&W2s[warp_m + mf * 16 + (lane & 15)][kk + (lane >> 4) * 8]));
        uint32_t bfr[2][4];
        #pragma unroll
        for (int h = 0; h < 2; h++)
            ldsm4t(bfr[h], saddr(&Ss[kk + (lane & 7) + ((lane >> 3) & 1) * 8]
                                    [warp_n + h * 16 + ((lane >> 4) & 1) * 8]));
        #pragma unroll
        for (int mf = 0; mf < 2; mf++)
            #pragma unroll
            for (int nf = 0; nf < 4; nf++)
                mma16816(acc[mf][nf], a[mf],
                         bfr[nf >> 1][(nf & 1) * 2], bfr[nf >> 1][(nf & 1) * 2 + 1]);
    }

    #pragma unroll
    for (int mf = 0; mf < 2; mf++)
        #pragma unroll
        for (int nf = 0; nf < 4; nf++)
            #pragma unroll
            for (int l = 0; l < 4; l++) {
                int o = warp_m + mf * 16 + g + (l >> 1) * 8;
                int hw = hw0 + warp_n + nf * 8 + 2 * tig + (l & 1);
                float v = __half2float(g_h5h[(size_t)((b * 64 + o) * 32 + t) * 1024 + hw])
                          + acc[mf][nf][l] + cb[o];
                g_yTh[((size_t)bt * 1024 + hw) * 64 + o] = __float2half_rn(v);
            }
}

// K7: up GEMM (fp16 mma + ldmatrix, K=64 single chunk) + bias + GELU + residual
__global__ void __launch_bounds__(256) k_up(const float* __restrict__ x,
                                            const float* __restrict__ bias,
                                            float* __restrict__ out) {
    __shared__ __align__(16) __half As[128][72];
    __shared__ __align__(16) __half Bs[128][72];
    int tid = threadIdx.x;
    int r0 = blockIdx.x * 128;
    int n0 = blockIdx.y * 128;
    int wid = tid >> 5, lane = tid & 31;
    int g = lane >> 2, tig = lane & 3;
    int warp_m = (wid & 1) * 64;
    int warp_n = (wid >> 1) * 32;

    float acc[4][4][4];
    #pragma unroll
    for (int i = 0; i < 4; i++)
        #pragma unroll
        for (int j = 0; j < 4; j++)
            #pragma unroll
            for (int l = 0; l < 4; l++) acc[i][j][l] = 0.f;

    #pragma unroll
    for (int i = 0; i < 4; i++) {
        int idx = tid + i * 256;
        int m = idx >> 3, sg = idx & 7;
        *reinterpret_cast<uint4*>(&As[m][sg * 8]) =
            *reinterpret_cast<const uint4*>(&g_yTh[(size_t)(r0 + m) * 64 + sg * 8]);
    }
    #pragma unroll
    for (int i = 0; i < 4; i++) {
        int idx = tid + i * 256;
        int n = idx >> 3, sg = idx & 7;
        *reinterpret_cast<uint4*>(&Bs[n][sg * 8]) =
            *reinterpret_cast<const uint4*>(&g_Wph[(size_t)(n0 + n) * 64 + sg * 8]);
    }
    __syncthreads();
    #pragma unroll
    for (int ks = 0; ks < 4; ks++) {
        int kk = ks * 16;
        uint32_t a[4][4];
        #pragma unroll
        for (int mf = 0; mf < 4; mf++)
            ldsm4(a[mf], saddr(&As[warp_m + mf * 16 + (lane & 15)][kk + (lane >> 4) * 8]));
        uint32_t bfr[2][4];
        #pragma unroll
        for (int h = 0; h < 2; h++)
            ldsm4(bfr[h], saddr(&Bs[warp_n + h * 16 + ((lane >> 4) & 1) * 8 + (lane & 7)]
                                   [kk + ((lane >> 3) & 1) * 8]));
        #pragma unroll
        for (int mf = 0; mf < 4; mf++)
            #pragma unroll
            for (int nf = 0; nf < 4; nf++)
                mma16816(acc[mf][nf], a[mf],
                         bfr[nf >> 1][(nf & 1) * 2], bfr[nf >> 1][(nf & 1) * 2 + 1]);
    }
    #pragma unroll
    for (int nf = 0; nf < 4; nf++) {
        int col = n0 + warp_n + nf * 8 + 2 * tig;
        float bs0 = bias[col], bs1 = bias[col + 1];
        #pragma unroll
        for (int mf = 0; mf < 4; mf++) {
            #pragma unroll
            for (int half = 0; half < 2; half++) {
                int row = r0 + warp_m + mf * 16 + g + half * 8;
                float c0 = acc[mf][nf][half * 2 + 0];
                float c1 = acc[mf][nf][half * 2 + 1];
                const float2 xin = *reinterpret_cast<const float2*>(&x[(size_t)row * 384 + col]);
                float2 o;
                o.x = xin.x + gelu_f(c0 + bs0);
                o.y = xin.y + gelu_f(c1 + bs1);
                *reinterpret_cast<float2*>(&out[(size_t)row * 384 + col]) = o;
            }
        }
    }
}

extern "C" void kernel_launch(void* const* d_in, const int* in_sizes, int n_in,
                              void* d_out, int out_size) {
    const float* x      = (const float*)d_in[0];
    const float* down_w = (const float*)d_in[1];
    const float* down_b = (const float*)d_in[2];
    const float* k31w   = (const float*)d_in[3];
    const float* k31b   = (const float*)d_in[4];
    const float* k32w   = (const float*)d_in[5];
    const float* k32b   = (const float*)d_in[6];
    const float* bn3g   = (const float*)d_in[7];
    const float* bn3b   = (const float*)d_in[8];
    const float* k51w   = (const float*)d_in[9];
    const float* k51b   = (const float*)d_in[10];
    const float* k52w   = (const float*)d_in[11];
    const float* k52b   = (const float*)d_in[12];
    const float* bn5g   = (const float*)d_in[13];
    const float* bn5b   = (const float*)d_in[14];
    const float* convw  = (const float*)d_in[15];
    const float* convb  = (const float*)d_in[16];
    const float* fw     = (const float*)d_in[17];
    const float* fb     = (const float*)d_in[18];
    const float* upw    = (const float*)d_in[19];
    const float* upb    = (const float*)d_in[20];
    float* out = (float*)d_out;

    cudaFuncSetAttribute(k_conv2, cudaFuncAttributeMaxDynamicSharedMemorySize, 60416);

    k_init    <<<384, 64>>>(fw, fb, upw, convw);
    k_down    <<<512, 256>>>(x, down_w, down_b);
    k_conv2   <<<512, 256, 60416>>>(k31w, k31b, k51w, k51b, k32w, k32b, k52w, k52b);
    k_branch3 <<<512, 256>>>(bn3g, bn3b, bn5g, bn5b);
    k_mix     <<<512, 256>>>(convb);
    {
        dim3 grid(ROWS / 128, 384 / 128);
        k_up <<<grid, 256>>>(x, upb, out);
    }
}

// round 16
// speedup vs baseline: 2.0517x; 1.0140x over previous
#include <cuda_runtime.h>
#include <cuda_fp16.h>
#include <math.h>
#include <stdint.h>

#define LTOT (2*64*32*1024)
#define ROWS 65536

__device__ __align__(16) __half g_h5h[LTOT];
__device__ __align__(16) __half2 g_x12[LTOT];
__device__ __align__(16) __half g_sh[LTOT];
__device__ __align__(16) __half g_yTh[(size_t)ROWS * 64];
__device__ __align__(16) __half g_Wph[384 * 64];
__device__ __align__(16) __half g_W2h[64 * 64];

__device__ float g_gre[32], g_gim[32], g_qre[32], g_qim[32];
__device__ float g_sum1[64], g_sq1[64], g_sum2[64], g_sq2[64];

__device__ __forceinline__ float gelu_f(float v) {
    return 0.5f * v * (1.0f + erff(v * 0.70710678118654752f));
}

__device__ __forceinline__ uint32_t pack2(float a, float b) {
    __half2 h = __floats2half2_rn(a, b);
    return *reinterpret_cast<uint32_t*>(&h);
}

__device__ __forceinline__ uint32_t saddr(const void* p) {
    return static_cast<uint32_t>(__cvta_generic_to_shared(p));
}

__device__ __forceinline__ void ldsm4(uint32_t r[4], uint32_t a) {
    asm volatile("ldmatrix.sync.aligned.m8n8.x4.shared.b16 {%0,%1,%2,%3}, [%4];"
                 : "=r"(r[0]), "=r"(r[1]), "=r"(r[2]), "=r"(r[3]) : "r"(a));
}

__device__ __forceinline__ void ldsm4t(uint32_t r[4], uint32_t a) {
    asm volatile("ldmatrix.sync.aligned.m8n8.x4.trans.shared.b16 {%0,%1,%2,%3}, [%4];"
                 : "=r"(r[0]), "=r"(r[1]), "=r"(r[2]), "=r"(r[3]) : "r"(a));
}

__device__ __forceinline__ void mma16816(float c[4], const uint32_t a[4],
                                         uint32_t b0, uint32_t b1) {
    asm volatile(
        "mma.sync.aligned.m16n8k16.row.col.f32.f16.f16.f32 "
        "{%0,%1,%2,%3}, {%4,%5,%6,%7}, {%8,%9}, {%0,%1,%2,%3};"
        : "+f"(c[0]), "+f"(c[1]), "+f"(c[2]), "+f"(c[3])
        : "r"(a[0]), "r"(a[1]), "r"(a[2]), "r"(a[3]), "r"(b0), "r"(b1));
}

// K0: fused prep (ifft of fw/fb, zero stats) + weight conversion to fp16
__global__ void k_init(const float* __restrict__ fw, const float* __restrict__ fb,
                       const float* __restrict__ up, const float* __restrict__ w2) {
    int of = blockIdx.x, j = threadIdx.x;
    g_Wph[of * 64 + j] = __float2half_rn(up[of * 64 + j]);
    if (of < 64) g_W2h[of * 64 + j] = __float2half_rn(w2[of * 64 + j]);
    if (of == 0) {
        int n = j;
        if (n < 32) {
            double gr = 0, gi = 0, qr = 0, qi = 0;
            for (int k = 0; k < 32; k++) {
                double ang = 6.283185307179586476925 * (double)((k * n) & 31) / 32.0;
                double cs = cos(ang), sn = sin(ang);
                gr += (double)fw[k] * cs; gi += (double)fw[k] * sn;
                qr += (double)fb[k] * cs; qi += (double)fb[k] * sn;
            }
            g_gre[n] = (float)(gr / 32.0); g_gim[n] = (float)(gi / 32.0);
            g_qre[n] = (float)(qr / 32.0); g_qim[n] = (float)(qi / 32.0);
        }
        g_sum1[n] = 0.f; g_sq1[n] = 0.f; g_sum2[n] = 0.f; g_sq2[n] = 0.f;
    }
}

// K1: down GEMM (fp16 mma + ldmatrix) + bias + GELU -> h5h NCDHW (fp16)
__global__ void __launch_bounds__(256) k_down(const float* __restrict__ x,
                                              const float* __restrict__ w,
                                              const float* __restrict__ bias) {
    __shared__ __align__(16) __half As[128][72];
    __shared__ __align__(16) __half Bs[64][72];
    int tid = threadIdx.x;
    int r0 = blockIdx.x * 128;
    int wid = tid >> 5, lane = tid & 31;
    int g = lane >> 2, tig = lane & 3;
    int warp_m = (wid & 3) * 32;
    int warp_n = (wid >> 2) * 32;

    float acc[2][4][4];
    #pragma unroll
    for (int i = 0; i < 2; i++)
        #pragma unroll
        for (int j = 0; j < 4; j++)
            #pragma unroll
            for (int l = 0; l < 4; l++) acc[i][j][l] = 0.f;

    for (int k0 = 0; k0 < 384; k0 += 64) {
        #pragma unroll
        for (int i = 0; i < 4; i++) {
            int idx = tid + i * 256;
            int m = idx >> 3, sg = idx & 7;
            const float4* p = reinterpret_cast<const float4*>(&x[(size_t)(r0 + m) * 384 + k0 + sg * 8]);
            float4 v0 = p[0], v1 = p[1];
            uint4 st;
            st.x = pack2(v0.x, v0.y); st.y = pack2(v0.z, v0.w);
            st.z = pack2(v1.x, v1.y); st.w = pack2(v1.z, v1.w);
            *reinterpret_cast<uint4*>(&As[m][sg * 8]) = st;
        }
        #pragma unroll
        for (int i = 0; i < 2; i++) {
            int idx = tid + i * 256;
            int n = idx >> 3, sg = idx & 7;
            const float4* p = reinterpret_cast<const float4*>(&w[n * 384 + k0 + sg * 8]);
            float4 v0 = p[0], v1 = p[1];
            uint4 st;
            st.x = pack2(v0.x, v0.y); st.y = pack2(v0.z, v0.w);
            st.z = pack2(v1.x, v1.y); st.w = pack2(v1.z, v1.w);
            *reinterpret_cast<uint4*>(&Bs[n][sg * 8]) = st;
        }
        __syncthreads();
        #pragma unroll
        for (int ks = 0; ks < 4; ks++) {
            int kk = ks * 16;
            uint32_t a[2][4];
            #pragma unroll
            for (int mf = 0; mf < 2; mf++)
                ldsm4(a[mf], saddr(&As[warp_m + mf * 16 + (lane & 15)][kk + (lane >> 4) * 8]));
            uint32_t b[2][4];
            #pragma unroll
            for (int h = 0; h < 2; h++)
                ldsm4(b[h], saddr(&Bs[warp_n + h * 16 + ((lane >> 4) & 1) * 8 + (lane & 7)]
                                     [kk + ((lane >> 3) & 1) * 8]));
            #pragma unroll
            for (int mf = 0; mf < 2; mf++)
                #pragma unroll
                for (int nf = 0; nf < 4; nf++)
                    mma16816(acc[mf][nf], a[mf], b[nf >> 1][(nf & 1) * 2], b[nf >> 1][(nf & 1) * 2 + 1]);
        }
        __syncthreads();
    }
    int bt = r0 >> 10, hwbase = r0 & 1023;
    int b5i = bt >> 5, t = bt & 31;
    size_t planebase = (size_t)(b5i * 64) * 32768 + (size_t)t * 1024;
    #pragma unroll
    for (int nf = 0; nf < 4; nf++) {
        int c0 = warp_n + nf * 8 + 2 * tig;
        float bs0 = bias[c0], bs1 = bias[c0 + 1];
        #pragma unroll
        for (int mf = 0; mf < 2; mf++) {
            int m = warp_m + mf * 16 + g;
            size_t p0 = planebase + (size_t)c0 * 32768;
            g_h5h[p0 + hwbase + m]             = __float2half_rn(gelu_f(acc[mf][nf][0] + bs0));
            g_h5h[p0 + 32768 + hwbase + m]     = __float2half_rn(gelu_f(acc[mf][nf][1] + bs1));
            g_h5h[p0 + hwbase + m + 8]         = __float2half_rn(gelu_f(acc[mf][nf][2] + bs0));
            g_h5h[p0 + 32768 + hwbase + m + 8] = __float2half_rn(gelu_f(acc[mf][nf][3] + bs1));
        }
    }
}

// K2: fused spatial+temporal depthwise + BN stats; padded rows, aligned loads
__global__ void __launch_bounds__(256) k_conv2(const float* __restrict__ w3g,
                                               const float* __restrict__ b3g,
                                               const float* __restrict__ w5g,
                                               const float* __restrict__ b5g,
                                               const float* __restrict__ wt3g,
                                               const float* __restrict__ bt3g,
                                               const float* __restrict__ wt5g,
                                               const float* __restrict__ bt5g) {
    extern __shared__ __half smh[];
    __half* in = smh;            // 32*12*36 = 13824 halves
    __half* s3 = smh + 13824;    // 8192
    __half* s5 = smh + 22016;    // 8192
    int bc = blockIdx.x >> 2;
    int band = blockIdx.x & 3;
    int h0 = band * 8;
    int c = bc & 63;
    size_t base = (size_t)bc * 32768;
    int tid = threadIdx.x;

    __shared__ float w3[9], w5[25], wt3[3], wt5[5];
    if (tid < 9)  w3[tid] = w3g[c * 9 + tid];
    if (tid >= 32 && tid < 57) w5[tid - 32] = w5g[c * 25 + (tid - 32)];
    if (tid >= 64 && tid < 67) wt3[tid - 64] = wt3g[c * 3 + (tid - 64)];
    if (tid >= 96 && tid < 101) wt5[tid - 96] = wt5g[c * 5 + (tid - 96)];

    for (int r = tid; r < 384; r += 256) {
        __half* row = &in[r * 36];
        *reinterpret_cast<uint32_t*>(&row[0]) = 0u;
        *reinterpret_cast<uint32_t*>(&row[34]) = 0u;
    }
    for (int i4 = tid; i4 < 1536; i4 += 256) {
        int t = i4 / 48, rem = i4 - t * 48;
        int r = rem >> 2, w8 = (rem & 3) * 8;
        int gh = h0 - 2 + r;
        uint4 v = make_uint4(0u, 0u, 0u, 0u);
        if ((unsigned)gh < 32u)
            v = *reinterpret_cast<const uint4*>(&g_h5h[base + (size_t)t * 1024 + gh * 32 + w8]);
        uint32_t* d = reinterpret_cast<uint32_t*>(&in[t * 432 + r * 36 + 2 + w8]);
        d[0] = v.x; d[1] = v.y; d[2] = v.z; d[3] = v.w;
    }
    __syncthreads();

    float b3 = b3g[c], b5 = b5g[c];
    for (int gid = tid; gid < 2048; gid += 256) {
        int t = gid >> 6;
        int rem = gid & 63;
        int h = rem >> 3;
        int w0 = (rem & 7) * 4;
        float a3[4] = {b3, b3, b3, b3};
        float a5[4] = {b5, b5, b5, b5};
        const __half* tbase = &in[t * 432];
        #pragma unroll
        for (int dh = 0; dh < 5; dh++) {
            const __half* rp = &tbase[(h + dh) * 36 + w0];
            uint2 u0 = *reinterpret_cast<const uint2*>(rp);
            uint2 u1 = *reinterpret_cast<const uint2*>(rp + 4);
            float2 f0 = __half22float2(*reinterpret_cast<const __half2*>(&u0.x));
            float2 f1 = __half22float2(*reinterpret_cast<const __half2*>(&u0.y));
            float2 f2 = __half22float2(*reinterpret_cast<const __half2*>(&u1.x));
            float2 f3 = __half22float2(*reinterpret_cast<const __half2*>(&u1.y));
            float r[8] = {f0.x, f0.y, f1.x, f1.y, f2.x, f2.y, f3.x, f3.y};
            #pragma unroll
            for (int px = 0; px < 4; px++)
                #pragma unroll
                for (int dw = 0; dw < 5; dw++)
                    a5[px] = fmaf(r[px + dw], w5[dh * 5 + dw], a5[px]);
            if (dh >= 1 && dh <= 3) {
                #pragma unroll
                for (int px = 0; px < 4; px++)
                    #pragma unroll
                    for (int dw = 0; dw < 3; dw++)
                        a3[px] = fmaf(r[px + dw + 1], w3[(dh - 1) * 3 + dw], a3[px]);
            }
        }
        int p = h * 32 + w0;
        uint2 v3, v5;
        v3.x = pack2(a3[0], a3[1]); v3.y = pack2(a3[2], a3[3]);
        v5.x = pack2(a5[0], a5[1]); v5.y = pack2(a5[2], a5[3]);
        *reinterpret_cast<uint2*>(&s3[t * 256 + p]) = v3;
        *reinterpret_cast<uint2*>(&s5[t * 256 + p]) = v5;
    }
    __syncthreads();

    float bt3 = bt3g[c], bt5 = bt5g[c];
    float s1 = 0, q1 = 0, s2 = 0, q2 = 0;
    for (int i = tid; i < 4096; i += 256) {
        int t = i >> 7, p2 = (i & 127) * 2;
        float2 a = make_float2(bt3, bt3);
        float2 e = make_float2(bt5, bt5);
        #pragma unroll
        for (int dt = -1; dt <= 1; dt++) {
            int tt = t + dt;
            if ((unsigned)tt < 32u) {
                float2 f = __half22float2(*reinterpret_cast<const __half2*>(&s3[tt * 256 + p2]));
                float wv = wt3[dt + 1];
                a.x = fmaf(f.x, wv, a.x); a.y = fmaf(f.y, wv, a.y);
            }
        }
        #pragma unroll
        for (int dt = -2; dt <= 2; dt++) {
            int tt = t + dt;
            if ((unsigned)tt < 32u) {
                float2 f = __half22float2(*reinterpret_cast<const __half2*>(&s5[tt * 256 + p2]));
                float wv = wt5[dt + 2];
                e.x = fmaf(f.x, wv, e.x); e.y = fmaf(f.y, wv, e.y);
            }
        }
        uint2 st;
        st.x = pack2(a.x, e.x);
        st.y = pack2(a.y, e.y);
        *reinterpret_cast<uint2*>(&g_x12[base + (size_t)t * 1024 + h0 * 32 + p2]) = st;
        s1 += a.x + a.y; q1 = fmaf(a.x, a.x, fmaf(a.y, a.y, q1));
        s2 += e.x + e.y; q2 = fmaf(e.x, e.x, fmaf(e.y, e.y, q2));
    }
    #pragma unroll
    for (int off = 16; off; off >>= 1) {
        s1 += __shfl_down_sync(0xffffffffu, s1, off);
        q1 += __shfl_down_sync(0xffffffffu, q1, off);
        s2 += __shfl_down_sync(0xffffffffu, s2, off);
        q2 += __shfl_down_sync(0xffffffffu, q2, off);
    }
    __shared__ float red[4][8];
    int wid = tid >> 5, lane = tid & 31;
    if (lane == 0) { red[0][wid] = s1; red[1][wid] = q1; red[2][wid] = s2; red[3][wid] = q2; }
    __syncthreads();
    if (tid == 0) {
        float a = 0, b = 0, c2 = 0, d = 0;
        for (int i = 0; i < 8; i++) { a += red[0][i]; b += red[1][i]; c2 += red[2][i]; d += red[3][i]; }
        atomicAdd(&g_sum1[c], a);  atomicAdd(&g_sq1[c], b);
        atomicAdd(&g_sum2[c], c2); atomicAdd(&g_sq2[c], d);
    }
}

// K5: circulant T-conv via fp16 MMA + BN-ReLU combine -> s (fp16). 128-hw blocks.
__global__ void __launch_bounds__(256) k_branch3(const float* __restrict__ g3,
                                                 const float* __restrict__ b3,
                                                 const float* __restrict__ g5,
                                                 const float* __restrict__ b5) {
    __shared__ __align__(16) __half Gre[32][40];
    __shared__ __align__(16) __half Gim[32][40];
    __shared__ __align__(16) __half Vs[32][136];
    __shared__ float2 qq[32];
    int bc  = blockIdx.x >> 3;
    int hw0 = (blockIdx.x & 7) << 7;
    int c = bc & 63;
    size_t base = (size_t)bc * 32768;
    int tid = threadIdx.x;
    int wid = tid >> 5, lane = tid & 31;
    int g = lane >> 2, tig = lane & 3;
    int hwb = wid * 16;

    const float inv = 1.0f / 65536.0f;
    float m1 = g_sum1[c] * inv;
    float v1 = g_sq1[c] * inv - m1 * m1;
    float a1 = g3[c] * rsqrtf(v1 + 1e-5f);
    float bb1 = b3[c] - m1 * a1;
    float m2 = g_sum2[c] * inv;
    float v2 = g_sq2[c] * inv - m2 * m2;
    float a2 = g5[c] * rsqrtf(v2 + 1e-5f);
    float bb2 = b5[c] - m2 * a2;

    if (tid < 32) qq[tid] = make_float2(g_qre[tid], g_qim[tid]);
    for (int i = tid; i < 1024; i += 256) {
        int t = i >> 5, tau = i & 31;
        int d = (t - tau + 32) & 31;
        Gre[t][tau] = __float2half_rn(g_gre[d]);
        Gim[t][tau] = __float2half_rn(g_gim[d]);
    }
    for (int i4 = tid; i4 < 512; i4 += 256) {
        int t = i4 >> 4, q8 = (i4 & 15) * 8;
        *reinterpret_cast<uint4*>(&Vs[t][q8]) =
            *reinterpret_cast<const uint4*>(&g_h5h[base + (size_t)t * 1024 + hw0 + q8]);
    }
    __syncthreads();

    float ar[2][2][4], ai[2][2][4];
    #pragma unroll
    for (int i = 0; i < 2; i++)
        #pragma unroll
        for (int j = 0; j < 2; j++)
            #pragma unroll
            for (int l = 0; l < 4; l++) { ar[i][j][l] = 0.f; ai[i][j][l] = 0.f; }

    #pragma unroll
    for (int ks = 0; ks < 2; ks++) {
        int kk = ks * 16;
        uint32_t are[2][4], aim[2][4];
        #pragma unroll
        for (int mf = 0; mf < 2; mf++) {
            ldsm4(are[mf], saddr(&Gre[mf * 16 + (lane & 15)][kk + (lane >> 4) * 8]));
            ldsm4(aim[mf], saddr(&Gim[mf * 16 + (lane & 15)][kk + (lane >> 4) * 8]));
        }
        uint32_t b[4];
        ldsm4t(b, saddr(&Vs[kk + (lane & 7) + ((lane >> 3) & 1) * 8]
                           [hwb + ((lane >> 4) & 1) * 8]));
        #pragma unroll
        for (int mf = 0; mf < 2; mf++)
            #pragma unroll
            for (int nf = 0; nf < 2; nf++) {
                uint32_t b0 = b[nf * 2], b1v = b[nf * 2 + 1];
                mma16816(ar[mf][nf], are[mf], b0, b1v);
                mma16816(ai[mf][nf], aim[mf], b0, b1v);
            }
    }

    #pragma unroll
    for (int mf = 0; mf < 2; mf++)
        #pragma unroll
        for (int nf = 0; nf < 2; nf++)
            #pragma unroll
            for (int l = 0; l < 4; l++) {
                int t = mf * 16 + g + (l >> 1) * 8;
                int hw = hw0 + hwb + nf * 8 + 2 * tig + (l & 1);
                float rr = ar[mf][nf][l], ii = ai[mf][nf][l];
                if (hw == 0) { rr += qq[t].x; ii += qq[t].y; }
                float x3 = sqrtf(rr * rr + ii * ii);
                size_t idx = base + (size_t)t * 1024 + hw;
                float2 v12 = __half22float2(g_x12[idx]);
                float x1v = fmaxf(fmaf(v12.x, a1, bb1), 0.f);
                float x2v = fmaxf(fmaf(v12.y, a2, bb2), 0.f);
                g_sh[idx] = __float2half_rn(x1v + x2v + x3);
            }
}

// K6: channel mix via fp16 MMA + shortcut -> yT fp16 [row][o]
__global__ void __launch_bounds__(256) k_mix(const float* __restrict__ cb) {
    __shared__ __align__(16) __half W2s[64][72];
    __shared__ __align__(16) __half Ss[64][136];
    int bt  = blockIdx.x >> 3;
    int hw0 = (blockIdx.x & 7) << 7;
    int b = bt >> 5, t = bt & 31;
    int tid = threadIdx.x;
    int wid = tid >> 5, lane = tid & 31;
    int g = lane >> 2, tig = lane & 3;
    int warp_m = (wid & 1) * 32;
    int warp_n = (wid >> 1) * 32;

    for (int i = tid; i < 512; i += 256) {
        int o = i >> 3, sg = i & 7;
        *reinterpret_cast<uint4*>(&W2s[o][sg * 8]) =
            *reinterpret_cast<const uint4*>(&g_W2h[o * 64 + sg * 8]);
    }
    for (int i = tid; i < 1024; i += 256) {
        int cx = i >> 4, p8 = (i & 15) * 8;
        *reinterpret_cast<uint4*>(&Ss[cx][p8]) =
            *reinterpret_cast<const uint4*>(&g_sh[(size_t)((b * 64 + cx) * 32 + t) * 1024 + hw0 + p8]);
    }
    __syncthreads();

    float acc[2][4][4];
    #pragma unroll
    for (int i = 0; i < 2; i++)
        #pragma unroll
        for (int j = 0; j < 4; j++)
            #pragma unroll
            for (int l = 0; l < 4; l++) acc[i][j][l] = 0.f;

    #pragma unroll
    for (int ks = 0; ks < 4; ks++) {
        int kk = ks * 16;
        uint32_t a[2][4];
        #pragma unroll
        for (int mf = 0; mf < 2; mf++)
            ldsm4(a[mf], saddr(&W2s[warp_m + mf * 16 + (lane & 15)][kk + (lane >> 4) * 8]));
        uint32_t bfr[2][4];
        #pragma unroll
        for (int h = 0; h < 2; h++)
            ldsm4t(bfr[h], saddr(&Ss[kk + (lane & 7) + ((lane >> 3) & 1) * 8]
                                    [warp_n + h * 16 + ((lane >> 4) & 1) * 8]));
        #pragma unroll
        for (int mf = 0; mf < 2; mf++)
            #pragma unroll
            for (int nf = 0; nf < 4; nf++)
                mma16816(acc[mf][nf], a[mf],
                         bfr[nf >> 1][(nf & 1) * 2], bfr[nf >> 1][(nf & 1) * 2 + 1]);
    }

    #pragma unroll
    for (int mf = 0; mf < 2; mf++)
        #pragma unroll
        for (int nf = 0; nf < 4; nf++)
            #pragma unroll
            for (int l = 0; l < 4; l++) {
                int o = warp_m + mf * 16 + g + (l >> 1) * 8;
                int hw = hw0 + warp_n + nf * 8 + 2 * tig + (l & 1);
                float v = __half2float(g_h5h[(size_t)((b * 64 + o) * 32 + t) * 1024 + hw])
                          + acc[mf][nf][l] + cb[o];
                g_yTh[((size_t)bt * 1024 + hw) * 64 + o] = __float2half_rn(v);
            }
}

// K7: up GEMM (fp16 mma + ldmatrix, K=64 single chunk) + bias + GELU + residual
__global__ void __launch_bounds__(256) k_up(const float* __restrict__ x,
                                            const float* __restrict__ bias,
                                            float* __restrict__ out) {
    __shared__ __align__(16) __half As[128][72];
    __shared__ __align__(16) __half Bs[128][72];
    int tid = threadIdx.x;
    int r0 = blockIdx.x * 128;
    int n0 = blockIdx.y * 128;
    int wid = tid >> 5, lane = tid & 31;
    int g = lane >> 2, tig = lane & 3;
    int warp_m = (wid & 1) * 64;
    int warp_n = (wid >> 1) * 32;

    float acc[4][4][4];
    #pragma unroll
    for (int i = 0; i < 4; i++)
        #pragma unroll
        for (int j = 0; j < 4; j++)
            #pragma unroll
            for (int l = 0; l < 4; l++) acc[i][j][l] = 0.f;

    #pragma unroll
    for (int i = 0; i < 4; i++) {
        int idx = tid + i * 256;
        int m = idx >> 3, sg = idx & 7;
        *reinterpret_cast<uint4*>(&As[m][sg * 8]) =
            *reinterpret_cast<const uint4*>(&g_yTh[(size_t)(r0 + m) * 64 + sg * 8]);
    }
    #pragma unroll
    for (int i = 0; i < 4; i++) {
        int idx = tid + i * 256;
        int n = idx >> 3, sg = idx & 7;
        *reinterpret_cast<uint4*>(&Bs[n][sg * 8]) =
            *reinterpret_cast<const uint4*>(&g_Wph[(size_t)(n0 + n) * 64 + sg * 8]);
    }
    __syncthreads();
    #pragma unroll
    for (int ks = 0; ks < 4; ks++) {
        int kk = ks * 16;
        uint32_t a[4][4];
        #pragma unroll
        for (int mf = 0; mf < 4; mf++)
            ldsm4(a[mf], saddr(&As[warp_m + mf * 16 + (lane & 15)][kk + (lane >> 4) * 8]));
        uint32_t bfr[2][4];
        #pragma unroll
        for (int h = 0; h < 2; h++)
            ldsm4(bfr[h], saddr(&Bs[warp_n + h * 16 + ((lane >> 4) & 1) * 8 + (lane & 7)]
                                   [kk + ((lane >> 3) & 1) * 8]));
        #pragma unroll
        for (int mf = 0; mf < 4; mf++)
            #pragma unroll
            for (int nf = 0; nf < 4; nf++)
                mma16816(acc[mf][nf], a[mf],
                         bfr[nf >> 1][(nf & 1) * 2], bfr[nf >> 1][(nf & 1) * 2 + 1]);
    }
    #pragma unroll
    for (int nf = 0; nf < 4; nf++) {
        int col = n0 + warp_n + nf * 8 + 2 * tig;
        float bs0 = bias[col], bs1 = bias[col + 1];
        #pragma unroll
        for (int mf = 0; mf < 4; mf++) {
            #pragma unroll
            for (int half = 0; half < 2; half++) {
                int row = r0 + warp_m + mf * 16 + g + half * 8;
                float c0 = acc[mf][nf][half * 2 + 0];
                float c1 = acc[mf][nf][half * 2 + 1];
                const float2 xin = *reinterpret_cast<const float2*>(&x[(size_t)row * 384 + col]);
                float2 o;
                o.x = xin.x + gelu_f(c0 + bs0);
                o.y = xin.y + gelu_f(c1 + bs1);
                *reinterpret_cast<float2*>(&out[(size_t)row * 384 + col]) = o;
            }
        }
    }
}

extern "C" void kernel_launch(void* const* d_in, const int* in_sizes, int n_in,
                              void* d_out, int out_size) {
    const float* x      = (const float*)d_in[0];
    const float* down_w = (const float*)d_in[1];
    const float* down_b = (const float*)d_in[2];
    const float* k31w   = (const float*)d_in[3];
    const float* k31b   = (const float*)d_in[4];
    const float* k32w   = (const float*)d_in[5];
    const float* k32b   = (const float*)d_in[6];
    const float* bn3g   = (const float*)d_in[7];
    const float* bn3b   = (const float*)d_in[8];
    const float* k51w   = (const float*)d_in[9];
    const float* k51b   = (const float*)d_in[10];
    const float* k52w   = (const float*)d_in[11];
    const float* k52b   = (const float*)d_in[12];
    const float* bn5g   = (const float*)d_in[13];
    const float* bn5b   = (const float*)d_in[14];
    const float* convw  = (const float*)d_in[15];
    const float* convb  = (const float*)d_in[16];
    const float* fw     = (const float*)d_in[17];
    const float* fb     = (const float*)d_in[18];
    const float* upw    = (const float*)d_in[19];
    const float* upb    = (const float*)d_in[20];
    float* out = (float*)d_out;

    cudaFuncSetAttribute(k_conv2, cudaFuncAttributeMaxDynamicSharedMemorySize, 60416);

    k_init    <<<384, 64>>>(fw, fb, upw, convw);
    k_down    <<<512, 256>>>(x, down_w, down_b);
    k_conv2   <<<512, 256, 60416>>>(k31w, k31b, k51w, k51b, k32w, k32b, k52w, k52b);
    k_branch3 <<<1024, 256>>>(bn3g, bn3b, bn5g, bn5b);
    k_mix     <<<512, 256>>>(convb);
    {
        dim3 grid(ROWS / 128, 384 / 128);
        k_up <<<grid, 256>>>(x, upb, out);
    }
}